// round 10
// baseline (speedup 1.0000x reference)
#include <cuda_runtime.h>
#include <cuda_fp16.h>
#include <cstdint>
#include <cstddef>

// ---------------------------------------------------------------------------
// Problem constants
// ---------------------------------------------------------------------------
#define NB   8
#define NH   4
#define SEQ  2048
#define DM   64

// attention tiling
#define TQA  64          // q rows per CTA
#define KH   136         // half stride for qs/ks rows (128 data + 8 pad)
#define VH   72          // half stride for vsh / psh rows

// ---------------------------------------------------------------------------
// Static device scratch
// ---------------------------------------------------------------------------
__device__ float    g_gates[3 * NB];
__device__ int      g_mask_mode;                           // 1 = int32 mask, 0 = byte mask
__device__ __half   g_Qeh[(size_t)NB * NH * SEQ * 128];    // 16.8 MB fp16
__device__ __half   g_Keh[(size_t)NB * NH * SEQ * 128];    // 16.8 MB fp16
__device__ float    g_Ve[(size_t)NB * NH * SEQ * 64];      // 16.8 MB
__device__ __half   g_Veh[(size_t)NB * NH * 64 * SEQ];     // 8.4 MB (transposed [v][k] fp16)
__device__ float    g_ctx[(size_t)NB * SEQ * 256];         // 16.8 MB
__device__ unsigned g_maskb[(size_t)NB * SEQ * 64];        // 4 MB (bit-packed mask)
__device__ __half   g_ph[(size_t)NB * NH * SEQ * SEQ];     // 268 MB fp16 p scratch

// ---------------------------------------------------------------------------
// Helpers
// ---------------------------------------------------------------------------
__device__ __forceinline__ void mma_f16_k16(float& c0, float& c1, float& c2, float& c3,
                                            unsigned a0, unsigned a1, unsigned a2, unsigned a3,
                                            unsigned b0, unsigned b1) {
    asm volatile(
        "mma.sync.aligned.m16n8k16.row.col.f32.f16.f16.f32 "
        "{%0,%1,%2,%3},{%4,%5,%6,%7},{%8,%9},{%0,%1,%2,%3};"
        : "+f"(c0), "+f"(c1), "+f"(c2), "+f"(c3)
        : "r"(a0), "r"(a1), "r"(a2), "r"(a3), "r"(b0), "r"(b1));
}

__device__ __forceinline__ void cp_async16(void* smem, const void* gmem) {
    unsigned sa = (unsigned)__cvta_generic_to_shared(smem);
    asm volatile("cp.async.cg.shared.global [%0], [%1], 16;\n" :: "r"(sa), "l"(gmem));
}
__device__ __forceinline__ void cp_async4(void* smem, const void* gmem) {
    unsigned sa = (unsigned)__cvta_generic_to_shared(smem);
    asm volatile("cp.async.ca.shared.global [%0], [%1], 4;\n" :: "r"(sa), "l"(gmem));
}
#define CP_COMMIT() asm volatile("cp.async.commit_group;\n")
#define CP_WAIT(n)  asm volatile("cp.async.wait_group %0;\n" :: "n"(n))

// ---------------------------------------------------------------------------
// Kernel D: detect mask encoding (int32 vs byte)
// ---------------------------------------------------------------------------
__global__ void detect_mask_kernel(const unsigned char* __restrict__ m) {
    int found = 0;
    for (int i = threadIdx.x; i < 1024; i += 32)
        if (m[i * 4 + 1] | m[i * 4 + 2] | m[i * 4 + 3]) found = 1;
    for (int o = 16; o; o >>= 1)
        found |= __shfl_xor_sync(0xffffffffu, found, o);
    if (threadIdx.x == 0) g_mask_mode = found ? 0 : 1;
}

// ---------------------------------------------------------------------------
// Kernel M: bit-pack the mask (ballot-based, coalesced)
// ---------------------------------------------------------------------------
__global__ void __launch_bounds__(256) convert_mask_kernel(const void* __restrict__ mask) {
    unsigned gid = blockIdx.x * 256 + threadIdx.x;
    unsigned nz;
    if (g_mask_mode) nz = (((const int*)mask)[gid] != 0) ? 1u : 0u;
    else             nz = (((const unsigned char*)mask)[gid] != 0) ? 1u : 0u;
    unsigned bits = __ballot_sync(0xffffffffu, nz);
    if ((threadIdx.x & 31) == 0) g_maskb[gid >> 5] = bits;
}

// ---------------------------------------------------------------------------
// Kernel 0: scalar gates
// ---------------------------------------------------------------------------
__global__ void gates_kernel(const float* __restrict__ u,
                             const float* __restrict__ sq1, const float* __restrict__ sq2,
                             const float* __restrict__ sk1, const float* __restrict__ sk2,
                             const float* __restrict__ sv1, const float* __restrict__ sv2) {
    const int b = blockIdx.x;
    const int lane = threadIdx.x;
    float hq = 0.f, hk = 0.f, hv = 0.f;
    for (int d = 0; d < DM; ++d) {
        float uv = u[b * DM + d];
        hq += uv * sq1[d * 32 + lane];
        hk += uv * sk1[d * 32 + lane];
        hv += uv * sv1[d * 32 + lane];
    }
    hq = fmaxf(hq, 0.f) * sq2[lane];
    hk = fmaxf(hk, 0.f) * sk2[lane];
    hv = fmaxf(hv, 0.f) * sv2[lane];
    for (int off = 16; off; off >>= 1) {
        hq += __shfl_xor_sync(0xffffffffu, hq, off);
        hk += __shfl_xor_sync(0xffffffffu, hk, off);
        hv += __shfl_xor_sync(0xffffffffu, hv, off);
    }
    if (lane == 0) {
        g_gates[b]      = hq;
        g_gates[8 + b]  = hk;
        g_gates[16 + b] = hv;
    }
}

// ---------------------------------------------------------------------------
// Kernel 1 (v3): projections, 2 CTAs/SM. Weight tiles in 64x132 halves.
// ---------------------------------------------------------------------------
#define PROJ_SMEM_BYTES ((64*68 + 3*64*68 + 64*132) * 4)

__global__ void __launch_bounds__(256, 2) proj_kernel(
    const float* __restrict__ x,
    const float* __restrict__ wq, const float* __restrict__ wk, const float* __restrict__ wv,
    const float* __restrict__ uqw, const float* __restrict__ ukw, const float* __restrict__ uvw) {
    extern __shared__ float sm[];
    float* xs   = sm;                 // 64 x 68
    float* uo   = xs + 64 * 68;       // 3 x (64 x 68): u-weights, then u outputs
    float* wbig = uo + 3 * 64 * 68;   // 64 x 132

    const int t = threadIdx.x;
    const int row0 = blockIdx.x * 64;
    const int b    = row0 >> 11;
    const int lr0  = row0 & (SEQ - 1);

    for (int i = t; i < 64 * 16; i += 256) {
        int r = i >> 4, c = (i & 15) * 4;
        *(float4*)(xs + r * 68 + c)            = *(const float4*)(x + (size_t)(row0 + r) * DM + c);
        *(float4*)(uo + 0 * 4352 + r * 68 + c) = *(const float4*)(uqw + r * 64 + c);
        *(float4*)(uo + 1 * 4352 + r * 68 + c) = *(const float4*)(ukw + r * 64 + c);
        *(float4*)(uo + 2 * 4352 + r * 68 + c) = *(const float4*)(uvw + r * 64 + c);
    }
    __syncthreads();

    const int rg = t >> 5;
    const int cg = t & 31;

    float uacc[8][8];
    if (cg < 24) {
        const int mat = cg >> 3;
        const int c0 = (cg & 7) * 8;
        const float* w = uo + mat * 4352;
        #pragma unroll
        for (int i = 0; i < 8; ++i)
            #pragma unroll
            for (int j = 0; j < 8; ++j) uacc[i][j] = 0.f;
        for (int k = 0; k < 64; ++k) {
            float av[8];
            #pragma unroll
            for (int i = 0; i < 8; ++i) av[i] = xs[(rg * 8 + i) * 68 + k];
            float4 b0 = *(const float4*)(w + k * 68 + c0);
            float4 b1 = *(const float4*)(w + k * 68 + c0 + 4);
            float bv[8] = {b0.x, b0.y, b0.z, b0.w, b1.x, b1.y, b1.z, b1.w};
            #pragma unroll
            for (int i = 0; i < 8; ++i)
                #pragma unroll
                for (int j = 0; j < 8; ++j) uacc[i][j] += av[i] * bv[j];
        }
    }
    __syncthreads();

    if (cg < 24) {
        const int mat = cg >> 3;
        const int c0 = (cg & 7) * 8;
        float* dst = uo + mat * 4352;
        #pragma unroll
        for (int i = 0; i < 8; ++i)
            #pragma unroll
            for (int j = 0; j < 8; ++j)
                dst[(rg * 8 + i) * 68 + c0 + j] = uacc[i][j];
    }
    __syncthreads();

    const float gq = g_gates[b] * 0.125f;
    const float gk = g_gates[8 + b];
    const float gv = g_gates[16 + b];

    for (int i = t; i < 64 * 64; i += 256) {
        int r = i >> 6, j = i & 63;
        __half vq = __float2half(uo[r * 68 + j] * gq);
        __half vk = __float2half(uo[4352 + r * 68 + j] * gk);
        size_t l = lr0 + r;
        #pragma unroll
        for (int h = 0; h < 4; ++h) {
            size_t base = (((size_t)b * 4 + h) * SEQ + l) * 128 + 64 + j;
            g_Qeh[base] = vq;
            g_Keh[base] = vk;
        }
    }

    for (int m = 0; m < 3; ++m) {
        const float* w = (m == 0) ? wq : (m == 1) ? wk : wv;
        for (int h2 = 0; h2 < 2; ++h2) {
            __syncthreads();
            for (int i = t; i < 64 * 32; i += 256) {
                int r = i >> 5, c = (i & 31) * 4;
                *(float4*)(wbig + r * 132 + c) = *(const float4*)(w + r * 256 + h2 * 128 + c);
            }
            __syncthreads();

            float acc[8][4];
            #pragma unroll
            for (int i = 0; i < 8; ++i)
                #pragma unroll
                for (int j = 0; j < 4; ++j) acc[i][j] = 0.f;
            for (int k = 0; k < 64; ++k) {
                float av[8];
                #pragma unroll
                for (int i = 0; i < 8; ++i) av[i] = xs[(rg * 8 + i) * 68 + k];
                float4 bb = *(const float4*)(wbig + k * 132 + cg * 4);
                float bv[4] = {bb.x, bb.y, bb.z, bb.w};
                #pragma unroll
                for (int i = 0; i < 8; ++i)
                    #pragma unroll
                    for (int j = 0; j < 4; ++j) acc[i][j] += av[i] * bv[j];
            }

            const int gc = h2 * 128 + cg * 4;
            const int h  = gc >> 6;
            const int j0 = gc & 63;
            if (m == 2) {
                #pragma unroll
                for (int i = 0; i < 8; ++i) {
                    size_t l = lr0 + rg * 8 + i;
                    size_t base = (((size_t)b * 4 + h) * SEQ + l) * 64 + j0;
                    #pragma unroll
                    for (int j = 0; j < 4; ++j)
                        g_Ve[base + j] = acc[i][j] + uo[2 * 4352 + (rg * 8 + i) * 68 + j0 + j] * gv;
                }
            } else {
                __half* tgt = (m == 0) ? g_Qeh : g_Keh;
                float s = (m == 0) ? 0.125f : 1.0f;
                #pragma unroll
                for (int i = 0; i < 8; ++i) {
                    size_t l = lr0 + rg * 8 + i;
                    size_t base = (((size_t)b * 4 + h) * SEQ + l) * 128 + j0;
                    *(__half2*)(tgt + base)     = __floats2half2_rn(acc[i][0] * s, acc[i][1] * s);
                    *(__half2*)(tgt + base + 2) = __floats2half2_rn(acc[i][2] * s, acc[i][3] * s);
                }
            }
        }
    }
}

// ---------------------------------------------------------------------------
// Kernel 1b: transpose Ve -> g_Veh [bh][v][k] fp16
// ---------------------------------------------------------------------------
__global__ void __launch_bounds__(256) transpose_v_kernel() {
    __shared__ float ts[64][65];
    const int bh = blockIdx.x >> 5;
    const int kt = blockIdx.x & 31;
    const int t  = threadIdx.x;
    const float* src = g_Ve + ((size_t)bh * SEQ + kt * 64) * 64;
    for (int i = t; i < 64 * 16; i += 256) {
        int r = i >> 4, c = (i & 15) * 4;
        float4 v = *(const float4*)(src + (size_t)r * 64 + c);
        ts[r][c] = v.x; ts[r][c + 1] = v.y; ts[r][c + 2] = v.z; ts[r][c + 3] = v.w;
    }
    __syncthreads();
    __half* dst = g_Veh + (size_t)bh * 64 * SEQ + kt * 64;
    for (int i = t; i < 64 * 16; i += 256) {
        int v = i >> 4, k = (i & 15) * 4;
        __half2 h0 = __floats2half2_rn(ts[k][v],     ts[k + 1][v]);
        __half2 h1 = __floats2half2_rn(ts[k + 2][v], ts[k + 3][v]);
        *(__half2*)(dst + (size_t)v * SEQ + k)     = h0;
        *(__half2*)(dst + (size_t)v * SEQ + k + 2) = h1;
    }
}

// ---------------------------------------------------------------------------
// Kernel 2 (v7): attention, TQ=64 per CTA, M=32 per warp (B-frag reuse).
// 512 threads / 16 warps: qq = w>>3 selects 32-row half, n0 = (w&7)*8.
// Each warp: rows r0=qq*32+g, r1=+8, r2=+16, r3=+24; 2 mmas share each B pair.
// smem(halves): qs 64x136 | ks 2x64x136 | vsh 2x64x72 | psh 2x64x72
//   + red 512f | inv 64f | msb 2x128 u32  = 92,416 B  (2 CTAs/SM)
// ---------------------------------------------------------------------------
#define ATT_SMEM_BYTES ((64*KH + 2*64*KH + 2*64*VH + 2*64*VH) * 2 + 512*4 + 64*4 + 256*4)

__global__ void __launch_bounds__(512) attn2_kernel(float* __restrict__ attn_out) {
    extern __shared__ __half smh[];
    __half* qs  = smh;                       // 64 x 136
    __half* ks  = qs + 64 * KH;              // 2 x 64 x 136
    __half* vsh = ks + 2 * 64 * KH;          // 2 x 64 x 72
    __half* psh = vsh + 2 * 64 * VH;         // 2 x 64 x 72
    float*  red = (float*)(psh + 2 * 64 * VH);   // 16 x 32
    float*  inv = red + 512;                     // 64
    unsigned* msb = (unsigned*)(inv + 64);       // 2 x 128

    const int t    = threadIdx.x;
    const int w    = t >> 5;
    const int lane = t & 31;
    const int g    = lane >> 2;
    const int tig  = lane & 3;
    const int qq   = w >> 3;               // 0/1: 32-row half
    const int n0   = (w & 7) * 8;          // k-col group within tile
    const int r0   = qq * 32 + g;
    const int r1   = r0 + 8;
    const int r2   = r0 + 16;
    const int r3   = r0 + 24;

    const int bh = blockIdx.x >> 5;        // 32 q-tiles per (b,h)
    const int qt = blockIdx.x & 31;
    const int b  = bh >> 2;
    const int h  = bh & 3;
    const int q0 = qt * TQA;

    const __half* Qg = g_Qeh + ((size_t)bh * SEQ + q0) * 128;
    const __half* Kg = g_Keh + (size_t)bh * SEQ * 128;
    const __half* Vg = g_Veh + (size_t)bh * 64 * SEQ;
    const unsigned* Mb = g_maskb + ((size_t)b * SEQ + q0) * 64;
    __half* php = g_ph + ((size_t)bh * SEQ + q0) * SEQ;
    float* ao = attn_out + ((size_t)bh * SEQ + q0) * SEQ;

    // ---- stage Q + tile 0 ----
    for (int i = t; i < TQA * 16; i += 512) {
        int r = i >> 4, c8 = (i & 15) * 8;
        cp_async16(qs + r * KH + c8, Qg + (size_t)r * 128 + c8);
    }
    for (int i = t; i < 64 * 16; i += 512) {
        int r = i >> 4, c8 = (i & 15) * 8;
        cp_async16(ks + r * KH + c8, Kg + (size_t)r * 128 + c8);
    }
    for (int i = t; i < 64 * 8; i += 512) {
        int r = i >> 3, c8 = (i & 7) * 8;
        cp_async16(vsh + r * VH + c8, Vg + (size_t)r * SEQ + c8);
    }
    if (t < 2 * TQA)
        cp_async4(msb + t, Mb + (size_t)(t >> 1) * 64 + (t & 1));
    CP_COMMIT();
    CP_WAIT(0);
    __syncthreads();

    // ---- hoist A (Q) fragments for all 4 row groups ----
    unsigned aA[8][4], aB[8][4];
    #pragma unroll
    for (int kk = 0; kk < 8; ++kk) {
        aA[kk][0] = *(const unsigned*)(qs + r0 * KH + kk * 16 + 2 * tig);
        aA[kk][1] = *(const unsigned*)(qs + r1 * KH + kk * 16 + 2 * tig);
        aA[kk][2] = *(const unsigned*)(qs + r0 * KH + kk * 16 + 2 * tig + 8);
        aA[kk][3] = *(const unsigned*)(qs + r1 * KH + kk * 16 + 2 * tig + 8);
        aB[kk][0] = *(const unsigned*)(qs + r2 * KH + kk * 16 + 2 * tig);
        aB[kk][1] = *(const unsigned*)(qs + r3 * KH + kk * 16 + 2 * tig);
        aB[kk][2] = *(const unsigned*)(qs + r2 * KH + kk * 16 + 2 * tig + 8);
        aB[kk][3] = *(const unsigned*)(qs + r3 * KH + kk * 16 + 2 * tig + 8);
    }

    float cxA0 = 0.f, cxA1 = 0.f, cxA2 = 0.f, cxA3 = 0.f;
    float cxB0 = 0.f, cxB1 = 0.f, cxB2 = 0.f, cxB3 = 0.f;
    float s0 = 0.f, s1 = 0.f, s2 = 0.f, s3 = 0.f;
    const int col = n0 + 2 * tig;

    for (int tile = 0; tile < SEQ / 64; ++tile) {
        const int buf = tile & 1;
        const __half* kb = ks  + buf * 64 * KH;
        const __half* vb = vsh + buf * 64 * VH;
        const __half* pb = psh + buf * 64 * VH;
        const unsigned* mb = msb + buf * 2 * TQA;
        const int k0 = tile * 64;

        // ---- prefetch tile+1 ----
        if (tile + 1 < SEQ / 64) {
            const int nb = buf ^ 1;
            const int nk0 = k0 + 64;
            for (int i = t; i < 64 * 16; i += 512) {
                int r = i >> 4, c8 = (i & 15) * 8;
                cp_async16(ks + nb * 64 * KH + r * KH + c8,
                           Kg + (size_t)(nk0 + r) * 128 + c8);
            }
            for (int i = t; i < 64 * 8; i += 512) {
                int r = i >> 3, c8 = (i & 7) * 8;
                cp_async16(vsh + nb * 64 * VH + r * VH + c8,
                           Vg + (size_t)r * SEQ + nk0 + c8);
            }
            if (t < 2 * TQA)
                cp_async4(msb + nb * 2 * TQA + t,
                          Mb + (size_t)(t >> 1) * 64 + (nk0 >> 5) + (t & 1));
            CP_COMMIT();
        }

        // ---- QK scores: 8 chunks x 2 mmas sharing B ----
        float cA0 = 0.f, cA1 = 0.f, cA2 = 0.f, cA3 = 0.f;
        float cB0 = 0.f, cB1 = 0.f, cB2 = 0.f, cB3 = 0.f;
        #pragma unroll
        for (int kk = 0; kk < 8; ++kk) {
            unsigned b0 = *(const unsigned*)(kb + (n0 + g) * KH + kk * 16 + 2 * tig);
            unsigned b1 = *(const unsigned*)(kb + (n0 + g) * KH + kk * 16 + 2 * tig + 8);
            mma_f16_k16(cA0, cA1, cA2, cA3, aA[kk][0], aA[kk][1], aA[kk][2], aA[kk][3], b0, b1);
            mma_f16_k16(cB0, cB1, cB2, cB3, aB[kk][0], aB[kk][1], aB[kk][2], aB[kk][3], b0, b1);
        }

        // ---- mask + exp (4 rows x 2 cols) ----
        unsigned w0 = mb[r0 * 2 + (col >> 5)];
        unsigned w1 = mb[r1 * 2 + (col >> 5)];
        unsigned w2 = mb[r2 * 2 + (col >> 5)];
        unsigned w3 = mb[r3 * 2 + (col >> 5)];
        float p00 = ((w0 >> (col & 31)) & 1u)       ? 0.f : __expf(cA0);
        float p01 = ((w0 >> ((col + 1) & 31)) & 1u) ? 0.f : __expf(cA1);
        float p10 = ((w1 >> (col & 31)) & 1u)       ? 0.f : __expf(cA2);
        float p11 = ((w1 >> ((col + 1) & 31)) & 1u) ? 0.f : __expf(cA3);
        float p20 = ((w2 >> (col & 31)) & 1u)       ? 0.f : __expf(cB0);
        float p21 = ((w2 >> ((col + 1) & 31)) & 1u) ? 0.f : __expf(cB1);
        float p30 = ((w3 >> (col & 31)) & 1u)       ? 0.f : __expf(cB2);
        float p31 = ((w3 >> ((col + 1) & 31)) & 1u) ? 0.f : __expf(cB3);
        s0 += p00 + p01;
        s1 += p10 + p11;
        s2 += p20 + p21;
        s3 += p30 + p31;

        // ---- p fp16 -> scratch global + psh ----
        __half2 hp0 = __floats2half2_rn(p00, p01);
        __half2 hp1 = __floats2half2_rn(p10, p11);
        __half2 hp2 = __floats2half2_rn(p20, p21);
        __half2 hp3 = __floats2half2_rn(p30, p31);
        *(__half2*)(php + (size_t)r0 * SEQ + k0 + col) = hp0;
        *(__half2*)(php + (size_t)r1 * SEQ + k0 + col) = hp1;
        *(__half2*)(php + (size_t)r2 * SEQ + k0 + col) = hp2;
        *(__half2*)(php + (size_t)r3 * SEQ + k0 + col) = hp3;
        __half* pw = psh + buf * 64 * VH;
        *(__half2*)(pw + r0 * VH + col) = hp0;
        *(__half2*)(pw + r1 * VH + col) = hp1;
        *(__half2*)(pw + r2 * VH + col) = hp2;
        *(__half2*)(pw + r3 * VH + col) = hp3;
        __syncthreads();    // S1: psh complete

        // ---- fp16 PV: 4 chunks x 2 mmas sharing V ----
        #pragma unroll
        for (int kk = 0; kk < 4; ++kk) {
            unsigned vb0 = *(const unsigned*)(vb + (n0 + g) * VH + kk * 16 + 2 * tig);
            unsigned vb1 = *(const unsigned*)(vb + (n0 + g) * VH + kk * 16 + 2 * tig + 8);
            unsigned paA0 = *(const unsigned*)(pb + r0 * VH + kk * 16 + 2 * tig);
            unsigned paA1 = *(const unsigned*)(pb + r1 * VH + kk * 16 + 2 * tig);
            unsigned paA2 = *(const unsigned*)(pb + r0 * VH + kk * 16 + 2 * tig + 8);
            unsigned paA3 = *(const unsigned*)(pb + r1 * VH + kk * 16 + 2 * tig + 8);
            mma_f16_k16(cxA0, cxA1, cxA2, cxA3, paA0, paA1, paA2, paA3, vb0, vb1);
            unsigned paB0 = *(const unsigned*)(pb + r2 * VH + kk * 16 + 2 * tig);
            unsigned paB1 = *(const unsigned*)(pb + r3 * VH + kk * 16 + 2 * tig);
            unsigned paB2 = *(const unsigned*)(pb + r2 * VH + kk * 16 + 2 * tig + 8);
            unsigned paB3 = *(const unsigned*)(pb + r3 * VH + kk * 16 + 2 * tig + 8);
            mma_f16_k16(cxB0, cxB1, cxB2, cxB3, paB0, paB1, paB2, paB3, vb0, vb1);
        }

        CP_WAIT(0);
        __syncthreads();    // S2: next tile visible; buffers free
    }

    // ---- row-sum reduction ----
    s0 += __shfl_xor_sync(0xffffffffu, s0, 1);
    s0 += __shfl_xor_sync(0xffffffffu, s0, 2);
    s1 += __shfl_xor_sync(0xffffffffu, s1, 1);
    s1 += __shfl_xor_sync(0xffffffffu, s1, 2);
    s2 += __shfl_xor_sync(0xffffffffu, s2, 1);
    s2 += __shfl_xor_sync(0xffffffffu, s2, 2);
    s3 += __shfl_xor_sync(0xffffffffu, s3, 1);
    s3 += __shfl_xor_sync(0xffffffffu, s3, 2);
    if (tig == 0) {
        red[w * 32 + g]      = s0;
        red[w * 32 + 8 + g]  = s1;
        red[w * 32 + 16 + g] = s2;
        red[w * 32 + 24 + g] = s3;
    }
    __syncthreads();
    if (t < TQA) {
        int half = t >> 5;
        int lr   = t & 31;
        float s = 0.f;
        #pragma unroll
        for (int ww = 0; ww < 8; ++ww) s += red[(half * 8 + ww) * 32 + lr];
        inv[t] = 1.f / s;
    }
    __syncthreads();

    // ---- normalized ctx write (4 rows) ----
    {
        float iv0 = inv[r0], iv1 = inv[r1], iv2 = inv[r2], iv3 = inv[r3];
        size_t rr = (size_t)b * SEQ + q0;
        *(float2*)(g_ctx + (rr + r0) * 256 + h * 64 + col) = make_float2(cxA0 * iv0, cxA1 * iv0);
        *(float2*)(g_ctx + (rr + r1) * 256 + h * 64 + col) = make_float2(cxA2 * iv1, cxA3 * iv1);
        *(float2*)(g_ctx + (rr + r2) * 256 + h * 64 + col) = make_float2(cxB0 * iv2, cxB1 * iv2);
        *(float2*)(g_ctx + (rr + r3) * 256 + h * 64 + col) = make_float2(cxB2 * iv3, cxB3 * iv3);
    }

    // ---- normalize: read fp16 scratch (L2-warm), write fp32 attn once ----
    for (int r = 0; r < TQA; ++r) {
        float iv = inv[r];
        const __half2* src = (const __half2*)(php + (size_t)r * SEQ) + t * 2;
        __half2 h0 = src[0];
        __half2 h1 = src[1];
        float2 f0 = __half22float2(h0);
        float2 f1 = __half22float2(h1);
        float4 v;
        v.x = f0.x * iv; v.y = f0.y * iv; v.z = f1.x * iv; v.w = f1.y * iv;
        *((float4*)(ao + (size_t)r * SEQ) + t) = v;
    }
}

// ---------------------------------------------------------------------------
// Kernel 3: fc + LN1 + FFN + LN2 (unchanged)
// ---------------------------------------------------------------------------
#define POST_SMEM_BYTES ((64*260 + 256*68 + 4*64*68) * 4)

__global__ void __launch_bounds__(256) post_kernel(
    const float* __restrict__ x, const float* __restrict__ fcw,
    const float* __restrict__ ln1g, const float* __restrict__ ln1b,
    const float* __restrict__ f1, const float* __restrict__ f2,
    const float* __restrict__ ln2g, const float* __restrict__ ln2b,
    float* __restrict__ res) {
    extern __shared__ float sm[];
    float* cs  = sm;                 // 64 x 260
    float* fs  = cs + 64 * 260;      // 256 x 68
    float* hs  = fs + 256 * 68;      // 64 x 68
    float* es  = hs + 64 * 68;       // 64 x 68
    float* f1s = es + 64 * 68;       // 64 x 68
    float* f2s = f1s + 64 * 68;      // 64 x 68

    const int t = threadIdx.x;
    const int row0 = blockIdx.x * 64;

    for (int i = t; i < 64 * 64; i += 256) {
        int r = i >> 6, c = (i & 63) * 4;
        *(float4*)(cs + r * 260 + c) = *(const float4*)(g_ctx + (size_t)(row0 + r) * 256 + c);
    }
    for (int i = t; i < 256 * 16; i += 256) {
        int r = i >> 4, c = (i & 15) * 4;
        *(float4*)(fs + r * 68 + c) = *(const float4*)(fcw + r * 64 + c);
    }
    for (int i = t; i < 64 * 16; i += 256) {
        int r = i >> 4, c = (i & 15) * 4;
        *(float4*)(hs + r * 68 + c)  = *(const float4*)(x + (size_t)(row0 + r) * DM + c);
        *(float4*)(f1s + r * 68 + c) = *(const float4*)(f1 + r * 64 + c);
        *(float4*)(f2s + r * 68 + c) = *(const float4*)(f2 + r * 64 + c);
    }
    __syncthreads();

    const int rg = t >> 4;
    const int cg = t & 15;

    float acc[4][4];
    #pragma unroll
    for (int i = 0; i < 4; ++i)
        #pragma unroll
        for (int j = 0; j < 4; ++j) acc[i][j] = 0.f;
    for (int k = 0; k < 256; ++k) {
        float av[4];
        #pragma unroll
        for (int i = 0; i < 4; ++i) av[i] = cs[(rg * 4 + i) * 260 + k];
        float4 bb = *(const float4*)(fs + k * 68 + cg * 4);
        float bv[4] = {bb.x, bb.y, bb.z, bb.w};
        #pragma unroll
        for (int i = 0; i < 4; ++i)
            #pragma unroll
            for (int j = 0; j < 4; ++j) acc[i][j] += av[i] * bv[j];
    }

    #pragma unroll
    for (int i = 0; i < 4; ++i) {
        float y[4];
        #pragma unroll
        for (int j = 0; j < 4; ++j) y[j] = acc[i][j] + hs[(rg * 4 + i) * 68 + cg * 4 + j];
        float s = y[0] + y[1] + y[2] + y[3];
        float q = y[0]*y[0] + y[1]*y[1] + y[2]*y[2] + y[3]*y[3];
        #pragma unroll
        for (int o = 1; o < 16; o <<= 1) {
            s += __shfl_xor_sync(0xffffffffu, s, o);
            q += __shfl_xor_sync(0xffffffffu, q, o);
        }
        float mu = s * (1.f / 64.f);
        float var = q * (1.f / 64.f) - mu * mu;
        float rs = rsqrtf(var + 1e-5f);
        #pragma unroll
        for (int j = 0; j < 4; ++j) {
            int c = cg * 4 + j;
            es[(rg * 4 + i) * 68 + c] = (y[j] - mu) * rs * ln1g[c] + ln1b[c];
        }
    }
    __syncthreads();

    float h4[4][4];
    #pragma unroll
    for (int i = 0; i < 4; ++i)
        #pragma unroll
        for (int j = 0; j < 4; ++j) h4[i][j] = 0.f;
    for (int k = 0; k < 64; ++k) {
        float av[4];
        #pragma unroll
        for (int i = 0; i < 4; ++i) av[i] = es[(rg * 4 + i) * 68 + k];
        float4 bb = *(const float4*)(f1s + k * 68 + cg * 4);
        float bv[4] = {bb.x, bb.y, bb.z, bb.w};
        #pragma unroll
        for (int i = 0; i < 4; ++i)
            #pragma unroll
            for (int j = 0; j < 4; ++j) h4[i][j] += av[i] * bv[j];
    }
    #pragma unroll
    for (int i = 0; i < 4; ++i)
        #pragma unroll
        for (int j = 0; j < 4; ++j)
            hs[(rg * 4 + i) * 68 + cg * 4 + j] = fmaxf(h4[i][j], 0.f);
    __syncthreads();

    float fa[4][4];
    #pragma unroll
    for (int i = 0; i < 4; ++i)
        #pragma unroll
        for (int j = 0; j < 4; ++j) fa[i][j] = 0.f;
    for (int k = 0; k < 64; ++k) {
        float av[4];
        #pragma unroll
        for (int i = 0; i < 4; ++i) av[i] = hs[(rg * 4 + i) * 68 + k];
        float4 bb = *(const float4*)(f2s + k * 68 + cg * 4);
        float bv[4] = {bb.x, bb.y, bb.z, bb.w};
        #pragma unroll
        for (int i = 0; i < 4; ++i)
            #pragma unroll
            for (int j = 0; j < 4; ++j) fa[i][j] += av[i] * bv[j];
    }
    #pragma unroll
    for (int i = 0; i < 4; ++i) {
        float y[4];
        #pragma unroll
        for (int j = 0; j < 4; ++j) y[j] = fa[i][j] + es[(rg * 4 + i) * 68 + cg * 4 + j];
        float s = y[0] + y[1] + y[2] + y[3];
        float q = y[0]*y[0] + y[1]*y[1] + y[2]*y[2] + y[3]*y[3];
        #pragma unroll
        for (int o = 1; o < 16; o <<= 1) {
            s += __shfl_xor_sync(0xffffffffu, s, o);
            q += __shfl_xor_sync(0xffffffffu, q, o);
        }
        float mu = s * (1.f / 64.f);
        float var = q * (1.f / 64.f) - mu * mu;
        float rs = rsqrtf(var + 1e-5f);
        float4 o4;
        o4.x = (y[0] - mu) * rs * ln2g[cg * 4 + 0] + ln2b[cg * 4 + 0];
        o4.y = (y[1] - mu) * rs * ln2g[cg * 4 + 1] + ln2b[cg * 4 + 1];
        o4.z = (y[2] - mu) * rs * ln2g[cg * 4 + 2] + ln2b[cg * 4 + 2];
        o4.w = (y[3] - mu) * rs * ln2g[cg * 4 + 3] + ln2b[cg * 4 + 3];
        *(float4*)(res + (size_t)(row0 + rg * 4 + i) * 64 + cg * 4) = o4;
    }
}

// ---------------------------------------------------------------------------
// Launch
// ---------------------------------------------------------------------------
extern "C" void kernel_launch(void* const* d_in, const int* in_sizes, int n_in,
                              void* d_out, int out_size) {
    const float* x    = (const float*)d_in[0];
    const void*  mask = d_in[1];
    const float* u    = (const float*)d_in[2];
    const float* wq   = (const float*)d_in[3];
    const float* wk   = (const float*)d_in[4];
    const float* wv   = (const float*)d_in[5];
    const float* uqw  = (const float*)d_in[6];
    const float* ukw  = (const float*)d_in[7];
    const float* uvw  = (const float*)d_in[8];
    const float* sq1  = (const float*)d_in[9];
    const float* sq2  = (const float*)d_in[10];
    const float* sk1  = (const float*)d_in[11];
    const float* sk2  = (const float*)d_in[12];
    const float* sv1  = (const float*)d_in[13];
    const float* sv2  = (const float*)d_in[14];
    const float* fcw  = (const float*)d_in[15];
    const float* ln1g = (const float*)d_in[16];
    const float* ln1b = (const float*)d_in[17];
    const float* ffn1 = (const float*)d_in[18];
    const float* ffn2 = (const float*)d_in[19];
    const float* ln2g = (const float*)d_in[20];
    const float* ln2b = (const float*)d_in[21];

    float* res  = (float*)d_out;
    float* attn = res + (size_t)NB * SEQ * DM;

    cudaFuncSetAttribute(proj_kernel,  cudaFuncAttributeMaxDynamicSharedMemorySize, PROJ_SMEM_BYTES);
    cudaFuncSetAttribute(attn2_kernel, cudaFuncAttributeMaxDynamicSharedMemorySize, ATT_SMEM_BYTES);
    cudaFuncSetAttribute(post_kernel,  cudaFuncAttributeMaxDynamicSharedMemorySize, POST_SMEM_BYTES);

    detect_mask_kernel<<<1, 32>>>((const unsigned char*)mask);
    convert_mask_kernel<<<(NB * SEQ * SEQ) / 256, 256>>>(mask);
    gates_kernel<<<NB, 32>>>(u, sq1, sq2, sk1, sk2, sv1, sv2);
    proj_kernel<<<(NB * SEQ) / 64, 256, PROJ_SMEM_BYTES>>>(x, wq, wk, wv, uqw, ukw, uvw);
    transpose_v_kernel<<<NB * NH * 32, 256>>>();
    attn2_kernel<<<NB * NH * (SEQ / TQA), 512, ATT_SMEM_BYTES>>>(attn);
    post_kernel<<<(NB * SEQ) / 64, 256, POST_SMEM_BYTES>>>(x, fcw, ln1g, ln1b, ffn1, ffn2,
                                                           ln2g, ln2b, res);
}

// round 11
// speedup vs baseline: 1.1235x; 1.1235x over previous
#include <cuda_runtime.h>
#include <cuda_fp16.h>
#include <cstdint>
#include <cstddef>

// ---------------------------------------------------------------------------
// Problem constants
// ---------------------------------------------------------------------------
#define NB   8
#define NH   4
#define SEQ  2048
#define DM   64

// attention tiling
#define TQ   32          // q rows per CTA
#define KH   136         // half stride for qs/ks rows (128 data + 8 pad)
#define VH   72          // half stride for vsh / psh rows
#define NT   (SEQ / 64)  // 32 k-tiles

#define LOG2E 1.4426950408889634f

// ---------------------------------------------------------------------------
// Static device scratch
// ---------------------------------------------------------------------------
__device__ float    g_gates[3 * NB];
__device__ int      g_mask_mode;                           // 1 = int32 mask, 0 = byte mask
__device__ __half   g_Qeh[(size_t)NB * NH * SEQ * 128];    // 16.8 MB fp16 (scaled by 0.125*log2e)
__device__ __half   g_Keh[(size_t)NB * NH * SEQ * 128];    // 16.8 MB fp16
__device__ float    g_Ve[(size_t)NB * NH * SEQ * 64];      // 16.8 MB
__device__ __half   g_Veh[(size_t)NB * NH * 64 * SEQ];     // 8.4 MB (transposed [v][k] fp16)
__device__ float    g_ctx[(size_t)NB * SEQ * 256];         // 16.8 MB
__device__ unsigned g_maskb[(size_t)NB * SEQ * 64];        // 4 MB (bit-packed mask)
__device__ __half   g_ph[(size_t)NB * NH * SEQ * SEQ];     // 268 MB fp16 p scratch

// ---------------------------------------------------------------------------
// Helpers
// ---------------------------------------------------------------------------
__device__ __forceinline__ void mma_f16_k16(float& c0, float& c1, float& c2, float& c3,
                                            unsigned a0, unsigned a1, unsigned a2, unsigned a3,
                                            unsigned b0, unsigned b1) {
    asm volatile(
        "mma.sync.aligned.m16n8k16.row.col.f32.f16.f16.f32 "
        "{%0,%1,%2,%3},{%4,%5,%6,%7},{%8,%9},{%0,%1,%2,%3};"
        : "+f"(c0), "+f"(c1), "+f"(c2), "+f"(c3)
        : "r"(a0), "r"(a1), "r"(a2), "r"(a3), "r"(b0), "r"(b1));
}

__device__ __forceinline__ __half2 h2exp2_approx(__half2 x) {
    __half2 r;
    asm("ex2.approx.f16x2 %0, %1;" : "=r"(*(unsigned*)&r) : "r"(*(unsigned*)&x));
    return r;
}

__device__ __forceinline__ void cp_async16(void* smem, const void* gmem) {
    unsigned sa = (unsigned)__cvta_generic_to_shared(smem);
    asm volatile("cp.async.cg.shared.global [%0], [%1], 16;\n" :: "r"(sa), "l"(gmem));
}
__device__ __forceinline__ void cp_async4(void* smem, const void* gmem) {
    unsigned sa = (unsigned)__cvta_generic_to_shared(smem);
    asm volatile("cp.async.ca.shared.global [%0], [%1], 4;\n" :: "r"(sa), "l"(gmem));
}
#define CP_COMMIT() asm volatile("cp.async.commit_group;\n")
#define CP_WAIT(n)  asm volatile("cp.async.wait_group %0;\n" :: "n"(n))

// ---------------------------------------------------------------------------
// Kernel D: detect mask encoding (int32 vs byte)
// ---------------------------------------------------------------------------
__global__ void detect_mask_kernel(const unsigned char* __restrict__ m) {
    int found = 0;
    for (int i = threadIdx.x; i < 1024; i += 32)
        if (m[i * 4 + 1] | m[i * 4 + 2] | m[i * 4 + 3]) found = 1;
    for (int o = 16; o; o >>= 1)
        found |= __shfl_xor_sync(0xffffffffu, found, o);
    if (threadIdx.x == 0) g_mask_mode = found ? 0 : 1;
}

// ---------------------------------------------------------------------------
// Kernel M: bit-pack the mask (ballot-based, coalesced)
// ---------------------------------------------------------------------------
__global__ void __launch_bounds__(256) convert_mask_kernel(const void* __restrict__ mask) {
    unsigned gid = blockIdx.x * 256 + threadIdx.x;
    unsigned nz;
    if (g_mask_mode) nz = (((const int*)mask)[gid] != 0) ? 1u : 0u;
    else             nz = (((const unsigned char*)mask)[gid] != 0) ? 1u : 0u;
    unsigned bits = __ballot_sync(0xffffffffu, nz);
    if ((threadIdx.x & 31) == 0) g_maskb[gid >> 5] = bits;
}

// ---------------------------------------------------------------------------
// Kernel 0: scalar gates
// ---------------------------------------------------------------------------
__global__ void gates_kernel(const float* __restrict__ u,
                             const float* __restrict__ sq1, const float* __restrict__ sq2,
                             const float* __restrict__ sk1, const float* __restrict__ sk2,
                             const float* __restrict__ sv1, const float* __restrict__ sv2) {
    const int b = blockIdx.x;
    const int lane = threadIdx.x;
    float hq = 0.f, hk = 0.f, hv = 0.f;
    for (int d = 0; d < DM; ++d) {
        float uv = u[b * DM + d];
        hq += uv * sq1[d * 32 + lane];
        hk += uv * sk1[d * 32 + lane];
        hv += uv * sv1[d * 32 + lane];
    }
    hq = fmaxf(hq, 0.f) * sq2[lane];
    hk = fmaxf(hk, 0.f) * sk2[lane];
    hv = fmaxf(hv, 0.f) * sv2[lane];
    for (int off = 16; off; off >>= 1) {
        hq += __shfl_xor_sync(0xffffffffu, hq, off);
        hk += __shfl_xor_sync(0xffffffffu, hk, off);
        hv += __shfl_xor_sync(0xffffffffu, hv, off);
    }
    if (lane == 0) {
        g_gates[b]      = hq;
        g_gates[8 + b]  = hk;
        g_gates[16 + b] = hv;
    }
}

// ---------------------------------------------------------------------------
// Kernel 1 (v3): projections, 2 CTAs/SM. Weight tiles in 64x132 halves.
// Q side carries 0.125*log2e so attention scores arrive pre-scaled for exp2.
// ---------------------------------------------------------------------------
#define PROJ_SMEM_BYTES ((64*68 + 3*64*68 + 64*132) * 4)

__global__ void __launch_bounds__(256, 2) proj_kernel(
    const float* __restrict__ x,
    const float* __restrict__ wq, const float* __restrict__ wk, const float* __restrict__ wv,
    const float* __restrict__ uqw, const float* __restrict__ ukw, const float* __restrict__ uvw) {
    extern __shared__ float sm[];
    float* xs   = sm;                 // 64 x 68
    float* uo   = xs + 64 * 68;       // 3 x (64 x 68): u-weights, then u outputs
    float* wbig = uo + 3 * 64 * 68;   // 64 x 132

    const int t = threadIdx.x;
    const int row0 = blockIdx.x * 64;
    const int b    = row0 >> 11;
    const int lr0  = row0 & (SEQ - 1);

    for (int i = t; i < 64 * 16; i += 256) {
        int r = i >> 4, c = (i & 15) * 4;
        *(float4*)(xs + r * 68 + c)            = *(const float4*)(x + (size_t)(row0 + r) * DM + c);
        *(float4*)(uo + 0 * 4352 + r * 68 + c) = *(const float4*)(uqw + r * 64 + c);
        *(float4*)(uo + 1 * 4352 + r * 68 + c) = *(const float4*)(ukw + r * 64 + c);
        *(float4*)(uo + 2 * 4352 + r * 68 + c) = *(const float4*)(uvw + r * 64 + c);
    }
    __syncthreads();

    const int rg = t >> 5;
    const int cg = t & 31;

    float uacc[8][8];
    if (cg < 24) {
        const int mat = cg >> 3;
        const int c0 = (cg & 7) * 8;
        const float* w = uo + mat * 4352;
        #pragma unroll
        for (int i = 0; i < 8; ++i)
            #pragma unroll
            for (int j = 0; j < 8; ++j) uacc[i][j] = 0.f;
        for (int k = 0; k < 64; ++k) {
            float av[8];
            #pragma unroll
            for (int i = 0; i < 8; ++i) av[i] = xs[(rg * 8 + i) * 68 + k];
            float4 b0 = *(const float4*)(w + k * 68 + c0);
            float4 b1 = *(const float4*)(w + k * 68 + c0 + 4);
            float bv[8] = {b0.x, b0.y, b0.z, b0.w, b1.x, b1.y, b1.z, b1.w};
            #pragma unroll
            for (int i = 0; i < 8; ++i)
                #pragma unroll
                for (int j = 0; j < 8; ++j) uacc[i][j] += av[i] * bv[j];
        }
    }
    __syncthreads();

    if (cg < 24) {
        const int mat = cg >> 3;
        const int c0 = (cg & 7) * 8;
        float* dst = uo + mat * 4352;
        #pragma unroll
        for (int i = 0; i < 8; ++i)
            #pragma unroll
            for (int j = 0; j < 8; ++j)
                dst[(rg * 8 + i) * 68 + c0 + j] = uacc[i][j];
    }
    __syncthreads();

    const float gq = g_gates[b] * 0.125f * LOG2E;
    const float gk = g_gates[8 + b];
    const float gv = g_gates[16 + b];

    for (int i = t; i < 64 * 64; i += 256) {
        int r = i >> 6, j = i & 63;
        __half vq = __float2half(uo[r * 68 + j] * gq);
        __half vk = __float2half(uo[4352 + r * 68 + j] * gk);
        size_t l = lr0 + r;
        #pragma unroll
        for (int h = 0; h < 4; ++h) {
            size_t base = (((size_t)b * 4 + h) * SEQ + l) * 128 + 64 + j;
            g_Qeh[base] = vq;
            g_Keh[base] = vk;
        }
    }

    for (int m = 0; m < 3; ++m) {
        const float* w = (m == 0) ? wq : (m == 1) ? wk : wv;
        for (int h2 = 0; h2 < 2; ++h2) {
            __syncthreads();
            for (int i = t; i < 64 * 32; i += 256) {
                int r = i >> 5, c = (i & 31) * 4;
                *(float4*)(wbig + r * 132 + c) = *(const float4*)(w + r * 256 + h2 * 128 + c);
            }
            __syncthreads();

            float acc[8][4];
            #pragma unroll
            for (int i = 0; i < 8; ++i)
                #pragma unroll
                for (int j = 0; j < 4; ++j) acc[i][j] = 0.f;
            for (int k = 0; k < 64; ++k) {
                float av[8];
                #pragma unroll
                for (int i = 0; i < 8; ++i) av[i] = xs[(rg * 8 + i) * 68 + k];
                float4 bb = *(const float4*)(wbig + k * 132 + cg * 4);
                float bv[4] = {bb.x, bb.y, bb.z, bb.w};
                #pragma unroll
                for (int i = 0; i < 8; ++i)
                    #pragma unroll
                    for (int j = 0; j < 4; ++j) acc[i][j] += av[i] * bv[j];
            }

            const int gc = h2 * 128 + cg * 4;
            const int h  = gc >> 6;
            const int j0 = gc & 63;
            if (m == 2) {
                #pragma unroll
                for (int i = 0; i < 8; ++i) {
                    size_t l = lr0 + rg * 8 + i;
                    size_t base = (((size_t)b * 4 + h) * SEQ + l) * 64 + j0;
                    #pragma unroll
                    for (int j = 0; j < 4; ++j)
                        g_Ve[base + j] = acc[i][j] + uo[2 * 4352 + (rg * 8 + i) * 68 + j0 + j] * gv;
                }
            } else {
                __half* tgt = (m == 0) ? g_Qeh : g_Keh;
                float s = (m == 0) ? (0.125f * LOG2E) : 1.0f;
                #pragma unroll
                for (int i = 0; i < 8; ++i) {
                    size_t l = lr0 + rg * 8 + i;
                    size_t base = (((size_t)b * 4 + h) * SEQ + l) * 128 + j0;
                    *(__half2*)(tgt + base)     = __floats2half2_rn(acc[i][0] * s, acc[i][1] * s);
                    *(__half2*)(tgt + base + 2) = __floats2half2_rn(acc[i][2] * s, acc[i][3] * s);
                }
            }
        }
    }
}

// ---------------------------------------------------------------------------
// Kernel 1b: transpose Ve -> g_Veh [bh][v][k] fp16
// ---------------------------------------------------------------------------
__global__ void __launch_bounds__(256) transpose_v_kernel() {
    __shared__ float ts[64][65];
    const int bh = blockIdx.x >> 5;
    const int kt = blockIdx.x & 31;
    const int t  = threadIdx.x;
    const float* src = g_Ve + ((size_t)bh * SEQ + kt * 64) * 64;
    for (int i = t; i < 64 * 16; i += 256) {
        int r = i >> 4, c = (i & 15) * 4;
        float4 v = *(const float4*)(src + (size_t)r * 64 + c);
        ts[r][c] = v.x; ts[r][c + 1] = v.y; ts[r][c + 2] = v.z; ts[r][c + 3] = v.w;
    }
    __syncthreads();
    __half* dst = g_Veh + (size_t)bh * 64 * SEQ + kt * 64;
    for (int i = t; i < 64 * 16; i += 256) {
        int v = i >> 4, k = (i & 15) * 4;
        __half2 h0 = __floats2half2_rn(ts[k][v],     ts[k + 1][v]);
        __half2 h1 = __floats2half2_rn(ts[k + 2][v], ts[k + 3][v]);
        *(__half2*)(dst + (size_t)v * SEQ + k)     = h0;
        *(__half2*)(dst + (size_t)v * SEQ + k + 2) = h1;
    }
}

// ---------------------------------------------------------------------------
// Kernel 2 (v8): attention. TQ=32, 512 threads, 3-deep cp.async pipeline,
// fp16x2 ex2.approx exponent (scores arrive pre-scaled by log2e).
// smem(halves): qs 32x136 | ks 3x64x136 | vsh 3x64x72 | psh 2x32x72
//   + red 256f | inv 32f | msb 3x64 u32  = 99,712 B
// ---------------------------------------------------------------------------
#define ATT_SMEM_BYTES ((TQ*KH + 3*64*KH + 3*64*VH + 2*TQ*VH) * 2 + 256*4 + 32*4 + 192*4)

__global__ void __launch_bounds__(512) attn2_kernel(float* __restrict__ attn_out) {
    extern __shared__ __half smh[];
    __half* qs  = smh;                       // 32 x 136
    __half* ks  = qs + TQ * KH;              // 3 x 64 x 136
    __half* vsh = ks + 3 * 64 * KH;          // 3 x 64 x 72
    __half* psh = vsh + 3 * 64 * VH;         // 2 x 32 x 72
    float*  red = (float*)(psh + 2 * TQ * VH);   // 16 x 16
    float*  inv = red + 256;                     // 32
    unsigned* msb = (unsigned*)(inv + 32);       // 3 x 64

    const int t    = threadIdx.x;
    const int w    = t >> 5;
    const int lane = t & 31;
    const int g    = lane >> 2;
    const int tig  = lane & 3;
    const int qh   = w >> 3;               // 0/1: 16-row half
    const int n0   = (w & 7) * 8;          // k-col group within tile
    const int ra   = qh * 16 + g;
    const int rb   = ra + 8;

    const int bh = blockIdx.x >> 6;        // 64 q-tiles per (b,h)
    const int qt = blockIdx.x & 63;
    const int b  = bh >> 2;
    const int h  = bh & 3;
    const int q0 = qt * TQ;

    const __half* Qg = g_Qeh + ((size_t)bh * SEQ + q0) * 128;
    const __half* Kg = g_Keh + (size_t)bh * SEQ * 128;
    const __half* Vg = g_Veh + (size_t)bh * 64 * SEQ;
    const unsigned* Mb = g_maskb + ((size_t)b * SEQ + q0) * 64;
    __half* php = g_ph + ((size_t)bh * SEQ + q0) * SEQ;
    float* ao = attn_out + ((size_t)bh * SEQ + q0) * SEQ;

    // ---- stage Q + tile 0 (group 0) ----
    for (int i = t; i < TQ * 16; i += 512) {
        int r = i >> 4, c8 = (i & 15) * 8;
        cp_async16(qs + r * KH + c8, Qg + (size_t)r * 128 + c8);
    }
    for (int i = t; i < 64 * 16; i += 512) {
        int r = i >> 4, c8 = (i & 15) * 8;
        cp_async16(ks + r * KH + c8, Kg + (size_t)r * 128 + c8);
    }
    for (int i = t; i < 64 * 8; i += 512) {
        int r = i >> 3, c8 = (i & 7) * 8;
        cp_async16(vsh + r * VH + c8, Vg + (size_t)r * SEQ + c8);
    }
    if (t < 2 * TQ)
        cp_async4(msb + t, Mb + (size_t)(t >> 1) * 64 + (t & 1));
    CP_COMMIT();

    // ---- tile 1 (group 1) ----
    {
        const int nk0 = 64;
        for (int i = t; i < 64 * 16; i += 512) {
            int r = i >> 4, c8 = (i & 15) * 8;
            cp_async16(ks + 64 * KH + r * KH + c8, Kg + (size_t)(nk0 + r) * 128 + c8);
        }
        for (int i = t; i < 64 * 8; i += 512) {
            int r = i >> 3, c8 = (i & 7) * 8;
            cp_async16(vsh + 64 * VH + r * VH + c8, Vg + (size_t)r * SEQ + nk0 + c8);
        }
        if (t < 2 * TQ)
            cp_async4(msb + 64 + t, Mb + (size_t)(t >> 1) * 64 + 2 + (t & 1));
        CP_COMMIT();
    }

    // wait for group 0 (leave group 1 in flight), then read Q fragments
    CP_WAIT(1);
    __syncthreads();

    unsigned a[8][4];
    #pragma unroll
    for (int kk = 0; kk < 8; ++kk) {
        a[kk][0] = *(const unsigned*)(qs + ra * KH + kk * 16 + 2 * tig);
        a[kk][1] = *(const unsigned*)(qs + rb * KH + kk * 16 + 2 * tig);
        a[kk][2] = *(const unsigned*)(qs + ra * KH + kk * 16 + 2 * tig + 8);
        a[kk][3] = *(const unsigned*)(qs + rb * KH + kk * 16 + 2 * tig + 8);
    }

    float ctx0 = 0.f, ctx1 = 0.f, ctx2 = 0.f, ctx3 = 0.f;
    float sl0 = 0.f, sl1 = 0.f;
    const int col = n0 + 2 * tig;

    for (int tile = 0; tile < NT; ++tile) {
        const int buf = tile % 3;
        const int pbuf = tile & 1;
        const __half* kb = ks  + buf * 64 * KH;
        const __half* vb = vsh + buf * 64 * VH;
        const __half* pb = psh + pbuf * TQ * VH;
        const unsigned* mb = msb + buf * 2 * TQ;
        const int k0 = tile * 64;

        if (tile > 0) {
            // ensure this tile's group is complete (tile+1's may still be in flight)
            if (tile + 1 < NT) { CP_WAIT(1); } else { CP_WAIT(0); }
            __syncthreads();
        }

        // ---- QK scores: 8 fp16 k16 mmas (result = s * log2e) ----
        float c0 = 0.f, c1 = 0.f, c2 = 0.f, c3 = 0.f;
        #pragma unroll
        for (int kk = 0; kk < 8; ++kk) {
            unsigned b0 = *(const unsigned*)(kb + (n0 + g) * KH + kk * 16 + 2 * tig);
            unsigned b1 = *(const unsigned*)(kb + (n0 + g) * KH + kk * 16 + 2 * tig + 8);
            mma_f16_k16(c0, c1, c2, c3, a[kk][0], a[kk][1], a[kk][2], a[kk][3], b0, b1);
        }

        // ---- mask (-> -100 => exp2 -> 0) + fp16x2 exp2 ----
        unsigned w0 = mb[ra * 2 + (col >> 5)];
        unsigned w1 = mb[rb * 2 + (col >> 5)];
        float m00 = ((w0 >> (col & 31)) & 1u)       ? -100.f : c0;
        float m01 = ((w0 >> ((col + 1) & 31)) & 1u) ? -100.f : c1;
        float m10 = ((w1 >> (col & 31)) & 1u)       ? -100.f : c2;
        float m11 = ((w1 >> ((col + 1) & 31)) & 1u) ? -100.f : c3;
        __half2 hp0 = h2exp2_approx(__floats2half2_rn(m00, m01));
        __half2 hp1 = h2exp2_approx(__floats2half2_rn(m10, m11));
        float2 f0 = __half22float2(hp0);
        float2 f1 = __half22float2(hp1);
        sl0 += f0.x + f0.y;
        sl1 += f1.x + f1.y;

        // ---- p fp16: scratch global + psh ----
        *(__half2*)(php + (size_t)ra * SEQ + k0 + col) = hp0;
        *(__half2*)(php + (size_t)rb * SEQ + k0 + col) = hp1;
        *(__half2*)(psh + pbuf * TQ * VH + ra * VH + col) = hp0;
        *(__half2*)(psh + pbuf * TQ * VH + rb * VH + col) = hp1;
        __syncthreads();    // S1: psh complete; buffer (tile-1)%3 fully consumed

        // ---- prefetch tile+2 into (tile+2)%3 ----
        if (tile + 2 < NT) {
            const int nb = (tile + 2) % 3;
            const int nk0 = k0 + 128;
            for (int i = t; i < 64 * 16; i += 512) {
                int r = i >> 4, c8 = (i & 15) * 8;
                cp_async16(ks + nb * 64 * KH + r * KH + c8,
                           Kg + (size_t)(nk0 + r) * 128 + c8);
            }
            for (int i = t; i < 64 * 8; i += 512) {
                int r = i >> 3, c8 = (i & 7) * 8;
                cp_async16(vsh + nb * 64 * VH + r * VH + c8,
                           Vg + (size_t)r * SEQ + nk0 + c8);
            }
            if (t < 2 * TQ)
                cp_async4(msb + nb * 2 * TQ + t,
                          Mb + (size_t)(t >> 1) * 64 + (nk0 >> 5) + (t & 1));
            CP_COMMIT();
        }

        // ---- fp16 PV: 4 k16 mmas ----
        #pragma unroll
        for (int kk = 0; kk < 4; ++kk) {
            unsigned pa0 = *(const unsigned*)(pb + ra * VH + kk * 16 + 2 * tig);
            unsigned pa1 = *(const unsigned*)(pb + rb * VH + kk * 16 + 2 * tig);
            unsigned pa2 = *(const unsigned*)(pb + ra * VH + kk * 16 + 2 * tig + 8);
            unsigned pa3 = *(const unsigned*)(pb + rb * VH + kk * 16 + 2 * tig + 8);
            unsigned vb0 = *(const unsigned*)(vb + (n0 + g) * VH + kk * 16 + 2 * tig);
            unsigned vb1 = *(const unsigned*)(vb + (n0 + g) * VH + kk * 16 + 2 * tig + 8);
            mma_f16_k16(ctx0, ctx1, ctx2, ctx3, pa0, pa1, pa2, pa3, vb0, vb1);
        }
    }

    __syncthreads();

    // ---- row-sum reduction ----
    sl0 += __shfl_xor_sync(0xffffffffu, sl0, 1);
    sl0 += __shfl_xor_sync(0xffffffffu, sl0, 2);
    sl1 += __shfl_xor_sync(0xffffffffu, sl1, 1);
    sl1 += __shfl_xor_sync(0xffffffffu, sl1, 2);
    if (tig == 0) {
        red[w * 16 + g]     = sl0;
        red[w * 16 + 8 + g] = sl1;
    }
    __syncthreads();
    if (t < TQ) {
        int qh_r = t >> 4;
        int rr   = t & 15;
        float s = 0.f;
        #pragma unroll
        for (int ww = 0; ww < 8; ++ww) s += red[(qh_r * 8 + ww) * 16 + rr];
        inv[t] = 1.f / s;
    }
    __syncthreads();

    // ---- normalized ctx write ----
    {
        float iv0 = inv[ra];
        float iv1 = inv[rb];
        size_t r0 = (size_t)b * SEQ + q0;
        *(float2*)(g_ctx + (r0 + ra) * 256 + h * 64 + col) = make_float2(ctx0 * iv0, ctx1 * iv0);
        *(float2*)(g_ctx + (r0 + rb) * 256 + h * 64 + col) = make_float2(ctx2 * iv1, ctx3 * iv1);
    }

    // ---- normalize: read fp16 scratch (L2-warm), write fp32 attn once ----
    for (int r = 0; r < TQ; ++r) {
        float iv = inv[r];
        const __half2* src = (const __half2*)(php + (size_t)r * SEQ) + t * 2;
        __half2 h0 = src[0];
        __half2 h1 = src[1];
        float2 f0 = __half22float2(h0);
        float2 f1 = __half22float2(h1);
        float4 v;
        v.x = f0.x * iv; v.y = f0.y * iv; v.z = f1.x * iv; v.w = f1.y * iv;
        *((float4*)(ao + (size_t)r * SEQ) + t) = v;
    }
}

// ---------------------------------------------------------------------------
// Kernel 3: fc + LN1 + FFN + LN2 (unchanged)
// ---------------------------------------------------------------------------
#define POST_SMEM_BYTES ((64*260 + 256*68 + 4*64*68) * 4)

__global__ void __launch_bounds__(256) post_kernel(
    const float* __restrict__ x, const float* __restrict__ fcw,
    const float* __restrict__ ln1g, const float* __restrict__ ln1b,
    const float* __restrict__ f1, const float* __restrict__ f2,
    const float* __restrict__ ln2g, const float* __restrict__ ln2b,
    float* __restrict__ res) {
    extern __shared__ float sm[];
    float* cs  = sm;                 // 64 x 260
    float* fs  = cs + 64 * 260;      // 256 x 68
    float* hs  = fs + 256 * 68;      // 64 x 68
    float* es  = hs + 64 * 68;       // 64 x 68
    float* f1s = es + 64 * 68;       // 64 x 68
    float* f2s = f1s + 64 * 68;      // 64 x 68

    const int t = threadIdx.x;
    const int row0 = blockIdx.x * 64;

    for (int i = t; i < 64 * 64; i += 256) {
        int r = i >> 6, c = (i & 63) * 4;
        *(float4*)(cs + r * 260 + c) = *(const float4*)(g_ctx + (size_t)(row0 + r) * 256 + c);
    }
    for (int i = t; i < 256 * 16; i += 256) {
        int r = i >> 4, c = (i & 15) * 4;
        *(float4*)(fs + r * 68 + c) = *(const float4*)(fcw + r * 64 + c);
    }
    for (int i = t; i < 64 * 16; i += 256) {
        int r = i >> 4, c = (i & 15) * 4;
        *(float4*)(hs + r * 68 + c)  = *(const float4*)(x + (size_t)(row0 + r) * DM + c);
        *(float4*)(f1s + r * 68 + c) = *(const float4*)(f1 + r * 64 + c);
        *(float4*)(f2s + r * 68 + c) = *(const float4*)(f2 + r * 64 + c);
    }
    __syncthreads();

    const int rg = t >> 4;
    const int cg = t & 15;

    float acc[4][4];
    #pragma unroll
    for (int i = 0; i < 4; ++i)
        #pragma unroll
        for (int j = 0; j < 4; ++j) acc[i][j] = 0.f;
    for (int k = 0; k < 256; ++k) {
        float av[4];
        #pragma unroll
        for (int i = 0; i < 4; ++i) av[i] = cs[(rg * 4 + i) * 260 + k];
        float4 bb = *(const float4*)(fs + k * 68 + cg * 4);
        float bv[4] = {bb.x, bb.y, bb.z, bb.w};
        #pragma unroll
        for (int i = 0; i < 4; ++i)
            #pragma unroll
            for (int j = 0; j < 4; ++j) acc[i][j] += av[i] * bv[j];
    }

    #pragma unroll
    for (int i = 0; i < 4; ++i) {
        float y[4];
        #pragma unroll
        for (int j = 0; j < 4; ++j) y[j] = acc[i][j] + hs[(rg * 4 + i) * 68 + cg * 4 + j];
        float s = y[0] + y[1] + y[2] + y[3];
        float q = y[0]*y[0] + y[1]*y[1] + y[2]*y[2] + y[3]*y[3];
        #pragma unroll
        for (int o = 1; o < 16; o <<= 1) {
            s += __shfl_xor_sync(0xffffffffu, s, o);
            q += __shfl_xor_sync(0xffffffffu, q, o);
        }
        float mu = s * (1.f / 64.f);
        float var = q * (1.f / 64.f) - mu * mu;
        float rs = rsqrtf(var + 1e-5f);
        #pragma unroll
        for (int j = 0; j < 4; ++j) {
            int c = cg * 4 + j;
            es[(rg * 4 + i) * 68 + c] = (y[j] - mu) * rs * ln1g[c] + ln1b[c];
        }
    }
    __syncthreads();

    float h4[4][4];
    #pragma unroll
    for (int i = 0; i < 4; ++i)
        #pragma unroll
        for (int j = 0; j < 4; ++j) h4[i][j] = 0.f;
    for (int k = 0; k < 64; ++k) {
        float av[4];
        #pragma unroll
        for (int i = 0; i < 4; ++i) av[i] = es[(rg * 4 + i) * 68 + k];
        float4 bb = *(const float4*)(f1s + k * 68 + cg * 4);
        float bv[4] = {bb.x, bb.y, bb.z, bb.w};
        #pragma unroll
        for (int i = 0; i < 4; ++i)
            #pragma unroll
            for (int j = 0; j < 4; ++j) h4[i][j] += av[i] * bv[j];
    }
    #pragma unroll
    for (int i = 0; i < 4; ++i)
        #pragma unroll
        for (int j = 0; j < 4; ++j)
            hs[(rg * 4 + i) * 68 + cg * 4 + j] = fmaxf(h4[i][j], 0.f);
    __syncthreads();

    float fa[4][4];
    #pragma unroll
    for (int i = 0; i < 4; ++i)
        #pragma unroll
        for (int j = 0; j < 4; ++j) fa[i][j] = 0.f;
    for (int k = 0; k < 64; ++k) {
        float av[4];
        #pragma unroll
        for (int i = 0; i < 4; ++i) av[i] = hs[(rg * 4 + i) * 68 + k];
        float4 bb = *(const float4*)(f2s + k * 68 + cg * 4);
        float bv[4] = {bb.x, bb.y, bb.z, bb.w};
        #pragma unroll
        for (int i = 0; i < 4; ++i)
            #pragma unroll
            for (int j = 0; j < 4; ++j) fa[i][j] += av[i] * bv[j];
    }
    #pragma unroll
    for (int i = 0; i < 4; ++i) {
        float y[4];
        #pragma unroll
        for (int j = 0; j < 4; ++j) y[j] = fa[i][j] + es[(rg * 4 + i) * 68 + cg * 4 + j];
        float s = y[0] + y[1] + y[2] + y[3];
        float q = y[0]*y[0] + y[1]*y[1] + y[2]*y[2] + y[3]*y[3];
        #pragma unroll
        for (int o = 1; o < 16; o <<= 1) {
            s += __shfl_xor_sync(0xffffffffu, s, o);
            q += __shfl_xor_sync(0xffffffffu, q, o);
        }
        float mu = s * (1.f / 64.f);
        float var = q * (1.f / 64.f) - mu * mu;
        float rs = rsqrtf(var + 1e-5f);
        float4 o4;
        o4.x = (y[0] - mu) * rs * ln2g[cg * 4 + 0] + ln2b[cg * 4 + 0];
        o4.y = (y[1] - mu) * rs * ln2g[cg * 4 + 1] + ln2b[cg * 4 + 1];
        o4.z = (y[2] - mu) * rs * ln2g[cg * 4 + 2] + ln2b[cg * 4 + 2];
        o4.w = (y[3] - mu) * rs * ln2g[cg * 4 + 3] + ln2b[cg * 4 + 3];
        *(float4*)(res + (size_t)(row0 + rg * 4 + i) * 64 + cg * 4) = o4;
    }
}

// ---------------------------------------------------------------------------
// Launch
// ---------------------------------------------------------------------------
extern "C" void kernel_launch(void* const* d_in, const int* in_sizes, int n_in,
                              void* d_out, int out_size) {
    const float* x    = (const float*)d_in[0];
    const void*  mask = d_in[1];
    const float* u    = (const float*)d_in[2];
    const float* wq   = (const float*)d_in[3];
    const float* wk   = (const float*)d_in[4];
    const float* wv   = (const float*)d_in[5];
    const float* uqw  = (const float*)d_in[6];
    const float* ukw  = (const float*)d_in[7];
    const float* uvw  = (const float*)d_in[8];
    const float* sq1  = (const float*)d_in[9];
    const float* sq2  = (const float*)d_in[10];
    const float* sk1  = (const float*)d_in[11];
    const float* sk2  = (const float*)d_in[12];
    const float* sv1  = (const float*)d_in[13];
    const float* sv2  = (const float*)d_in[14];
    const float* fcw  = (const float*)d_in[15];
    const float* ln1g = (const float*)d_in[16];
    const float* ln1b = (const float*)d_in[17];
    const float* ffn1 = (const float*)d_in[18];
    const float* ffn2 = (const float*)d_in[19];
    const float* ln2g = (const float*)d_in[20];
    const float* ln2b = (const float*)d_in[21];

    float* res  = (float*)d_out;
    float* attn = res + (size_t)NB * SEQ * DM;

    cudaFuncSetAttribute(proj_kernel,  cudaFuncAttributeMaxDynamicSharedMemorySize, PROJ_SMEM_BYTES);
    cudaFuncSetAttribute(attn2_kernel, cudaFuncAttributeMaxDynamicSharedMemorySize, ATT_SMEM_BYTES);
    cudaFuncSetAttribute(post_kernel,  cudaFuncAttributeMaxDynamicSharedMemorySize, POST_SMEM_BYTES);

    detect_mask_kernel<<<1, 32>>>((const unsigned char*)mask);
    convert_mask_kernel<<<(NB * SEQ * SEQ) / 256, 256>>>(mask);
    gates_kernel<<<NB, 32>>>(u, sq1, sq2, sk1, sk2, sv1, sv2);
    proj_kernel<<<(NB * SEQ) / 64, 256, PROJ_SMEM_BYTES>>>(x, wq, wk, wv, uqw, ukw, uvw);
    transpose_v_kernel<<<NB * NH * 32, 256>>>();
    attn2_kernel<<<NB * NH * (SEQ / TQ), 512, ATT_SMEM_BYTES>>>(attn);
    post_kernel<<<(NB * SEQ) / 64, 256, POST_SMEM_BYTES>>>(x, fcw, ln1g, ln1b, ffn1, ffn2,
                                                           ln2g, ln2b, res);
}

// round 12
// speedup vs baseline: 1.1748x; 1.0456x over previous
#include <cuda_runtime.h>
#include <cuda_fp16.h>
#include <cstdint>
#include <cstddef>

// ---------------------------------------------------------------------------
// Problem constants
// ---------------------------------------------------------------------------
#define NB   8
#define NH   4
#define SEQ  2048
#define DM   64

// attention tiling
#define TQ   32          // q rows per CTA
#define KH   136         // half stride for qs/ks rows (128 data + 8 pad)
#define VH   72          // half stride for vsh / psh rows
#define NT   (SEQ / 64)  // 32 k-tiles

#define LOG2E 1.4426950408889634f

// ---------------------------------------------------------------------------
// Static device scratch
// ---------------------------------------------------------------------------
__device__ float    g_gates[3 * NB];
__device__ int      g_mask_mode;
__device__ __half   g_Qeh[(size_t)NB * NH * SEQ * 128];    // fp16, scaled 0.125*log2e
__device__ __half   g_Keh[(size_t)NB * NH * SEQ * 128];
__device__ float    g_Ve[(size_t)NB * NH * SEQ * 64];
__device__ __half   g_Veh[(size_t)NB * NH * 64 * SEQ];     // transposed [v][k] fp16
__device__ float    g_ctx[(size_t)NB * SEQ * 256];
__device__ unsigned g_maskb[(size_t)NB * SEQ * 64];
__device__ __half   g_ph[(size_t)NB * NH * SEQ * SEQ];     // fp16 p scratch

// ---------------------------------------------------------------------------
// Helpers
// ---------------------------------------------------------------------------
__device__ __forceinline__ void mma_f16_k16(float& c0, float& c1, float& c2, float& c3,
                                            unsigned a0, unsigned a1, unsigned a2, unsigned a3,
                                            unsigned b0, unsigned b1) {
    asm volatile(
        "mma.sync.aligned.m16n8k16.row.col.f32.f16.f16.f32 "
        "{%0,%1,%2,%3},{%4,%5,%6,%7},{%8,%9},{%0,%1,%2,%3};"
        : "+f"(c0), "+f"(c1), "+f"(c2), "+f"(c3)
        : "r"(a0), "r"(a1), "r"(a2), "r"(a3), "r"(b0), "r"(b1));
}

__device__ __forceinline__ void ldsm_x2(unsigned& r0, unsigned& r1, unsigned addr) {
    asm volatile("ldmatrix.sync.aligned.m8n8.x2.shared.b16 {%0,%1}, [%2];"
                 : "=r"(r0), "=r"(r1) : "r"(addr));
}
__device__ __forceinline__ void ldsm_x4(unsigned& r0, unsigned& r1, unsigned& r2, unsigned& r3,
                                        unsigned addr) {
    asm volatile("ldmatrix.sync.aligned.m8n8.x4.shared.b16 {%0,%1,%2,%3}, [%4];"
                 : "=r"(r0), "=r"(r1), "=r"(r2), "=r"(r3) : "r"(addr));
}

__device__ __forceinline__ __half2 h2exp2_approx(__half2 x) {
    __half2 r;
    asm("ex2.approx.f16x2 %0, %1;" : "=r"(*(unsigned*)&r) : "r"(*(unsigned*)&x));
    return r;
}

__device__ __forceinline__ void cp_async16(void* smem, const void* gmem) {
    unsigned sa = (unsigned)__cvta_generic_to_shared(smem);
    asm volatile("cp.async.cg.shared.global [%0], [%1], 16;\n" :: "r"(sa), "l"(gmem));
}
__device__ __forceinline__ void cp_async4(void* smem, const void* gmem) {
    unsigned sa = (unsigned)__cvta_generic_to_shared(smem);
    asm volatile("cp.async.ca.shared.global [%0], [%1], 4;\n" :: "r"(sa), "l"(gmem));
}
#define CP_COMMIT() asm volatile("cp.async.commit_group;\n")
#define CP_WAIT(n)  asm volatile("cp.async.wait_group %0;\n" :: "n"(n))

// ---------------------------------------------------------------------------
// Kernel D: detect mask encoding (int32 vs byte)
// ---------------------------------------------------------------------------
__global__ void detect_mask_kernel(const unsigned char* __restrict__ m) {
    int found = 0;
    for (int i = threadIdx.x; i < 1024; i += 32)
        if (m[i * 4 + 1] | m[i * 4 + 2] | m[i * 4 + 3]) found = 1;
    for (int o = 16; o; o >>= 1)
        found |= __shfl_xor_sync(0xffffffffu, found, o);
    if (threadIdx.x == 0) g_mask_mode = found ? 0 : 1;
}

// ---------------------------------------------------------------------------
// Kernel M: bit-pack the mask (ballot-based, coalesced)
// ---------------------------------------------------------------------------
__global__ void __launch_bounds__(256) convert_mask_kernel(const void* __restrict__ mask) {
    unsigned gid = blockIdx.x * 256 + threadIdx.x;
    unsigned nz;
    if (g_mask_mode) nz = (((const int*)mask)[gid] != 0) ? 1u : 0u;
    else             nz = (((const unsigned char*)mask)[gid] != 0) ? 1u : 0u;
    unsigned bits = __ballot_sync(0xffffffffu, nz);
    if ((threadIdx.x & 31) == 0) g_maskb[gid >> 5] = bits;
}

// ---------------------------------------------------------------------------
// Kernel 0: scalar gates
// ---------------------------------------------------------------------------
__global__ void gates_kernel(const float* __restrict__ u,
                             const float* __restrict__ sq1, const float* __restrict__ sq2,
                             const float* __restrict__ sk1, const float* __restrict__ sk2,
                             const float* __restrict__ sv1, const float* __restrict__ sv2) {
    const int b = blockIdx.x;
    const int lane = threadIdx.x;
    float hq = 0.f, hk = 0.f, hv = 0.f;
    for (int d = 0; d < DM; ++d) {
        float uv = u[b * DM + d];
        hq += uv * sq1[d * 32 + lane];
        hk += uv * sk1[d * 32 + lane];
        hv += uv * sv1[d * 32 + lane];
    }
    hq = fmaxf(hq, 0.f) * sq2[lane];
    hk = fmaxf(hk, 0.f) * sk2[lane];
    hv = fmaxf(hv, 0.f) * sv2[lane];
    for (int off = 16; off; off >>= 1) {
        hq += __shfl_xor_sync(0xffffffffu, hq, off);
        hk += __shfl_xor_sync(0xffffffffu, hk, off);
        hv += __shfl_xor_sync(0xffffffffu, hv, off);
    }
    if (lane == 0) {
        g_gates[b]      = hq;
        g_gates[8 + b]  = hk;
        g_gates[16 + b] = hv;
    }
}

// ---------------------------------------------------------------------------
// Kernel 1: projections, 2 CTAs/SM (measured 67 us). Q carries 0.125*log2e.
// ---------------------------------------------------------------------------
#define PROJ_SMEM_BYTES ((64*68 + 3*64*68 + 64*132) * 4)

__global__ void __launch_bounds__(256, 2) proj_kernel(
    const float* __restrict__ x,
    const float* __restrict__ wq, const float* __restrict__ wk, const float* __restrict__ wv,
    const float* __restrict__ uqw, const float* __restrict__ ukw, const float* __restrict__ uvw) {
    extern __shared__ float sm[];
    float* xs   = sm;                 // 64 x 68
    float* uo   = xs + 64 * 68;       // 3 x (64 x 68)
    float* wbig = uo + 3 * 64 * 68;   // 64 x 132

    const int t = threadIdx.x;
    const int row0 = blockIdx.x * 64;
    const int b    = row0 >> 11;
    const int lr0  = row0 & (SEQ - 1);

    for (int i = t; i < 64 * 16; i += 256) {
        int r = i >> 4, c = (i & 15) * 4;
        *(float4*)(xs + r * 68 + c)            = *(const float4*)(x + (size_t)(row0 + r) * DM + c);
        *(float4*)(uo + 0 * 4352 + r * 68 + c) = *(const float4*)(uqw + r * 64 + c);
        *(float4*)(uo + 1 * 4352 + r * 68 + c) = *(const float4*)(ukw + r * 64 + c);
        *(float4*)(uo + 2 * 4352 + r * 68 + c) = *(const float4*)(uvw + r * 64 + c);
    }
    __syncthreads();

    const int rg = t >> 5;
    const int cg = t & 31;

    float uacc[8][8];
    if (cg < 24) {
        const int mat = cg >> 3;
        const int c0 = (cg & 7) * 8;
        const float* w = uo + mat * 4352;
        #pragma unroll
        for (int i = 0; i < 8; ++i)
            #pragma unroll
            for (int j = 0; j < 8; ++j) uacc[i][j] = 0.f;
        for (int k = 0; k < 64; ++k) {
            float av[8];
            #pragma unroll
            for (int i = 0; i < 8; ++i) av[i] = xs[(rg * 8 + i) * 68 + k];
            float4 b0 = *(const float4*)(w + k * 68 + c0);
            float4 b1 = *(const float4*)(w + k * 68 + c0 + 4);
            float bv[8] = {b0.x, b0.y, b0.z, b0.w, b1.x, b1.y, b1.z, b1.w};
            #pragma unroll
            for (int i = 0; i < 8; ++i)
                #pragma unroll
                for (int j = 0; j < 8; ++j) uacc[i][j] += av[i] * bv[j];
        }
    }
    __syncthreads();

    if (cg < 24) {
        const int mat = cg >> 3;
        const int c0 = (cg & 7) * 8;
        float* dst = uo + mat * 4352;
        #pragma unroll
        for (int i = 0; i < 8; ++i)
            #pragma unroll
            for (int j = 0; j < 8; ++j)
                dst[(rg * 8 + i) * 68 + c0 + j] = uacc[i][j];
    }
    __syncthreads();

    const float gq = g_gates[b] * 0.125f * LOG2E;
    const float gk = g_gates[8 + b];
    const float gv = g_gates[16 + b];

    for (int i = t; i < 64 * 64; i += 256) {
        int r = i >> 6, j = i & 63;
        __half vq = __float2half(uo[r * 68 + j] * gq);
        __half vk = __float2half(uo[4352 + r * 68 + j] * gk);
        size_t l = lr0 + r;
        #pragma unroll
        for (int h = 0; h < 4; ++h) {
            size_t base = (((size_t)b * 4 + h) * SEQ + l) * 128 + 64 + j;
            g_Qeh[base] = vq;
            g_Keh[base] = vk;
        }
    }

    for (int m = 0; m < 3; ++m) {
        const float* w = (m == 0) ? wq : (m == 1) ? wk : wv;
        for (int h2 = 0; h2 < 2; ++h2) {
            __syncthreads();
            for (int i = t; i < 64 * 32; i += 256) {
                int r = i >> 5, c = (i & 31) * 4;
                *(float4*)(wbig + r * 132 + c) = *(const float4*)(w + r * 256 + h2 * 128 + c);
            }
            __syncthreads();

            float acc[8][4];
            #pragma unroll
            for (int i = 0; i < 8; ++i)
                #pragma unroll
                for (int j = 0; j < 4; ++j) acc[i][j] = 0.f;
            for (int k = 0; k < 64; ++k) {
                float av[8];
                #pragma unroll
                for (int i = 0; i < 8; ++i) av[i] = xs[(rg * 8 + i) * 68 + k];
                float4 bb = *(const float4*)(wbig + k * 132 + cg * 4);
                float bv[4] = {bb.x, bb.y, bb.z, bb.w};
                #pragma unroll
                for (int i = 0; i < 8; ++i)
                    #pragma unroll
                    for (int j = 0; j < 4; ++j) acc[i][j] += av[i] * bv[j];
            }

            const int gc = h2 * 128 + cg * 4;
            const int h  = gc >> 6;
            const int j0 = gc & 63;
            if (m == 2) {
                #pragma unroll
                for (int i = 0; i < 8; ++i) {
                    size_t l = lr0 + rg * 8 + i;
                    size_t base = (((size_t)b * 4 + h) * SEQ + l) * 64 + j0;
                    #pragma unroll
                    for (int j = 0; j < 4; ++j)
                        g_Ve[base + j] = acc[i][j] + uo[2 * 4352 + (rg * 8 + i) * 68 + j0 + j] * gv;
                }
            } else {
                __half* tgt = (m == 0) ? g_Qeh : g_Keh;
                float s = (m == 0) ? (0.125f * LOG2E) : 1.0f;
                #pragma unroll
                for (int i = 0; i < 8; ++i) {
                    size_t l = lr0 + rg * 8 + i;
                    size_t base = (((size_t)b * 4 + h) * SEQ + l) * 128 + j0;
                    *(__half2*)(tgt + base)     = __floats2half2_rn(acc[i][0] * s, acc[i][1] * s);
                    *(__half2*)(tgt + base + 2) = __floats2half2_rn(acc[i][2] * s, acc[i][3] * s);
                }
            }
        }
    }
}

// ---------------------------------------------------------------------------
// Kernel 1b: transpose Ve -> g_Veh [bh][v][k] fp16
// ---------------------------------------------------------------------------
__global__ void __launch_bounds__(256) transpose_v_kernel() {
    __shared__ float ts[64][65];
    const int bh = blockIdx.x >> 5;
    const int kt = blockIdx.x & 31;
    const int t  = threadIdx.x;
    const float* src = g_Ve + ((size_t)bh * SEQ + kt * 64) * 64;
    for (int i = t; i < 64 * 16; i += 256) {
        int r = i >> 4, c = (i & 15) * 4;
        float4 v = *(const float4*)(src + (size_t)r * 64 + c);
        ts[r][c] = v.x; ts[r][c + 1] = v.y; ts[r][c + 2] = v.z; ts[r][c + 3] = v.w;
    }
    __syncthreads();
    __half* dst = g_Veh + (size_t)bh * 64 * SEQ + kt * 64;
    for (int i = t; i < 64 * 16; i += 256) {
        int v = i >> 4, k = (i & 15) * 4;
        __half2 h0 = __floats2half2_rn(ts[k][v],     ts[k + 1][v]);
        __half2 h1 = __floats2half2_rn(ts[k + 2][v], ts[k + 3][v]);
        *(__half2*)(dst + (size_t)v * SEQ + k)     = h0;
        *(__half2*)(dst + (size_t)v * SEQ + k + 2) = h1;
    }
}

// ---------------------------------------------------------------------------
// Kernel 2 (v9): attention. TQ=32, 512 threads, 3-deep cp.async pipeline,
// fp16x2 exp2, LDSM fragment loads, PV k-split (16 v-cols/warp over half-k).
// PV warp map: ng = w&3 (16 v), kh = (w>>2)&1 (k half), qh = w>>3 (16 q).
// Partial ctx combined once per CTA via scratch in the (dead) K region.
// ---------------------------------------------------------------------------
#define ATT_SMEM_BYTES ((TQ*KH + 3*64*KH + 3*64*VH + 2*TQ*VH) * 2 + 256*4 + 32*4 + 192*4)

__global__ void __launch_bounds__(512) attn2_kernel(float* __restrict__ attn_out) {
    extern __shared__ __half smh[];
    __half* qs  = smh;                       // 32 x 136
    __half* ks  = qs + TQ * KH;              // 3 x 64 x 136
    __half* vsh = ks + 3 * 64 * KH;          // 3 x 64 x 72
    __half* psh = vsh + 3 * 64 * VH;         // 2 x 32 x 72
    float*  red = (float*)(psh + 2 * TQ * VH);   // 16 x 16
    float*  inv = red + 256;                     // 32
    unsigned* msb = (unsigned*)(inv + 32);       // 3 x 64

    const unsigned smbase = (unsigned)__cvta_generic_to_shared(smh);
    const unsigned ks_a  = smbase + (unsigned)(TQ * KH) * 2;
    const unsigned vs_a  = ks_a + (unsigned)(3 * 64 * KH) * 2;
    const unsigned ps_a  = vs_a + (unsigned)(3 * 64 * VH) * 2;

    const int t    = threadIdx.x;
    const int w    = t >> 5;
    const int lane = t & 31;
    const int g    = lane >> 2;
    const int tig  = lane & 3;
    const int qh   = w >> 3;               // 0/1: 16-row half (QK and PV)
    const int n0   = (w & 7) * 8;          // QK: k-col group within tile
    const int ng   = w & 3;                // PV: v-group of 16
    const int kh   = (w >> 2) & 1;         // PV: k half of tile
    const int vn0  = ng * 16;
    const int ra   = qh * 16 + g;
    const int rb   = ra + 8;

    // LDSM per-lane byte offsets
    const unsigned koff  = (unsigned)(((n0 + (lane & 7)) * KH + ((lane >> 3) & 1) * 8) * 2);
    const unsigned poff  = (unsigned)((qh * 16 + (lane & 15)) * VH * 2 + ((lane >> 4) & 1) * 16);
    const unsigned voff0 = (unsigned)(((vn0 + (lane & 7)) * VH + ((lane >> 3) & 1) * 8) * 2);
    const unsigned voff1 = voff0 + (unsigned)(8 * VH * 2);

    const int bh = blockIdx.x >> 6;
    const int qt = blockIdx.x & 63;
    const int b  = bh >> 2;
    const int h  = bh & 3;
    const int q0 = qt * TQ;

    const __half* Qg = g_Qeh + ((size_t)bh * SEQ + q0) * 128;
    const __half* Kg = g_Keh + (size_t)bh * SEQ * 128;
    const __half* Vg = g_Veh + (size_t)bh * 64 * SEQ;
    const unsigned* Mb = g_maskb + ((size_t)b * SEQ + q0) * 64;
    __half* php = g_ph + ((size_t)bh * SEQ + q0) * SEQ;
    float* ao = attn_out + ((size_t)bh * SEQ + q0) * SEQ;

    // ---- stage Q + tile 0 (group 0) ----
    for (int i = t; i < TQ * 16; i += 512) {
        int r = i >> 4, c8 = (i & 15) * 8;
        cp_async16(qs + r * KH + c8, Qg + (size_t)r * 128 + c8);
    }
    for (int i = t; i < 64 * 16; i += 512) {
        int r = i >> 4, c8 = (i & 15) * 8;
        cp_async16(ks + r * KH + c8, Kg + (size_t)r * 128 + c8);
    }
    for (int i = t; i < 64 * 8; i += 512) {
        int r = i >> 3, c8 = (i & 7) * 8;
        cp_async16(vsh + r * VH + c8, Vg + (size_t)r * SEQ + c8);
    }
    if (t < 2 * TQ)
        cp_async4(msb + t, Mb + (size_t)(t >> 1) * 64 + (t & 1));
    CP_COMMIT();

    // ---- tile 1 (group 1) ----
    {
        const int nk0 = 64;
        for (int i = t; i < 64 * 16; i += 512) {
            int r = i >> 4, c8 = (i & 15) * 8;
            cp_async16(ks + 64 * KH + r * KH + c8, Kg + (size_t)(nk0 + r) * 128 + c8);
        }
        for (int i = t; i < 64 * 8; i += 512) {
            int r = i >> 3, c8 = (i & 7) * 8;
            cp_async16(vsh + 64 * VH + r * VH + c8, Vg + (size_t)r * SEQ + nk0 + c8);
        }
        if (t < 2 * TQ)
            cp_async4(msb + 64 + t, Mb + (size_t)(t >> 1) * 64 + 2 + (t & 1));
        CP_COMMIT();
    }

    CP_WAIT(1);
    __syncthreads();

    // ---- hoist A (Q) fragments ----
    unsigned a[8][4];
    #pragma unroll
    for (int kk = 0; kk < 8; ++kk) {
        a[kk][0] = *(const unsigned*)(qs + ra * KH + kk * 16 + 2 * tig);
        a[kk][1] = *(const unsigned*)(qs + rb * KH + kk * 16 + 2 * tig);
        a[kk][2] = *(const unsigned*)(qs + ra * KH + kk * 16 + 2 * tig + 8);
        a[kk][3] = *(const unsigned*)(qs + rb * KH + kk * 16 + 2 * tig + 8);
    }

    float cx[2][4];
    #pragma unroll
    for (int j = 0; j < 2; ++j)
        #pragma unroll
        for (int i = 0; i < 4; ++i) cx[j][i] = 0.f;
    float sl0 = 0.f, sl1 = 0.f;
    const int col = n0 + 2 * tig;

    for (int tile = 0; tile < NT; ++tile) {
        const int buf = tile % 3;
        const int pbuf = tile & 1;
        const unsigned kbuf_a = ks_a + (unsigned)(buf * 64 * KH) * 2;
        const unsigned vbuf_a = vs_a + (unsigned)(buf * 64 * VH) * 2;
        const unsigned pbuf_a = ps_a + (unsigned)(pbuf * TQ * VH) * 2;
        const unsigned* mb = msb + buf * 2 * TQ;
        const int k0 = tile * 64;

        if (tile > 0) {
            if (tile + 1 < NT) { CP_WAIT(1); } else { CP_WAIT(0); }
            __syncthreads();
        }

        // ---- QK scores: 8 LDSM.x2 + 8 mmas ----
        float c0 = 0.f, c1 = 0.f, c2 = 0.f, c3 = 0.f;
        #pragma unroll
        for (int kk = 0; kk < 8; ++kk) {
            unsigned b0, b1;
            ldsm_x2(b0, b1, kbuf_a + koff + kk * 32);
            mma_f16_k16(c0, c1, c2, c3, a[kk][0], a[kk][1], a[kk][2], a[kk][3], b0, b1);
        }

        // ---- mask + fp16x2 exp2 ----
        unsigned w0 = mb[ra * 2 + (col >> 5)];
        unsigned w1 = mb[rb * 2 + (col >> 5)];
        float m00 = ((w0 >> (col & 31)) & 1u)       ? -100.f : c0;
        float m01 = ((w0 >> ((col + 1) & 31)) & 1u) ? -100.f : c1;
        float m10 = ((w1 >> (col & 31)) & 1u)       ? -100.f : c2;
        float m11 = ((w1 >> ((col + 1) & 31)) & 1u) ? -100.f : c3;
        __half2 hp0 = h2exp2_approx(__floats2half2_rn(m00, m01));
        __half2 hp1 = h2exp2_approx(__floats2half2_rn(m10, m11));
        float2 f0 = __half22float2(hp0);
        float2 f1 = __half22float2(hp1);
        sl0 += f0.x + f0.y;
        sl1 += f1.x + f1.y;

        // ---- p fp16: scratch global + psh ----
        *(__half2*)(php + (size_t)ra * SEQ + k0 + col) = hp0;
        *(__half2*)(php + (size_t)rb * SEQ + k0 + col) = hp1;
        *(__half2*)(psh + pbuf * TQ * VH + ra * VH + col) = hp0;
        *(__half2*)(psh + pbuf * TQ * VH + rb * VH + col) = hp1;
        __syncthreads();    // S1: psh complete

        // ---- prefetch tile+2 ----
        if (tile + 2 < NT) {
            const int nb = (tile + 2) % 3;
            const int nk0 = k0 + 128;
            for (int i = t; i < 64 * 16; i += 512) {
                int r = i >> 4, c8 = (i & 15) * 8;
                cp_async16(ks + nb * 64 * KH + r * KH + c8,
                           Kg + (size_t)(nk0 + r) * 128 + c8);
            }
            for (int i = t; i < 64 * 8; i += 512) {
                int r = i >> 3, c8 = (i & 7) * 8;
                cp_async16(vsh + nb * 64 * VH + r * VH + c8,
                           Vg + (size_t)r * SEQ + nk0 + c8);
            }
            if (t < 2 * TQ)
                cp_async4(msb + nb * 2 * TQ + t,
                          Mb + (size_t)(t >> 1) * 64 + (nk0 >> 5) + (t & 1));
            CP_COMMIT();
        }

        // ---- fp16 PV k-split: 2 chunks x (1 LDSM.x4 p + 2 LDSM.x2 V + 2 mma) ----
        #pragma unroll
        for (int c = 0; c < 2; ++c) {
            const int kk = kh * 2 + c;
            unsigned p0, p1, p2, p3, v0, v1;
            ldsm_x4(p0, p1, p2, p3, pbuf_a + poff + kk * 32);
            ldsm_x2(v0, v1, vbuf_a + voff0 + kk * 32);
            mma_f16_k16(cx[0][0], cx[0][1], cx[0][2], cx[0][3], p0, p1, p2, p3, v0, v1);
            ldsm_x2(v0, v1, vbuf_a + voff1 + kk * 32);
            mma_f16_k16(cx[1][0], cx[1][1], cx[1][2], cx[1][3], p0, p1, p2, p3, v0, v1);
        }
    }

    __syncthreads();

    // ---- row-sum reduction ----
    sl0 += __shfl_xor_sync(0xffffffffu, sl0, 1);
    sl0 += __shfl_xor_sync(0xffffffffu, sl0, 2);
    sl1 += __shfl_xor_sync(0xffffffffu, sl1, 1);
    sl1 += __shfl_xor_sync(0xffffffffu, sl1, 2);
    if (tig == 0) {
        red[w * 16 + g]     = sl0;
        red[w * 16 + 8 + g] = sl1;
    }
    __syncthreads();
    if (t < TQ) {
        int qh_r = t >> 4;
        int rr   = t & 15;
        float s = 0.f;
        #pragma unroll
        for (int ww = 0; ww < 8; ++ww) s += red[(qh_r * 8 + ww) * 16 + rr];
        inv[t] = 1.f / s;
    }
    __syncthreads();

    // ---- ctx combine across k-halves (scratch in dead K region) ----
    float* cscr = (float*)ks;    // 32 x 64 floats = 8 KB
    if (kh == 1) {
        #pragma unroll
        for (int j = 0; j < 2; ++j) {
            int cc = vn0 + j * 8 + 2 * tig;
            *(float2*)(cscr + ra * 64 + cc) = make_float2(cx[j][0], cx[j][1]);
            *(float2*)(cscr + rb * 64 + cc) = make_float2(cx[j][2], cx[j][3]);
        }
    }
    __syncthreads();
    if (kh == 0) {
        float iv0 = inv[ra];
        float iv1 = inv[rb];
        size_t r0g = (size_t)b * SEQ + q0;
        #pragma unroll
        for (int j = 0; j < 2; ++j) {
            int cc = vn0 + j * 8 + 2 * tig;
            float2 o0 = *(float2*)(cscr + ra * 64 + cc);
            float2 o1 = *(float2*)(cscr + rb * 64 + cc);
            *(float2*)(g_ctx + (r0g + ra) * 256 + h * 64 + cc) =
                make_float2((cx[j][0] + o0.x) * iv0, (cx[j][1] + o0.y) * iv0);
            *(float2*)(g_ctx + (r0g + rb) * 256 + h * 64 + cc) =
                make_float2((cx[j][2] + o1.x) * iv1, (cx[j][3] + o1.y) * iv1);
        }
    }

    // ---- normalize: read fp16 scratch (L2-warm), write fp32 attn once ----
    for (int r = 0; r < TQ; ++r) {
        float iv = inv[r];
        const __half2* src = (const __half2*)(php + (size_t)r * SEQ) + t * 2;
        __half2 h0 = src[0];
        __half2 h1 = src[1];
        float2 f0 = __half22float2(h0);
        float2 f1 = __half22float2(h1);
        float4 v;
        v.x = f0.x * iv; v.y = f0.y * iv; v.z = f1.x * iv; v.w = f1.y * iv;
        *((float4*)(ao + (size_t)r * SEQ) + t) = v;
    }
}

// ---------------------------------------------------------------------------
// Kernel 3: fc + LN1 + FFN + LN2 (unchanged)
// ---------------------------------------------------------------------------
#define POST_SMEM_BYTES ((64*260 + 256*68 + 4*64*68) * 4)

__global__ void __launch_bounds__(256) post_kernel(
    const float* __restrict__ x, const float* __restrict__ fcw,
    const float* __restrict__ ln1g, const float* __restrict__ ln1b,
    const float* __restrict__ f1, const float* __restrict__ f2,
    const float* __restrict__ ln2g, const float* __restrict__ ln2b,
    float* __restrict__ res) {
    extern __shared__ float sm[];
    float* cs  = sm;                 // 64 x 260
    float* fs  = cs + 64 * 260;      // 256 x 68
    float* hs  = fs + 256 * 68;      // 64 x 68
    float* es  = hs + 64 * 68;       // 64 x 68
    float* f1s = es + 64 * 68;       // 64 x 68
    float* f2s = f1s + 64 * 68;      // 64 x 68

    const int t = threadIdx.x;
    const int row0 = blockIdx.x * 64;

    for (int i = t; i < 64 * 64; i += 256) {
        int r = i >> 6, c = (i & 63) * 4;
        *(float4*)(cs + r * 260 + c) = *(const float4*)(g_ctx + (size_t)(row0 + r) * 256 + c);
    }
    for (int i = t; i < 256 * 16; i += 256) {
        int r = i >> 4, c = (i & 15) * 4;
        *(float4*)(fs + r * 68 + c) = *(const float4*)(fcw + r * 64 + c);
    }
    for (int i = t; i < 64 * 16; i += 256) {
        int r = i >> 4, c = (i & 15) * 4;
        *(float4*)(hs + r * 68 + c)  = *(const float4*)(x + (size_t)(row0 + r) * DM + c);
        *(float4*)(f1s + r * 68 + c) = *(const float4*)(f1 + r * 64 + c);
        *(float4*)(f2s + r * 68 + c) = *(const float4*)(f2 + r * 64 + c);
    }
    __syncthreads();

    const int rg = t >> 4;
    const int cg = t & 15;

    float acc[4][4];
    #pragma unroll
    for (int i = 0; i < 4; ++i)
        #pragma unroll
        for (int j = 0; j < 4; ++j) acc[i][j] = 0.f;
    for (int k = 0; k < 256; ++k) {
        float av[4];
        #pragma unroll
        for (int i = 0; i < 4; ++i) av[i] = cs[(rg * 4 + i) * 260 + k];
        float4 bb = *(const float4*)(fs + k * 68 + cg * 4);
        float bv[4] = {bb.x, bb.y, bb.z, bb.w};
        #pragma unroll
        for (int i = 0; i < 4; ++i)
            #pragma unroll
            for (int j = 0; j < 4; ++j) acc[i][j] += av[i] * bv[j];
    }

    #pragma unroll
    for (int i = 0; i < 4; ++i) {
        float y[4];
        #pragma unroll
        for (int j = 0; j < 4; ++j) y[j] = acc[i][j] + hs[(rg * 4 + i) * 68 + cg * 4 + j];
        float s = y[0] + y[1] + y[2] + y[3];
        float q = y[0]*y[0] + y[1]*y[1] + y[2]*y[2] + y[3]*y[3];
        #pragma unroll
        for (int o = 1; o < 16; o <<= 1) {
            s += __shfl_xor_sync(0xffffffffu, s, o);
            q += __shfl_xor_sync(0xffffffffu, q, o);
        }
        float mu = s * (1.f / 64.f);
        float var = q * (1.f / 64.f) - mu * mu;
        float rs = rsqrtf(var + 1e-5f);
        #pragma unroll
        for (int j = 0; j < 4; ++j) {
            int c = cg * 4 + j;
            es[(rg * 4 + i) * 68 + c] = (y[j] - mu) * rs * ln1g[c] + ln1b[c];
        }
    }
    __syncthreads();

    float h4[4][4];
    #pragma unroll
    for (int i = 0; i < 4; ++i)
        #pragma unroll
        for (int j = 0; j < 4; ++j) h4[i][j] = 0.f;
    for (int k = 0; k < 64; ++k) {
        float av[4];
        #pragma unroll
        for (int i = 0; i < 4; ++i) av[i] = es[(rg * 4 + i) * 68 + k];
        float4 bb = *(const float4*)(f1s + k * 68 + cg * 4);
        float bv[4] = {bb.x, bb.y, bb.z, bb.w};
        #pragma unroll
        for (int i = 0; i < 4; ++i)
            #pragma unroll
            for (int j = 0; j < 4; ++j) h4[i][j] += av[i] * bv[j];
    }
    #pragma unroll
    for (int i = 0; i < 4; ++i)
        #pragma unroll
        for (int j = 0; j < 4; ++j)
            hs[(rg * 4 + i) * 68 + cg * 4 + j] = fmaxf(h4[i][j], 0.f);
    __syncthreads();

    float fa[4][4];
    #pragma unroll
    for (int i = 0; i < 4; ++i)
        #pragma unroll
        for (int j = 0; j < 4; ++j) fa[i][j] = 0.f;
    for (int k = 0; k < 64; ++k) {
        float av[4];
        #pragma unroll
        for (int i = 0; i < 4; ++i) av[i] = hs[(rg * 4 + i) * 68 + k];
        float4 bb = *(const float4*)(f2s + k * 68 + cg * 4);
        float bv[4] = {bb.x, bb.y, bb.z, bb.w};
        #pragma unroll
        for (int i = 0; i < 4; ++i)
            #pragma unroll
            for (int j = 0; j < 4; ++j) fa[i][j] += av[i] * bv[j];
    }
    #pragma unroll
    for (int i = 0; i < 4; ++i) {
        float y[4];
        #pragma unroll
        for (int j = 0; j < 4; ++j) y[j] = fa[i][j] + es[(rg * 4 + i) * 68 + cg * 4 + j];
        float s = y[0] + y[1] + y[2] + y[3];
        float q = y[0]*y[0] + y[1]*y[1] + y[2]*y[2] + y[3]*y[3];
        #pragma unroll
        for (int o = 1; o < 16; o <<= 1) {
            s += __shfl_xor_sync(0xffffffffu, s, o);
            q += __shfl_xor_sync(0xffffffffu, q, o);
        }
        float mu = s * (1.f / 64.f);
        float var = q * (1.f / 64.f) - mu * mu;
        float rs = rsqrtf(var + 1e-5f);
        float4 o4;
        o4.x = (y[0] - mu) * rs * ln2g[cg * 4 + 0] + ln2b[cg * 4 + 0];
        o4.y = (y[1] - mu) * rs * ln2g[cg * 4 + 1] + ln2b[cg * 4 + 1];
        o4.z = (y[2] - mu) * rs * ln2g[cg * 4 + 2] + ln2b[cg * 4 + 2];
        o4.w = (y[3] - mu) * rs * ln2g[cg * 4 + 3] + ln2b[cg * 4 + 3];
        *(float4*)(res + (size_t)(row0 + rg * 4 + i) * 64 + cg * 4) = o4;
    }
}

// ---------------------------------------------------------------------------
// Launch
// ---------------------------------------------------------------------------
extern "C" void kernel_launch(void* const* d_in, const int* in_sizes, int n_in,
                              void* d_out, int out_size) {
    const float* x    = (const float*)d_in[0];
    const void*  mask = d_in[1];
    const float* u    = (const float*)d_in[2];
    const float* wq   = (const float*)d_in[3];
    const float* wk   = (const float*)d_in[4];
    const float* wv   = (const float*)d_in[5];
    const float* uqw  = (const float*)d_in[6];
    const float* ukw  = (const float*)d_in[7];
    const float* uvw  = (const float*)d_in[8];
    const float* sq1  = (const float*)d_in[9];
    const float* sq2  = (const float*)d_in[10];
    const float* sk1  = (const float*)d_in[11];
    const float* sk2  = (const float*)d_in[12];
    const float* sv1  = (const float*)d_in[13];
    const float* sv2  = (const float*)d_in[14];
    const float* fcw  = (const float*)d_in[15];
    const float* ln1g = (const float*)d_in[16];
    const float* ln1b = (const float*)d_in[17];
    const float* ffn1 = (const float*)d_in[18];
    const float* ffn2 = (const float*)d_in[19];
    const float* ln2g = (const float*)d_in[20];
    const float* ln2b = (const float*)d_in[21];

    float* res  = (float*)d_out;
    float* attn = res + (size_t)NB * SEQ * DM;

    cudaFuncSetAttribute(proj_kernel,  cudaFuncAttributeMaxDynamicSharedMemorySize, PROJ_SMEM_BYTES);
    cudaFuncSetAttribute(attn2_kernel, cudaFuncAttributeMaxDynamicSharedMemorySize, ATT_SMEM_BYTES);
    cudaFuncSetAttribute(post_kernel,  cudaFuncAttributeMaxDynamicSharedMemorySize, POST_SMEM_BYTES);

    detect_mask_kernel<<<1, 32>>>((const unsigned char*)mask);
    convert_mask_kernel<<<(NB * SEQ * SEQ) / 256, 256>>>(mask);
    gates_kernel<<<NB, 32>>>(u, sq1, sq2, sk1, sk2, sv1, sv2);
    proj_kernel<<<(NB * SEQ) / 64, 256, PROJ_SMEM_BYTES>>>(x, wq, wk, wv, uqw, ukw, uvw);
    transpose_v_kernel<<<NB * NH * 32, 256>>>();
    attn2_kernel<<<NB * NH * (SEQ / TQ), 512, ATT_SMEM_BYTES>>>(attn);
    post_kernel<<<(NB * SEQ) / 64, 256, POST_SMEM_BYTES>>>(x, fcw, ln1g, ln1b, ffn1, ffn2,
                                                           ln2g, ln2b, res);
}

// round 14
// speedup vs baseline: 1.2529x; 1.0665x over previous
#include <cuda_runtime.h>
#include <cuda_fp16.h>
#include <cstdint>
#include <cstddef>

// ---------------------------------------------------------------------------
// Problem constants
// ---------------------------------------------------------------------------
#define NB   8
#define NH   4
#define SEQ  2048
#define DM   64

#define TQ   32
#define KH   136
#define VH   72
#define NT   (SEQ / 64)

#define LOG2E 1.4426950408889634f

// ---------------------------------------------------------------------------
// Static device scratch
// ---------------------------------------------------------------------------
__device__ float    g_gates[3 * NB];
__device__ int      g_mask_mode;
__device__ __half   g_Qeh[(size_t)NB * NH * SEQ * 128];    // fp16, scaled 0.125*log2e
__device__ __half   g_Keh[(size_t)NB * NH * SEQ * 128];
__device__ __half   g_Veh[(size_t)NB * NH * 64 * SEQ];     // transposed [v][k] fp16
__device__ float    g_ctx[(size_t)NB * SEQ * 256];
__device__ unsigned g_maskb[(size_t)NB * SEQ * 64];
__device__ __half   g_ph[(size_t)NB * NH * SEQ * SEQ];     // fp16 p scratch

// ---------------------------------------------------------------------------
// Helpers
// ---------------------------------------------------------------------------
__device__ __forceinline__ void mma_f16_k16(float& c0, float& c1, float& c2, float& c3,
                                            unsigned a0, unsigned a1, unsigned a2, unsigned a3,
                                            unsigned b0, unsigned b1) {
    asm volatile(
        "mma.sync.aligned.m16n8k16.row.col.f32.f16.f16.f32 "
        "{%0,%1,%2,%3},{%4,%5,%6,%7},{%8,%9},{%0,%1,%2,%3};"
        : "+f"(c0), "+f"(c1), "+f"(c2), "+f"(c3)
        : "r"(a0), "r"(a1), "r"(a2), "r"(a3), "r"(b0), "r"(b1));
}

__device__ __forceinline__ void ldsm_x4(unsigned& r0, unsigned& r1, unsigned& r2, unsigned& r3,
                                        unsigned addr) {
    asm volatile("ldmatrix.sync.aligned.m8n8.x4.shared.b16 {%0,%1,%2,%3}, [%4];"
                 : "=r"(r0), "=r"(r1), "=r"(r2), "=r"(r3) : "r"(addr));
}

__device__ __forceinline__ __half2 h2exp2_approx(__half2 x) {
    __half2 r;
    asm("ex2.approx.f16x2 %0, %1;" : "=r"(*(unsigned*)&r) : "r"(*(unsigned*)&x));
    return r;
}

__device__ __forceinline__ unsigned h2_as_u(__half2 v) {
    return *(unsigned*)&v;
}

__device__ __forceinline__ void cp_async16(void* smem, const void* gmem) {
    unsigned sa = (unsigned)__cvta_generic_to_shared(smem);
    asm volatile("cp.async.cg.shared.global [%0], [%1], 16;\n" :: "r"(sa), "l"(gmem));
}
__device__ __forceinline__ void cp_async4(void* smem, const void* gmem) {
    unsigned sa = (unsigned)__cvta_generic_to_shared(smem);
    asm volatile("cp.async.ca.shared.global [%0], [%1], 4;\n" :: "r"(sa), "l"(gmem));
}
#define CP_COMMIT() asm volatile("cp.async.commit_group;\n")
#define CP_WAIT(n)  asm volatile("cp.async.wait_group %0;\n" :: "n"(n))

// ---------------------------------------------------------------------------
// Kernel D: detect mask encoding
// ---------------------------------------------------------------------------
__global__ void detect_mask_kernel(const unsigned char* __restrict__ m) {
    int found = 0;
    for (int i = threadIdx.x; i < 1024; i += 32)
        if (m[i * 4 + 1] | m[i * 4 + 2] | m[i * 4 + 3]) found = 1;
    for (int o = 16; o; o >>= 1)
        found |= __shfl_xor_sync(0xffffffffu, found, o);
    if (threadIdx.x == 0) g_mask_mode = found ? 0 : 1;
}

// ---------------------------------------------------------------------------
// Kernel M: bit-pack the mask
// ---------------------------------------------------------------------------
__global__ void __launch_bounds__(256) convert_mask_kernel(const void* __restrict__ mask) {
    unsigned gid = blockIdx.x * 256 + threadIdx.x;
    unsigned nz;
    if (g_mask_mode) nz = (((const int*)mask)[gid] != 0) ? 1u : 0u;
    else             nz = (((const unsigned char*)mask)[gid] != 0) ? 1u : 0u;
    unsigned bits = __ballot_sync(0xffffffffu, nz);
    if ((threadIdx.x & 31) == 0) g_maskb[gid >> 5] = bits;
}

// ---------------------------------------------------------------------------
// Kernel 0: scalar gates
// ---------------------------------------------------------------------------
__global__ void gates_kernel(const float* __restrict__ u,
                             const float* __restrict__ sq1, const float* __restrict__ sq2,
                             const float* __restrict__ sk1, const float* __restrict__ sk2,
                             const float* __restrict__ sv1, const float* __restrict__ sv2) {
    const int b = blockIdx.x;
    const int lane = threadIdx.x;
    float hq = 0.f, hk = 0.f, hv = 0.f;
    for (int d = 0; d < DM; ++d) {
        float uv = u[b * DM + d];
        hq += uv * sq1[d * 32 + lane];
        hk += uv * sk1[d * 32 + lane];
        hv += uv * sv1[d * 32 + lane];
    }
    hq = fmaxf(hq, 0.f) * sq2[lane];
    hk = fmaxf(hk, 0.f) * sk2[lane];
    hv = fmaxf(hv, 0.f) * sv2[lane];
    for (int off = 16; off; off >>= 1) {
        hq += __shfl_xor_sync(0xffffffffu, hq, off);
        hk += __shfl_xor_sync(0xffffffffu, hk, off);
        hv += __shfl_xor_sync(0xffffffffu, hv, off);
    }
    if (lane == 0) {
        g_gates[b]      = hq;
        g_gates[8 + b]  = hk;
        g_gates[16 + b] = hv;
    }
}

// ---------------------------------------------------------------------------
// Kernel 1: projections, 2 CTAs/SM. Writes Veh directly (fp16 transposed).
// ---------------------------------------------------------------------------
#define PROJ_SMEM_BYTES ((64*68 + 3*64*68 + 64*132) * 4)

__global__ void __launch_bounds__(256, 2) proj_kernel(
    const float* __restrict__ x,
    const float* __restrict__ wq, const float* __restrict__ wk, const float* __restrict__ wv,
    const float* __restrict__ uqw, const float* __restrict__ ukw, const float* __restrict__ uvw) {
    extern __shared__ float sm[];
    float* xs   = sm;                 // 64 x 68
    float* uo   = xs + 64 * 68;       // 3 x (64 x 68)
    float* wbig = uo + 3 * 64 * 68;   // 64 x 132

    const int t = threadIdx.x;
    const int row0 = blockIdx.x * 64;
    const int b    = row0 >> 11;
    const int lr0  = row0 & (SEQ - 1);

    for (int i = t; i < 64 * 16; i += 256) {
        int r = i >> 4, c = (i & 15) * 4;
        *(float4*)(xs + r * 68 + c)            = *(const float4*)(x + (size_t)(row0 + r) * DM + c);
        *(float4*)(uo + 0 * 4352 + r * 68 + c) = *(const float4*)(uqw + r * 64 + c);
        *(float4*)(uo + 1 * 4352 + r * 68 + c) = *(const float4*)(ukw + r * 64 + c);
        *(float4*)(uo + 2 * 4352 + r * 68 + c) = *(const float4*)(uvw + r * 64 + c);
    }
    __syncthreads();

    const int rg = t >> 5;
    const int cg = t & 31;

    float uacc[8][8];
    if (cg < 24) {
        const int mat = cg >> 3;
        const int c0 = (cg & 7) * 8;
        const float* w = uo + mat * 4352;
        #pragma unroll
        for (int i = 0; i < 8; ++i)
            #pragma unroll
            for (int j = 0; j < 8; ++j) uacc[i][j] = 0.f;
        for (int k = 0; k < 64; ++k) {
            float av[8];
            #pragma unroll
            for (int i = 0; i < 8; ++i) av[i] = xs[(rg * 8 + i) * 68 + k];
            float4 b0 = *(const float4*)(w + k * 68 + c0);
            float4 b1 = *(const float4*)(w + k * 68 + c0 + 4);
            float bv[8] = {b0.x, b0.y, b0.z, b0.w, b1.x, b1.y, b1.z, b1.w};
            #pragma unroll
            for (int i = 0; i < 8; ++i)
                #pragma unroll
                for (int j = 0; j < 8; ++j) uacc[i][j] += av[i] * bv[j];
        }
    }
    __syncthreads();

    if (cg < 24) {
        const int mat = cg >> 3;
        const int c0 = (cg & 7) * 8;
        float* dst = uo + mat * 4352;
        #pragma unroll
        for (int i = 0; i < 8; ++i)
            #pragma unroll
            for (int j = 0; j < 8; ++j)
                dst[(rg * 8 + i) * 68 + c0 + j] = uacc[i][j];
    }
    __syncthreads();

    const float gq = g_gates[b] * 0.125f * LOG2E;
    const float gk = g_gates[8 + b];
    const float gv = g_gates[16 + b];

    for (int i = t; i < 64 * 64; i += 256) {
        int r = i >> 6, j = i & 63;
        __half vq = __float2half(uo[r * 68 + j] * gq);
        __half vk = __float2half(uo[4352 + r * 68 + j] * gk);
        size_t l = lr0 + r;
        #pragma unroll
        for (int h = 0; h < 4; ++h) {
            size_t base = (((size_t)b * 4 + h) * SEQ + l) * 128 + 64 + j;
            g_Qeh[base] = vq;
            g_Keh[base] = vk;
        }
    }

    for (int m = 0; m < 3; ++m) {
        const float* w = (m == 0) ? wq : (m == 1) ? wk : wv;
        for (int h2 = 0; h2 < 2; ++h2) {
            __syncthreads();
            for (int i = t; i < 64 * 32; i += 256) {
                int r = i >> 5, c = (i & 31) * 4;
                *(float4*)(wbig + r * 132 + c) = *(const float4*)(w + r * 256 + h2 * 128 + c);
            }
            __syncthreads();

            float acc[8][4];
            #pragma unroll
            for (int i = 0; i < 8; ++i)
                #pragma unroll
                for (int j = 0; j < 4; ++j) acc[i][j] = 0.f;
            for (int k = 0; k < 64; ++k) {
                float av[8];
                #pragma unroll
                for (int i = 0; i < 8; ++i) av[i] = xs[(rg * 8 + i) * 68 + k];
                float4 bb = *(const float4*)(wbig + k * 132 + cg * 4);
                float bv[4] = {bb.x, bb.y, bb.z, bb.w};
                #pragma unroll
                for (int i = 0; i < 8; ++i)
                    #pragma unroll
                    for (int j = 0; j < 4; ++j) acc[i][j] += av[i] * bv[j];
            }

            const int gc = h2 * 128 + cg * 4;
            const int h  = gc >> 6;
            const int j0 = gc & 63;
            if (m == 2) {
                // Ve -> g_Veh[bh][v = j0+j][k = lr0 + rg*8 + i], contiguous over i
                #pragma unroll
                for (int j = 0; j < 4; ++j) {
                    float vv[8];
                    #pragma unroll
                    for (int i = 0; i < 8; ++i)
                        vv[i] = acc[i][j] + uo[2 * 4352 + (rg * 8 + i) * 68 + j0 + j] * gv;
                    __half2 p0 = __floats2half2_rn(vv[0], vv[1]);
                    __half2 p1 = __floats2half2_rn(vv[2], vv[3]);
                    __half2 p2 = __floats2half2_rn(vv[4], vv[5]);
                    __half2 p3 = __floats2half2_rn(vv[6], vv[7]);
                    uint4 pk;
                    pk.x = h2_as_u(p0);
                    pk.y = h2_as_u(p1);
                    pk.z = h2_as_u(p2);
                    pk.w = h2_as_u(p3);
                    *(uint4*)(g_Veh + (((size_t)b * 4 + h) * 64 + j0 + j) * SEQ + lr0 + rg * 8) = pk;
                }
            } else {
                __half* tgt = (m == 0) ? g_Qeh : g_Keh;
                float s = (m == 0) ? (0.125f * LOG2E) : 1.0f;
                #pragma unroll
                for (int i = 0; i < 8; ++i) {
                    size_t l = lr0 + rg * 8 + i;
                    size_t base = (((size_t)b * 4 + h) * SEQ + l) * 128 + j0;
                    *(__half2*)(tgt + base)     = __floats2half2_rn(acc[i][0] * s, acc[i][1] * s);
                    *(__half2*)(tgt + base + 2) = __floats2half2_rn(acc[i][2] * s, acc[i][3] * s);
                }
            }
        }
    }
}

// ---------------------------------------------------------------------------
// Kernel 2 (v10): attention. 256 threads / 8 warps, 3 CTAs/SM, 2-buf cp.async.
// Warp = (qh = w>>2, np = w&3): 16 q-rows x 16 k/v-cols via A-reg reuse.
// LDSM.x4 for K, V, p fragments. fp16x2 exp2.
// smem(halves): qs 32x136 | ks 2x64x136 | vsh 2x64x72 | psh 2x32x72
//   + red 128f | inv 32f | msb 2x64 u32  = ~72.3 KB (3 CTAs/SM)
// ---------------------------------------------------------------------------
#define ATT_SMEM_BYTES ((TQ*KH + 2*64*KH + 2*64*VH + 2*TQ*VH) * 2 + 128*4 + 32*4 + 128*4)

__global__ void __launch_bounds__(256, 3) attn2_kernel(float* __restrict__ attn_out) {
    extern __shared__ __half smh[];
    __half* qs  = smh;                       // 32 x 136
    __half* ks  = qs + TQ * KH;              // 2 x 64 x 136
    __half* vsh = ks + 2 * 64 * KH;          // 2 x 64 x 72
    __half* psh = vsh + 2 * 64 * VH;         // 2 x 32 x 72
    float*  red = (float*)(psh + 2 * TQ * VH);   // 8 x 16
    float*  inv = red + 128;                     // 32
    unsigned* msb = (unsigned*)(inv + 32);       // 2 x 64

    const unsigned smbase = (unsigned)__cvta_generic_to_shared(smh);
    const unsigned ks_a = smbase + (unsigned)(TQ * KH) * 2;
    const unsigned vs_a = ks_a + (unsigned)(2 * 64 * KH) * 2;
    const unsigned ps_a = vs_a + (unsigned)(2 * 64 * VH) * 2;

    const int t    = threadIdx.x;
    const int w    = t >> 5;
    const int lane = t & 31;
    const int g    = lane >> 2;
    const int tig  = lane & 3;
    const int qh   = w >> 2;               // 0/1: 16-row half
    const int np   = w & 3;                // n-pair index
    const int n0   = np * 16;              // 16 cols per warp
    const int ra   = qh * 16 + g;
    const int rb   = ra + 8;

    // LDSM per-lane byte offsets
    const int lb  = lane & 7;
    const int r8  = ((lane >> 4) & 1) * 8;
    const int c8  = ((lane >> 3) & 1) * 8;
    const unsigned koff = (unsigned)(((n0 + r8 + lb) * KH + c8) * 2);
    const unsigned voff = (unsigned)(((n0 + r8 + lb) * VH + c8) * 2);
    const unsigned poff = (unsigned)((qh * 16 + (lane & 15)) * VH * 2 + ((lane >> 4) & 1) * 16);

    const int bh = blockIdx.x >> 6;
    const int qt = blockIdx.x & 63;
    const int b  = bh >> 2;
    const int h  = bh & 3;
    const int q0 = qt * TQ;

    const __half* Qg = g_Qeh + ((size_t)bh * SEQ + q0) * 128;
    const __half* Kg = g_Keh + (size_t)bh * SEQ * 128;
    const __half* Vg = g_Veh + (size_t)bh * 64 * SEQ;
    const unsigned* Mb = g_maskb + ((size_t)b * SEQ + q0) * 64;
    __half* php = g_ph + ((size_t)bh * SEQ + q0) * SEQ;
    float* ao = attn_out + ((size_t)bh * SEQ + q0) * SEQ;

    // ---- stage Q + tile 0 ----
    for (int i = t; i < TQ * 16; i += 256) {
        int r = i >> 4, cc = (i & 15) * 8;
        cp_async16(qs + r * KH + cc, Qg + (size_t)r * 128 + cc);
    }
    for (int i = t; i < 64 * 16; i += 256) {
        int r = i >> 4, cc = (i & 15) * 8;
        cp_async16(ks + r * KH + cc, Kg + (size_t)r * 128 + cc);
    }
    for (int i = t; i < 64 * 8; i += 256) {
        int r = i >> 3, cc = (i & 7) * 8;
        cp_async16(vsh + r * VH + cc, Vg + (size_t)r * SEQ + cc);
    }
    if (t < 2 * TQ)
        cp_async4(msb + t, Mb + (size_t)(t >> 1) * 64 + (t & 1));
    CP_COMMIT();
    CP_WAIT(0);
    __syncthreads();

    // ---- hoist A (Q) fragments ----
    unsigned a[8][4];
    #pragma unroll
    for (int kk = 0; kk < 8; ++kk) {
        a[kk][0] = *(const unsigned*)(qs + ra * KH + kk * 16 + 2 * tig);
        a[kk][1] = *(const unsigned*)(qs + rb * KH + kk * 16 + 2 * tig);
        a[kk][2] = *(const unsigned*)(qs + ra * KH + kk * 16 + 2 * tig + 8);
        a[kk][3] = *(const unsigned*)(qs + rb * KH + kk * 16 + 2 * tig + 8);
    }

    float cxA0 = 0.f, cxA1 = 0.f, cxA2 = 0.f, cxA3 = 0.f;
    float cxB0 = 0.f, cxB1 = 0.f, cxB2 = 0.f, cxB3 = 0.f;
    float sl0 = 0.f, sl1 = 0.f;
    const int colA = n0 + 2 * tig;
    const int colB = colA + 8;
    const int mw   = n0 >> 5;

    for (int tile = 0; tile < NT; ++tile) {
        const int buf = tile & 1;
        const unsigned kbuf_a = ks_a + (unsigned)(buf * 64 * KH) * 2;
        const unsigned vbuf_a = vs_a + (unsigned)(buf * 64 * VH) * 2;
        const unsigned pbuf_a = ps_a + (unsigned)(buf * TQ * VH) * 2;
        const unsigned* mb = msb + buf * 2 * TQ;
        const int k0 = tile * 64;

        // ---- QK: 8 chunks x (LDSM.x4 + 2 mmas reusing A) ----
        float cA0 = 0.f, cA1 = 0.f, cA2 = 0.f, cA3 = 0.f;
        float cB0 = 0.f, cB1 = 0.f, cB2 = 0.f, cB3 = 0.f;
        #pragma unroll
        for (int kk = 0; kk < 8; ++kk) {
            unsigned b0, b1, b2, b3;
            ldsm_x4(b0, b1, b2, b3, kbuf_a + koff + kk * 32);
            mma_f16_k16(cA0, cA1, cA2, cA3, a[kk][0], a[kk][1], a[kk][2], a[kk][3], b0, b1);
            mma_f16_k16(cB0, cB1, cB2, cB3, a[kk][0], a[kk][1], a[kk][2], a[kk][3], b2, b3);
        }

        // ---- mask + fp16x2 exp2 ----
        unsigned w0 = mb[ra * 2 + mw];
        unsigned w1 = mb[rb * 2 + mw];
        float mA00 = ((w0 >> (colA & 31)) & 1u)       ? -100.f : cA0;
        float mA01 = ((w0 >> ((colA + 1) & 31)) & 1u) ? -100.f : cA1;
        float mA10 = ((w1 >> (colA & 31)) & 1u)       ? -100.f : cA2;
        float mA11 = ((w1 >> ((colA + 1) & 31)) & 1u) ? -100.f : cA3;
        float mB00 = ((w0 >> (colB & 31)) & 1u)       ? -100.f : cB0;
        float mB01 = ((w0 >> ((colB + 1) & 31)) & 1u) ? -100.f : cB1;
        float mB10 = ((w1 >> (colB & 31)) & 1u)       ? -100.f : cB2;
        float mB11 = ((w1 >> ((colB + 1) & 31)) & 1u) ? -100.f : cB3;
        __half2 hA0 = h2exp2_approx(__floats2half2_rn(mA00, mA01));
        __half2 hA1 = h2exp2_approx(__floats2half2_rn(mA10, mA11));
        __half2 hB0 = h2exp2_approx(__floats2half2_rn(mB00, mB01));
        __half2 hB1 = h2exp2_approx(__floats2half2_rn(mB10, mB11));
        float2 fA0 = __half22float2(hA0);
        float2 fA1 = __half22float2(hA1);
        float2 fB0 = __half22float2(hB0);
        float2 fB1 = __half22float2(hB1);
        sl0 += fA0.x + fA0.y + fB0.x + fB0.y;
        sl1 += fA1.x + fA1.y + fB1.x + fB1.y;

        // ---- p fp16 -> scratch global + psh ----
        *(__half2*)(php + (size_t)ra * SEQ + k0 + colA) = hA0;
        *(__half2*)(php + (size_t)rb * SEQ + k0 + colA) = hA1;
        *(__half2*)(php + (size_t)ra * SEQ + k0 + colB) = hB0;
        *(__half2*)(php + (size_t)rb * SEQ + k0 + colB) = hB1;
        __half* pw = psh + buf * TQ * VH;
        *(__half2*)(pw + ra * VH + colA) = hA0;
        *(__half2*)(pw + rb * VH + colA) = hA1;
        *(__half2*)(pw + ra * VH + colB) = hB0;
        *(__half2*)(pw + rb * VH + colB) = hB1;
        __syncthreads();    // S1: psh ready; prior tile's buffers fully consumed

        // ---- prefetch tile+1 into the other buffer ----
        if (tile + 1 < NT) {
            const int nb = buf ^ 1;
            const int nk0 = k0 + 64;
            for (int i = t; i < 64 * 16; i += 256) {
                int r = i >> 4, cc = (i & 15) * 8;
                cp_async16(ks + nb * 64 * KH + r * KH + cc,
                           Kg + (size_t)(nk0 + r) * 128 + cc);
            }
            for (int i = t; i < 64 * 8; i += 256) {
                int r = i >> 3, cc = (i & 7) * 8;
                cp_async16(vsh + nb * 64 * VH + r * VH + cc,
                           Vg + (size_t)r * SEQ + nk0 + cc);
            }
            if (t < 2 * TQ)
                cp_async4(msb + nb * 2 * TQ + t,
                          Mb + (size_t)(t >> 1) * 64 + (nk0 >> 5) + (t & 1));
            CP_COMMIT();
        }

        // ---- PV: 4 chunks x (p LDSM.x4 + V LDSM.x4 + 2 mmas) ----
        #pragma unroll
        for (int kk = 0; kk < 4; ++kk) {
            unsigned p0, p1, p2, p3, v0, v1, v2, v3;
            ldsm_x4(p0, p1, p2, p3, pbuf_a + poff + kk * 32);
            ldsm_x4(v0, v1, v2, v3, vbuf_a + voff + kk * 32);
            mma_f16_k16(cxA0, cxA1, cxA2, cxA3, p0, p1, p2, p3, v0, v1);
            mma_f16_k16(cxB0, cxB1, cxB2, cxB3, p0, p1, p2, p3, v2, v3);
        }

        CP_WAIT(0);
        __syncthreads();    // end: next tile visible; buffers free
    }

    // ---- row-sum reduction (4 warps per qh) ----
    sl0 += __shfl_xor_sync(0xffffffffu, sl0, 1);
    sl0 += __shfl_xor_sync(0xffffffffu, sl0, 2);
    sl1 += __shfl_xor_sync(0xffffffffu, sl1, 1);
    sl1 += __shfl_xor_sync(0xffffffffu, sl1, 2);
    if (tig == 0) {
        red[w * 16 + g]     = sl0;
        red[w * 16 + 8 + g] = sl1;
    }
    __syncthreads();
    if (t < TQ) {
        int qh_r = t >> 4;
        int rr   = t & 15;
        float s = 0.f;
        #pragma unroll
        for (int ww = 0; ww < 4; ++ww) s += red[(qh_r * 4 + ww) * 16 + rr];
        inv[t] = 1.f / s;
    }
    __syncthreads();

    // ---- normalized ctx write ----
    {
        float iv0 = inv[ra];
        float iv1 = inv[rb];
        size_t r0g = (size_t)b * SEQ + q0;
        *(float2*)(g_ctx + (r0g + ra) * 256 + h * 64 + colA) = make_float2(cxA0 * iv0, cxA1 * iv0);
        *(float2*)(g_ctx + (r0g + rb) * 256 + h * 64 + colA) = make_float2(cxA2 * iv1, cxA3 * iv1);
        *(float2*)(g_ctx + (r0g + ra) * 256 + h * 64 + colB) = make_float2(cxB0 * iv0, cxB1 * iv0);
        *(float2*)(g_ctx + (r0g + rb) * 256 + h * 64 + colB) = make_float2(cxB2 * iv1, cxB3 * iv1);
    }

    // ---- normalize: read fp16 scratch (L2-warm), write fp32 attn once ----
    for (int r = 0; r < TQ; ++r) {
        float iv = inv[r];
        uint4 pk = *((const uint4*)(php + (size_t)r * SEQ) + t);
        float2 q0f = __half22float2(*(__half2*)&pk.x);
        float2 q1f = __half22float2(*(__half2*)&pk.y);
        float2 q2f = __half22float2(*(__half2*)&pk.z);
        float2 q3f = __half22float2(*(__half2*)&pk.w);
        float4 o0 = make_float4(q0f.x * iv, q0f.y * iv, q1f.x * iv, q1f.y * iv);
        float4 o1 = make_float4(q2f.x * iv, q2f.y * iv, q3f.x * iv, q3f.y * iv);
        float4* dst = (float4*)(ao + (size_t)r * SEQ) + t * 2;
        dst[0] = o0;
        dst[1] = o1;
    }
}

// ---------------------------------------------------------------------------
// Kernel 3 (v2): fc + LN1 + FFN + LN2. 32 rows/CTA, weights via __ldg.
// ---------------------------------------------------------------------------
#define POST_SMEM_BYTES ((32*260 + 2*32*68) * 4)

__global__ void __launch_bounds__(256, 4) post_kernel(
    const float* __restrict__ x, const float* __restrict__ fcw,
    const float* __restrict__ ln1g, const float* __restrict__ ln1b,
    const float* __restrict__ f1, const float* __restrict__ f2,
    const float* __restrict__ ln2g, const float* __restrict__ ln2b,
    float* __restrict__ res) {
    extern __shared__ float sm[];
    float* cs = sm;               // 32 x 260
    float* hs = cs + 32 * 260;    // 32 x 68 (x, then relu hidden)
    float* es = hs + 32 * 68;     // 32 x 68

    const int t = threadIdx.x;
    const int row0 = blockIdx.x * 32;

    for (int i = t; i < 32 * 64; i += 256) {
        int r = i >> 6, c = (i & 63) * 4;
        *(float4*)(cs + r * 260 + c) = *(const float4*)(g_ctx + (size_t)(row0 + r) * 256 + c);
    }
    for (int i = t; i < 32 * 16; i += 256) {
        int r = i >> 4, c = (i & 15) * 4;
        *(float4*)(hs + r * 68 + c) = *(const float4*)(x + (size_t)(row0 + r) * DM + c);
    }
    __syncthreads();

    const int rg = t >> 5;
    const int cg = t & 31;
    const int c0 = cg * 2;

    float acc[4][2];
    #pragma unroll
    for (int i = 0; i < 4; ++i) { acc[i][0] = 0.f; acc[i][1] = 0.f; }
    for (int k = 0; k < 256; ++k) {
        float2 bb = __ldg((const float2*)(fcw + k * 64 + c0));
        #pragma unroll
        for (int i = 0; i < 4; ++i) {
            float av = cs[(rg * 4 + i) * 260 + k];
            acc[i][0] += av * bb.x;
            acc[i][1] += av * bb.y;
        }
    }

    float g0 = __ldg(ln1g + c0), g1 = __ldg(ln1g + c0 + 1);
    float b0 = __ldg(ln1b + c0), b1 = __ldg(ln1b + c0 + 1);
    #pragma unroll
    for (int i = 0; i < 4; ++i) {
        float y0 = acc[i][0] + hs[(rg * 4 + i) * 68 + c0];
        float y1 = acc[i][1] + hs[(rg * 4 + i) * 68 + c0 + 1];
        float s = y0 + y1;
        float q = y0 * y0 + y1 * y1;
        #pragma unroll
        for (int o = 16; o; o >>= 1) {
            s += __shfl_xor_sync(0xffffffffu, s, o);
            q += __shfl_xor_sync(0xffffffffu, q, o);
        }
        float mu = s * (1.f / 64.f);
        float var = q * (1.f / 64.f) - mu * mu;
        float rs = rsqrtf(var + 1e-5f);
        *(float2*)(es + (rg * 4 + i) * 68 + c0) =
            make_float2((y0 - mu) * rs * g0 + b0, (y1 - mu) * rs * g1 + b1);
    }
    __syncthreads();

    float h4[4][2];
    #pragma unroll
    for (int i = 0; i < 4; ++i) { h4[i][0] = 0.f; h4[i][1] = 0.f; }
    for (int k = 0; k < 64; ++k) {
        float2 bb = __ldg((const float2*)(f1 + k * 64 + c0));
        #pragma unroll
        for (int i = 0; i < 4; ++i) {
            float av = es[(rg * 4 + i) * 68 + k];
            h4[i][0] += av * bb.x;
            h4[i][1] += av * bb.y;
        }
    }
    __syncthreads();
    #pragma unroll
    for (int i = 0; i < 4; ++i)
        *(float2*)(hs + (rg * 4 + i) * 68 + c0) =
            make_float2(fmaxf(h4[i][0], 0.f), fmaxf(h4[i][1], 0.f));
    __syncthreads();

    float fa[4][2];
    #pragma unroll
    for (int i = 0; i < 4; ++i) { fa[i][0] = 0.f; fa[i][1] = 0.f; }
    for (int k = 0; k < 64; ++k) {
        float2 bb = __ldg((const float2*)(f2 + k * 64 + c0));
        #pragma unroll
        for (int i = 0; i < 4; ++i) {
            float av = hs[(rg * 4 + i) * 68 + k];
            fa[i][0] += av * bb.x;
            fa[i][1] += av * bb.y;
        }
    }
    float g20 = __ldg(ln2g + c0), g21 = __ldg(ln2g + c0 + 1);
    float b20 = __ldg(ln2b + c0), b21 = __ldg(ln2b + c0 + 1);
    #pragma unroll
    for (int i = 0; i < 4; ++i) {
        float y0 = fa[i][0] + es[(rg * 4 + i) * 68 + c0];
        float y1 = fa[i][1] + es[(rg * 4 + i) * 68 + c0 + 1];
        float s = y0 + y1;
        float q = y0 * y0 + y1 * y1;
        #pragma unroll
        for (int o = 16; o; o >>= 1) {
            s += __shfl_xor_sync(0xffffffffu, s, o);
            q += __shfl_xor_sync(0xffffffffu, q, o);
        }
        float mu = s * (1.f / 64.f);
        float var = q * (1.f / 64.f) - mu * mu;
        float rs = rsqrtf(var + 1e-5f);
        *(float2*)(res + (size_t)(row0 + rg * 4 + i) * 64 + c0) =
            make_float2((y0 - mu) * rs * g20 + b20, (y1 - mu) * rs * g21 + b21);
    }
}

// ---------------------------------------------------------------------------
// Launch
// ---------------------------------------------------------------------------
extern "C" void kernel_launch(void* const* d_in, const int* in_sizes, int n_in,
                              void* d_out, int out_size) {
    const float* x    = (const float*)d_in[0];
    const void*  mask = d_in[1];
    const float* u    = (const float*)d_in[2];
    const float* wq   = (const float*)d_in[3];
    const float* wk   = (const float*)d_in[4];
    const float* wv   = (const float*)d_in[5];
    const float* uqw  = (const float*)d_in[6];
    const float* ukw  = (const float*)d_in[7];
    const float* uvw  = (const float*)d_in[8];
    const float* sq1  = (const float*)d_in[9];
    const float* sq2  = (const float*)d_in[10];
    const float* sk1  = (const float*)d_in[11];
    const float* sk2  = (const float*)d_in[12];
    const float* sv1  = (const float*)d_in[13];
    const float* sv2  = (const float*)d_in[14];
    const float* fcw  = (const float*)d_in[15];
    const float* ln1g = (const float*)d_in[16];
    const float* ln1b = (const float*)d_in[17];
    const float* ffn1 = (const float*)d_in[18];
    const float* ffn2 = (const float*)d_in[19];
    const float* ln2g = (const float*)d_in[20];
    const float* ln2b = (const float*)d_in[21];

    float* res  = (float*)d_out;
    float* attn = res + (size_t)NB * SEQ * DM;

    cudaFuncSetAttribute(proj_kernel,  cudaFuncAttributeMaxDynamicSharedMemorySize, PROJ_SMEM_BYTES);
    cudaFuncSetAttribute(attn2_kernel, cudaFuncAttributeMaxDynamicSharedMemorySize, ATT_SMEM_BYTES);
    cudaFuncSetAttribute(post_kernel,  cudaFuncAttributeMaxDynamicSharedMemorySize, POST_SMEM_BYTES);

    detect_mask_kernel<<<1, 32>>>((const unsigned char*)mask);
    convert_mask_kernel<<<(NB * SEQ * SEQ) / 256, 256>>>(mask);
    gates_kernel<<<NB, 32>>>(u, sq1, sq2, sk1, sk2, sv1, sv2);
    proj_kernel<<<(NB * SEQ) / 64, 256, PROJ_SMEM_BYTES>>>(x, wq, wk, wv, uqw, ukw, uvw);
    attn2_kernel<<<NB * NH * (SEQ / TQ), 256, ATT_SMEM_BYTES>>>(attn);
    post_kernel<<<(NB * SEQ) / 32, 256, POST_SMEM_BYTES>>>(x, fcw, ln1g, ln1b, ffn1, ffn2,
                                                           ln2g, ln2b, res);
}

// round 16
// speedup vs baseline: 1.2828x; 1.0239x over previous
#include <cuda_runtime.h>
#include <cuda_fp16.h>
#include <cstdint>
#include <cstddef>

// ---------------------------------------------------------------------------
// Problem constants
// ---------------------------------------------------------------------------
#define NB   8
#define NH   4
#define SEQ  2048
#define DM   64

#define TQ   32
#define KH   136
#define VH   72
#define NT   (SEQ / 64)

#define LOG2E 1.4426950408889634f

// ---------------------------------------------------------------------------
// Static device scratch
// ---------------------------------------------------------------------------
__device__ float    g_gates[3 * NB];
__device__ int      g_mask_mode;
__device__ __half   g_Qeh[(size_t)NB * NH * SEQ * 128];    // fp16, scaled 0.125*log2e
__device__ __half   g_Keh[(size_t)NB * NH * SEQ * 128];
__device__ __half   g_Veh[(size_t)NB * NH * 64 * SEQ];     // transposed [v][k] fp16
__device__ float    g_ctx[(size_t)NB * SEQ * 256];
__device__ unsigned g_maskb[(size_t)NB * SEQ * 64];
__device__ __half   g_ph[(size_t)NB * NH * SEQ * SEQ];     // fp16 p scratch

// ---------------------------------------------------------------------------
// Helpers
// ---------------------------------------------------------------------------
__device__ __forceinline__ void mma_f16_k16(float& c0, float& c1, float& c2, float& c3,
                                            unsigned a0, unsigned a1, unsigned a2, unsigned a3,
                                            unsigned b0, unsigned b1) {
    asm volatile(
        "mma.sync.aligned.m16n8k16.row.col.f32.f16.f16.f32 "
        "{%0,%1,%2,%3},{%4,%5,%6,%7},{%8,%9},{%0,%1,%2,%3};"
        : "+f"(c0), "+f"(c1), "+f"(c2), "+f"(c3)
        : "r"(a0), "r"(a1), "r"(a2), "r"(a3), "r"(b0), "r"(b1));
}

__device__ __forceinline__ void ldsm_x4(unsigned& r0, unsigned& r1, unsigned& r2, unsigned& r3,
                                        unsigned addr) {
    asm volatile("ldmatrix.sync.aligned.m8n8.x4.shared.b16 {%0,%1,%2,%3}, [%4];"
                 : "=r"(r0), "=r"(r1), "=r"(r2), "=r"(r3) : "r"(addr));
}

__device__ __forceinline__ __half2 h2exp2_approx(__half2 x) {
    __half2 r;
    asm("ex2.approx.f16x2 %0, %1;" : "=r"(*(unsigned*)&r) : "r"(*(unsigned*)&x));
    return r;
}

__device__ __forceinline__ unsigned h2_as_u(__half2 v) {
    return *(unsigned*)&v;
}

__device__ __forceinline__ void cp_async16(void* smem, const void* gmem) {
    unsigned sa = (unsigned)__cvta_generic_to_shared(smem);
    asm volatile("cp.async.cg.shared.global [%0], [%1], 16;\n" :: "r"(sa), "l"(gmem));
}
__device__ __forceinline__ void cp_async4(void* smem, const void* gmem) {
    unsigned sa = (unsigned)__cvta_generic_to_shared(smem);
    asm volatile("cp.async.ca.shared.global [%0], [%1], 4;\n" :: "r"(sa), "l"(gmem));
}
#define CP_COMMIT() asm volatile("cp.async.commit_group;\n")
#define CP_WAIT(n)  asm volatile("cp.async.wait_group %0;\n" :: "n"(n))

// ---------------------------------------------------------------------------
// Kernel D: detect mask encoding
// ---------------------------------------------------------------------------
__global__ void detect_mask_kernel(const unsigned char* __restrict__ m) {
    int found = 0;
    for (int i = threadIdx.x; i < 1024; i += 32)
        if (m[i * 4 + 1] | m[i * 4 + 2] | m[i * 4 + 3]) found = 1;
    for (int o = 16; o; o >>= 1)
        found |= __shfl_xor_sync(0xffffffffu, found, o);
    if (threadIdx.x == 0) g_mask_mode = found ? 0 : 1;
}

// ---------------------------------------------------------------------------
// Kernel M: bit-pack the mask
// ---------------------------------------------------------------------------
__global__ void __launch_bounds__(256) convert_mask_kernel(const void* __restrict__ mask) {
    unsigned gid = blockIdx.x * 256 + threadIdx.x;
    unsigned nz;
    if (g_mask_mode) nz = (((const int*)mask)[gid] != 0) ? 1u : 0u;
    else             nz = (((const unsigned char*)mask)[gid] != 0) ? 1u : 0u;
    unsigned bits = __ballot_sync(0xffffffffu, nz);
    if ((threadIdx.x & 31) == 0) g_maskb[gid >> 5] = bits;
}

// ---------------------------------------------------------------------------
// Kernel 0: scalar gates
// ---------------------------------------------------------------------------
__global__ void gates_kernel(const float* __restrict__ u,
                             const float* __restrict__ sq1, const float* __restrict__ sq2,
                             const float* __restrict__ sk1, const float* __restrict__ sk2,
                             const float* __restrict__ sv1, const float* __restrict__ sv2) {
    const int b = blockIdx.x;
    const int lane = threadIdx.x;
    float hq = 0.f, hk = 0.f, hv = 0.f;
    for (int d = 0; d < DM; ++d) {
        float uv = u[b * DM + d];
        hq += uv * sq1[d * 32 + lane];
        hk += uv * sk1[d * 32 + lane];
        hv += uv * sv1[d * 32 + lane];
    }
    hq = fmaxf(hq, 0.f) * sq2[lane];
    hk = fmaxf(hk, 0.f) * sk2[lane];
    hv = fmaxf(hv, 0.f) * sv2[lane];
    for (int off = 16; off; off >>= 1) {
        hq += __shfl_xor_sync(0xffffffffu, hq, off);
        hk += __shfl_xor_sync(0xffffffffu, hk, off);
        hv += __shfl_xor_sync(0xffffffffu, hv, off);
    }
    if (lane == 0) {
        g_gates[b]      = hq;
        g_gates[8 + b]  = hk;
        g_gates[16 + b] = hv;
    }
}

// ---------------------------------------------------------------------------
// Kernel 1 (v4): tensor-core projections. 64 rows/CTA, 256 threads, 2 CTAs/SM.
// smem: xh 64x72 h | wt 256x72 h | vt 256x72 h | uvs 64x68 f  = ~98 KB
// ---------------------------------------------------------------------------
#define PROJ_SMEM_BYTES ((64*72 + 256*72 + 256*72) * 2 + (64*68) * 4)

__global__ void __launch_bounds__(256, 2) proj_kernel(
    const float* __restrict__ x,
    const float* __restrict__ wq, const float* __restrict__ wk, const float* __restrict__ wv,
    const float* __restrict__ uqw, const float* __restrict__ ukw, const float* __restrict__ uvw) {
    extern __shared__ __half smh[];
    __half* xh  = smh;                 // 64 x 72
    __half* wt  = xh + 64 * 72;        // 256 x 72 (transposed weights [n][k])
    __half* vt  = wt + 256 * 72;       // 256 x 72 (V output staging [v][r])
    float*  uvs = (float*)(vt + 256 * 72);  // 64 x 68

    const unsigned smbase = (unsigned)__cvta_generic_to_shared(smh);
    const unsigned xh_a = smbase;
    const unsigned wt_a = smbase + (unsigned)(64 * 72) * 2;

    const int t    = threadIdx.x;
    const int w    = t >> 5;
    const int lane = t & 31;
    const int g    = lane >> 2;
    const int tig  = lane & 3;
    const int wr   = w >> 1;           // 0..3 : 16-row block
    const int wc   = w & 1;            // 0/1  : column half
    const int ra   = wr * 16 + g;
    const int rb   = ra + 8;

    const int lb = lane & 7;
    const int r8 = ((lane >> 4) & 1) * 8;
    const int c8 = ((lane >> 3) & 1) * 8;

    const int row0 = blockIdx.x * 64;
    const int b    = row0 >> 11;
    const int lr0  = row0 & (SEQ - 1);

    // ---- stage x (fp16) ----
    for (int i = t; i < 64 * 16; i += 256) {
        int r = i >> 4, c4 = (i & 15) * 4;
        float4 v = *(const float4*)(x + (size_t)(row0 + r) * DM + c4);
        __half2 h0 = __floats2half2_rn(v.x, v.y);
        __half2 h1 = __floats2half2_rn(v.z, v.w);
        *(__half2*)(xh + r * 72 + c4)     = h0;
        *(__half2*)(xh + r * 72 + c4 + 2) = h1;
    }
    // ---- stage u-weights transposed ----
    for (int i = t; i < 3 * 64 * 64; i += 256) {
        int mat = i >> 12;
        int j   = i & 4095;
        int k   = j >> 6;
        int n   = j & 63;
        const float* wsrc = (mat == 0) ? uqw : (mat == 1) ? ukw : uvw;
        wt[(mat * 64 + n) * 72 + k] = __float2half(wsrc[k * 64 + n]);
    }
    __syncthreads();

    // ---- hoist A (x) fragments: 4 k16 chunks ----
    unsigned a[4][4];
    {
        unsigned aoff = xh_a + (unsigned)((wr * 16 + (lane & 15)) * 72) * 2
                             + (unsigned)(((lane >> 4) & 1) * 16);
        #pragma unroll
        for (int kk = 0; kk < 4; ++kk)
            ldsm_x4(a[kk][0], a[kk][1], a[kk][2], a[kk][3], aoff + kk * 32);
    }

    const float gq = g_gates[b] * 0.125f * LOG2E;
    const float gk = g_gates[8 + b];
    const float gv = g_gates[16 + b];

    // ---- u GEMM: 6 groups of 16 cols per warp over N=192 ----
    for (int grp = 0; grp < 6; ++grp) {
        const int gn0 = wc * 96 + grp * 16;
        float cA0 = 0.f, cA1 = 0.f, cA2 = 0.f, cA3 = 0.f;
        float cB0 = 0.f, cB1 = 0.f, cB2 = 0.f, cB3 = 0.f;
        unsigned boff = wt_a + (unsigned)(((gn0 + r8 + lb) * 72 + c8) * 2);
        #pragma unroll
        for (int kk = 0; kk < 4; ++kk) {
            unsigned b0, b1, b2, b3;
            ldsm_x4(b0, b1, b2, b3, boff + kk * 32);
            mma_f16_k16(cA0, cA1, cA2, cA3, a[kk][0], a[kk][1], a[kk][2], a[kk][3], b0, b1);
            mma_f16_k16(cB0, cB1, cB2, cB3, a[kk][0], a[kk][1], a[kk][2], a[kk][3], b2, b3);
        }
        const int mat = gn0 >> 6;
        const int jc  = gn0 & 63;
        if (mat < 2) {
            float s = (mat == 0) ? gq : gk;
            __half* tgt = (mat == 0) ? g_Qeh : g_Keh;
            __half2 hA0 = __floats2half2_rn(cA0 * s, cA1 * s);
            __half2 hA1 = __floats2half2_rn(cA2 * s, cA3 * s);
            __half2 hB0 = __floats2half2_rn(cB0 * s, cB1 * s);
            __half2 hB1 = __floats2half2_rn(cB2 * s, cB3 * s);
            #pragma unroll
            for (int h = 0; h < 4; ++h) {
                size_t rowA = ((size_t)(b * 4 + h) * SEQ + lr0 + ra) * 128 + 64 + jc + 2 * tig;
                size_t rowB = ((size_t)(b * 4 + h) * SEQ + lr0 + rb) * 128 + 64 + jc + 2 * tig;
                *(__half2*)(tgt + rowA)     = hA0;
                *(__half2*)(tgt + rowB)     = hA1;
                *(__half2*)(tgt + rowA + 8) = hB0;
                *(__half2*)(tgt + rowB + 8) = hB1;
            }
        } else {
            int cc = jc + 2 * tig;
            *(float2*)(uvs + ra * 68 + cc)     = make_float2(cA0 * gv, cA1 * gv);
            *(float2*)(uvs + rb * 68 + cc)     = make_float2(cA2 * gv, cA3 * gv);
            *(float2*)(uvs + ra * 68 + cc + 8) = make_float2(cB0 * gv, cB1 * gv);
            *(float2*)(uvs + rb * 68 + cc + 8) = make_float2(cB2 * gv, cB3 * gv);
        }
    }
    __syncthreads();   // uvs complete, wt free

    // ---- Q / K / V GEMMs (N = 256) ----
    for (int m = 0; m < 3; ++m) {
        const float* wsrc = (m == 0) ? wq : (m == 1) ? wk : wv;
        for (int i = t; i < 64 * 256; i += 256) {
            int k = i >> 8;
            int n = i & 255;
            wt[n * 72 + k] = __float2half(wsrc[k * 256 + n]);
        }
        __syncthreads();

        for (int grp = 0; grp < 8; ++grp) {
            const int gn0 = wc * 128 + grp * 16;
            float cA0 = 0.f, cA1 = 0.f, cA2 = 0.f, cA3 = 0.f;
            float cB0 = 0.f, cB1 = 0.f, cB2 = 0.f, cB3 = 0.f;
            unsigned boff = wt_a + (unsigned)(((gn0 + r8 + lb) * 72 + c8) * 2);
            #pragma unroll
            for (int kk = 0; kk < 4; ++kk) {
                unsigned b0, b1, b2, b3;
                ldsm_x4(b0, b1, b2, b3, boff + kk * 32);
                mma_f16_k16(cA0, cA1, cA2, cA3, a[kk][0], a[kk][1], a[kk][2], a[kk][3], b0, b1);
                mma_f16_k16(cB0, cB1, cB2, cB3, a[kk][0], a[kk][1], a[kk][2], a[kk][3], b2, b3);
            }
            const int h  = gn0 >> 6;
            const int jc = gn0 & 63;
            if (m < 2) {
                float s = (m == 0) ? (0.125f * LOG2E) : 1.0f;
                __half* tgt = (m == 0) ? g_Qeh : g_Keh;
                size_t rowA = ((size_t)(b * 4 + h) * SEQ + lr0 + ra) * 128 + jc + 2 * tig;
                size_t rowB = ((size_t)(b * 4 + h) * SEQ + lr0 + rb) * 128 + jc + 2 * tig;
                *(__half2*)(tgt + rowA)     = __floats2half2_rn(cA0 * s, cA1 * s);
                *(__half2*)(tgt + rowB)     = __floats2half2_rn(cA2 * s, cA3 * s);
                *(__half2*)(tgt + rowA + 8) = __floats2half2_rn(cB0 * s, cB1 * s);
                *(__half2*)(tgt + rowB + 8) = __floats2half2_rn(cB2 * s, cB3 * s);
            } else {
                const int cc = jc + 2 * tig;
                const int v0 = gn0 + 2 * tig;
                vt[(v0    ) * 72 + ra] = __float2half(cA0 + uvs[ra * 68 + cc]);
                vt[(v0 + 1) * 72 + ra] = __float2half(cA1 + uvs[ra * 68 + cc + 1]);
                vt[(v0    ) * 72 + rb] = __float2half(cA2 + uvs[rb * 68 + cc]);
                vt[(v0 + 1) * 72 + rb] = __float2half(cA3 + uvs[rb * 68 + cc + 1]);
                vt[(v0 + 8) * 72 + ra] = __float2half(cB0 + uvs[ra * 68 + cc + 8]);
                vt[(v0 + 9) * 72 + ra] = __float2half(cB1 + uvs[ra * 68 + cc + 9]);
                vt[(v0 + 8) * 72 + rb] = __float2half(cB2 + uvs[rb * 68 + cc + 8]);
                vt[(v0 + 9) * 72 + rb] = __float2half(cB3 + uvs[rb * 68 + cc + 9]);
            }
        }
        __syncthreads();   // before wt restage / before vt readout
    }

    // ---- coalesced Veh write from vt: full 64-half rows (8 x uint4) ----
    {
        const int v  = t;             // 0..255
        const int h  = v >> 6;
        const int vr = v & 63;
        __half* dst = g_Veh + ((size_t)(b * 4 + h) * 64 + vr) * SEQ + lr0;
        #pragma unroll
        for (int c = 0; c < 8; ++c) {
            uint4 pk = *(const uint4*)(vt + v * 72 + c * 8);   // 8 halves per uint4
            *(uint4*)(dst + c * 8) = pk;
        }
    }
}

// ---------------------------------------------------------------------------
// Kernel 2 (v10): attention (identical to R14 passing version)
// ---------------------------------------------------------------------------
#define ATT_SMEM_BYTES ((TQ*KH + 2*64*KH + 2*64*VH + 2*TQ*VH) * 2 + 128*4 + 32*4 + 128*4)

__global__ void __launch_bounds__(256, 3) attn2_kernel(float* __restrict__ attn_out) {
    extern __shared__ __half smh[];
    __half* qs  = smh;                       // 32 x 136
    __half* ks  = qs + TQ * KH;              // 2 x 64 x 136
    __half* vsh = ks + 2 * 64 * KH;          // 2 x 64 x 72
    __half* psh = vsh + 2 * 64 * VH;         // 2 x 32 x 72
    float*  red = (float*)(psh + 2 * TQ * VH);   // 8 x 16
    float*  inv = red + 128;                     // 32
    unsigned* msb = (unsigned*)(inv + 32);       // 2 x 64

    const unsigned smbase = (unsigned)__cvta_generic_to_shared(smh);
    const unsigned ks_a = smbase + (unsigned)(TQ * KH) * 2;
    const unsigned vs_a = ks_a + (unsigned)(2 * 64 * KH) * 2;
    const unsigned ps_a = vs_a + (unsigned)(2 * 64 * VH) * 2;

    const int t    = threadIdx.x;
    const int w    = t >> 5;
    const int lane = t & 31;
    const int g    = lane >> 2;
    const int tig  = lane & 3;
    const int qh   = w >> 2;
    const int np   = w & 3;
    const int n0   = np * 16;
    const int ra   = qh * 16 + g;
    const int rb   = ra + 8;

    const int lb  = lane & 7;
    const int r8  = ((lane >> 4) & 1) * 8;
    const int c8  = ((lane >> 3) & 1) * 8;
    const unsigned koff = (unsigned)(((n0 + r8 + lb) * KH + c8) * 2);
    const unsigned voff = (unsigned)(((n0 + r8 + lb) * VH + c8) * 2);
    const unsigned poff = (unsigned)((qh * 16 + (lane & 15)) * VH * 2 + ((lane >> 4) & 1) * 16);

    const int bh = blockIdx.x >> 6;
    const int qt = blockIdx.x & 63;
    const int b  = bh >> 2;
    const int h  = bh & 3;
    const int q0 = qt * TQ;

    const __half* Qg = g_Qeh + ((size_t)bh * SEQ + q0) * 128;
    const __half* Kg = g_Keh + (size_t)bh * SEQ * 128;
    const __half* Vg = g_Veh + (size_t)bh * 64 * SEQ;
    const unsigned* Mb = g_maskb + ((size_t)b * SEQ + q0) * 64;
    __half* php = g_ph + ((size_t)bh * SEQ + q0) * SEQ;
    float* ao = attn_out + ((size_t)bh * SEQ + q0) * SEQ;

    for (int i = t; i < TQ * 16; i += 256) {
        int r = i >> 4, cc = (i & 15) * 8;
        cp_async16(qs + r * KH + cc, Qg + (size_t)r * 128 + cc);
    }
    for (int i = t; i < 64 * 16; i += 256) {
        int r = i >> 4, cc = (i & 15) * 8;
        cp_async16(ks + r * KH + cc, Kg + (size_t)r * 128 + cc);
    }
    for (int i = t; i < 64 * 8; i += 256) {
        int r = i >> 3, cc = (i & 7) * 8;
        cp_async16(vsh + r * VH + cc, Vg + (size_t)r * SEQ + cc);
    }
    if (t < 2 * TQ)
        cp_async4(msb + t, Mb + (size_t)(t >> 1) * 64 + (t & 1));
    CP_COMMIT();
    CP_WAIT(0);
    __syncthreads();

    unsigned a[8][4];
    #pragma unroll
    for (int kk = 0; kk < 8; ++kk) {
        a[kk][0] = *(const unsigned*)(qs + ra * KH + kk * 16 + 2 * tig);
        a[kk][1] = *(const unsigned*)(qs + rb * KH + kk * 16 + 2 * tig);
        a[kk][2] = *(const unsigned*)(qs + ra * KH + kk * 16 + 2 * tig + 8);
        a[kk][3] = *(const unsigned*)(qs + rb * KH + kk * 16 + 2 * tig + 8);
    }

    float cxA0 = 0.f, cxA1 = 0.f, cxA2 = 0.f, cxA3 = 0.f;
    float cxB0 = 0.f, cxB1 = 0.f, cxB2 = 0.f, cxB3 = 0.f;
    float sl0 = 0.f, sl1 = 0.f;
    const int colA = n0 + 2 * tig;
    const int colB = colA + 8;
    const int mw   = n0 >> 5;

    for (int tile = 0; tile < NT; ++tile) {
        const int buf = tile & 1;
        const unsigned kbuf_a = ks_a + (unsigned)(buf * 64 * KH) * 2;
        const unsigned vbuf_a = vs_a + (unsigned)(buf * 64 * VH) * 2;
        const unsigned pbuf_a = ps_a + (unsigned)(buf * TQ * VH) * 2;
        const unsigned* mb = msb + buf * 2 * TQ;
        const int k0 = tile * 64;

        float cA0 = 0.f, cA1 = 0.f, cA2 = 0.f, cA3 = 0.f;
        float cB0 = 0.f, cB1 = 0.f, cB2 = 0.f, cB3 = 0.f;
        #pragma unroll
        for (int kk = 0; kk < 8; ++kk) {
            unsigned b0, b1, b2, b3;
            ldsm_x4(b0, b1, b2, b3, kbuf_a + koff + kk * 32);
            mma_f16_k16(cA0, cA1, cA2, cA3, a[kk][0], a[kk][1], a[kk][2], a[kk][3], b0, b1);
            mma_f16_k16(cB0, cB1, cB2, cB3, a[kk][0], a[kk][1], a[kk][2], a[kk][3], b2, b3);
        }

        unsigned w0 = mb[ra * 2 + mw];
        unsigned w1 = mb[rb * 2 + mw];
        float mA00 = ((w0 >> (colA & 31)) & 1u)       ? -100.f : cA0;
        float mA01 = ((w0 >> ((colA + 1) & 31)) & 1u) ? -100.f : cA1;
        float mA10 = ((w1 >> (colA & 31)) & 1u)       ? -100.f : cA2;
        float mA11 = ((w1 >> ((colA + 1) & 31)) & 1u) ? -100.f : cA3;
        float mB00 = ((w0 >> (colB & 31)) & 1u)       ? -100.f : cB0;
        float mB01 = ((w0 >> ((colB + 1) & 31)) & 1u) ? -100.f : cB1;
        float mB10 = ((w1 >> (colB & 31)) & 1u)       ? -100.f : cB2;
        float mB11 = ((w1 >> ((colB + 1) & 31)) & 1u) ? -100.f : cB3;
        __half2 hA0 = h2exp2_approx(__floats2half2_rn(mA00, mA01));
        __half2 hA1 = h2exp2_approx(__floats2half2_rn(mA10, mA11));
        __half2 hB0 = h2exp2_approx(__floats2half2_rn(mB00, mB01));
        __half2 hB1 = h2exp2_approx(__floats2half2_rn(mB10, mB11));
        float2 fA0 = __half22float2(hA0);
        float2 fA1 = __half22float2(hA1);
        float2 fB0 = __half22float2(hB0);
        float2 fB1 = __half22float2(hB1);
        sl0 += fA0.x + fA0.y + fB0.x + fB0.y;
        sl1 += fA1.x + fA1.y + fB1.x + fB1.y;

        *(__half2*)(php + (size_t)ra * SEQ + k0 + colA) = hA0;
        *(__half2*)(php + (size_t)rb * SEQ + k0 + colA) = hA1;
        *(__half2*)(php + (size_t)ra * SEQ + k0 + colB) = hB0;
        *(__half2*)(php + (size_t)rb * SEQ + k0 + colB) = hB1;
        __half* pw = psh + buf * TQ * VH;
        *(__half2*)(pw + ra * VH + colA) = hA0;
        *(__half2*)(pw + rb * VH + colA) = hA1;
        *(__half2*)(pw + ra * VH + colB) = hB0;
        *(__half2*)(pw + rb * VH + colB) = hB1;
        __syncthreads();

        if (tile + 1 < NT) {
            const int nb = buf ^ 1;
            const int nk0 = k0 + 64;
            for (int i = t; i < 64 * 16; i += 256) {
                int r = i >> 4, cc = (i & 15) * 8;
                cp_async16(ks + nb * 64 * KH + r * KH + cc,
                           Kg + (size_t)(nk0 + r) * 128 + cc);
            }
            for (int i = t; i < 64 * 8; i += 256) {
                int r = i >> 3, cc = (i & 7) * 8;
                cp_async16(vsh + nb * 64 * VH + r * VH + cc,
                           Vg + (size_t)r * SEQ + nk0 + cc);
            }
            if (t < 2 * TQ)
                cp_async4(msb + nb * 2 * TQ + t,
                          Mb + (size_t)(t >> 1) * 64 + (nk0 >> 5) + (t & 1));
            CP_COMMIT();
        }

        #pragma unroll
        for (int kk = 0; kk < 4; ++kk) {
            unsigned p0, p1, p2, p3, v0, v1, v2, v3;
            ldsm_x4(p0, p1, p2, p3, pbuf_a + poff + kk * 32);
            ldsm_x4(v0, v1, v2, v3, vbuf_a + voff + kk * 32);
            mma_f16_k16(cxA0, cxA1, cxA2, cxA3, p0, p1, p2, p3, v0, v1);
            mma_f16_k16(cxB0, cxB1, cxB2, cxB3, p0, p1, p2, p3, v2, v3);
        }

        CP_WAIT(0);
        __syncthreads();
    }

    sl0 += __shfl_xor_sync(0xffffffffu, sl0, 1);
    sl0 += __shfl_xor_sync(0xffffffffu, sl0, 2);
    sl1 += __shfl_xor_sync(0xffffffffu, sl1, 1);
    sl1 += __shfl_xor_sync(0xffffffffu, sl1, 2);
    if (tig == 0) {
        red[w * 16 + g]     = sl0;
        red[w * 16 + 8 + g] = sl1;
    }
    __syncthreads();
    if (t < TQ) {
        int qh_r = t >> 4;
        int rr   = t & 15;
        float s = 0.f;
        #pragma unroll
        for (int ww = 0; ww < 4; ++ww) s += red[(qh_r * 4 + ww) * 16 + rr];
        inv[t] = 1.f / s;
    }
    __syncthreads();

    {
        float iv0 = inv[ra];
        float iv1 = inv[rb];
        size_t r0g = (size_t)b * SEQ + q0;
        *(float2*)(g_ctx + (r0g + ra) * 256 + h * 64 + colA) = make_float2(cxA0 * iv0, cxA1 * iv0);
        *(float2*)(g_ctx + (r0g + rb) * 256 + h * 64 + colA) = make_float2(cxA2 * iv1, cxA3 * iv1);
        *(float2*)(g_ctx + (r0g + ra) * 256 + h * 64 + colB) = make_float2(cxB0 * iv0, cxB1 * iv0);
        *(float2*)(g_ctx + (r0g + rb) * 256 + h * 64 + colB) = make_float2(cxB2 * iv1, cxB3 * iv1);
    }

    for (int r = 0; r < TQ; ++r) {
        float iv = inv[r];
        uint4 pk = *((const uint4*)(php + (size_t)r * SEQ) + t);
        float2 q0f = __half22float2(*(__half2*)&pk.x);
        float2 q1f = __half22float2(*(__half2*)&pk.y);
        float2 q2f = __half22float2(*(__half2*)&pk.z);
        float2 q3f = __half22float2(*(__half2*)&pk.w);
        float4 o0 = make_float4(q0f.x * iv, q0f.y * iv, q1f.x * iv, q1f.y * iv);
        float4 o1 = make_float4(q2f.x * iv, q2f.y * iv, q3f.x * iv, q3f.y * iv);
        float4* dst = (float4*)(ao + (size_t)r * SEQ) + t * 2;
        dst[0] = o0;
        dst[1] = o1;
    }
}

// ---------------------------------------------------------------------------
// Kernel 3 (v2): fc + LN1 + FFN + LN2 (identical to R14 passing version)
// ---------------------------------------------------------------------------
#define POST_SMEM_BYTES ((32*260 + 2*32*68) * 4)

__global__ void __launch_bounds__(256, 4) post_kernel(
    const float* __restrict__ x, const float* __restrict__ fcw,
    const float* __restrict__ ln1g, const float* __restrict__ ln1b,
    const float* __restrict__ f1, const float* __restrict__ f2,
    const float* __restrict__ ln2g, const float* __restrict__ ln2b,
    float* __restrict__ res) {
    extern __shared__ float sm[];
    float* cs = sm;               // 32 x 260
    float* hs = cs + 32 * 260;    // 32 x 68
    float* es = hs + 32 * 68;     // 32 x 68

    const int t = threadIdx.x;
    const int row0 = blockIdx.x * 32;

    for (int i = t; i < 32 * 64; i += 256) {
        int r = i >> 6, c = (i & 63) * 4;
        *(float4*)(cs + r * 260 + c) = *(const float4*)(g_ctx + (size_t)(row0 + r) * 256 + c);
    }
    for (int i = t; i < 32 * 16; i += 256) {
        int r = i >> 4, c = (i & 15) * 4;
        *(float4*)(hs + r * 68 + c) = *(const float4*)(x + (size_t)(row0 + r) * DM + c);
    }
    __syncthreads();

    const int rg = t >> 5;
    const int cg = t & 31;
    const int c0 = cg * 2;

    float acc[4][2];
    #pragma unroll
    for (int i = 0; i < 4; ++i) { acc[i][0] = 0.f; acc[i][1] = 0.f; }
    for (int k = 0; k < 256; ++k) {
        float2 bb = __ldg((const float2*)(fcw + k * 64 + c0));
        #pragma unroll
        for (int i = 0; i < 4; ++i) {
            float av = cs[(rg * 4 + i) * 260 + k];
            acc[i][0] += av * bb.x;
            acc[i][1] += av * bb.y;
        }
    }

    float g0 = __ldg(ln1g + c0), g1 = __ldg(ln1g + c0 + 1);
    float b0 = __ldg(ln1b + c0), b1 = __ldg(ln1b + c0 + 1);
    #pragma unroll
    for (int i = 0; i < 4; ++i) {
        float y0 = acc[i][0] + hs[(rg * 4 + i) * 68 + c0];
        float y1 = acc[i][1] + hs[(rg * 4 + i) * 68 + c0 + 1];
        float s = y0 + y1;
        float q = y0 * y0 + y1 * y1;
        #pragma unroll
        for (int o = 16; o; o >>= 1) {
            s += __shfl_xor_sync(0xffffffffu, s, o);
            q += __shfl_xor_sync(0xffffffffu, q, o);
        }
        float mu = s * (1.f / 64.f);
        float var = q * (1.f / 64.f) - mu * mu;
        float rs = rsqrtf(var + 1e-5f);
        *(float2*)(es + (rg * 4 + i) * 68 + c0) =
            make_float2((y0 - mu) * rs * g0 + b0, (y1 - mu) * rs * g1 + b1);
    }
    __syncthreads();

    float h4[4][2];
    #pragma unroll
    for (int i = 0; i < 4; ++i) { h4[i][0] = 0.f; h4[i][1] = 0.f; }
    for (int k = 0; k < 64; ++k) {
        float2 bb = __ldg((const float2*)(f1 + k * 64 + c0));
        #pragma unroll
        for (int i = 0; i < 4; ++i) {
            float av = es[(rg * 4 + i) * 68 + k];
            h4[i][0] += av * bb.x;
            h4[i][1] += av * bb.y;
        }
    }
    __syncthreads();
    #pragma unroll
    for (int i = 0; i < 4; ++i)
        *(float2*)(hs + (rg * 4 + i) * 68 + c0) =
            make_float2(fmaxf(h4[i][0], 0.f), fmaxf(h4[i][1], 0.f));
    __syncthreads();

    float fa[4][2];
    #pragma unroll
    for (int i = 0; i < 4; ++i) { fa[i][0] = 0.f; fa[i][1] = 0.f; }
    for (int k = 0; k < 64; ++k) {
        float2 bb = __ldg((const float2*)(f2 + k * 64 + c0));
        #pragma unroll
        for (int i = 0; i < 4; ++i) {
            float av = hs[(rg * 4 + i) * 68 + k];
            fa[i][0] += av * bb.x;
            fa[i][1] += av * bb.y;
        }
    }
    float g20 = __ldg(ln2g + c0), g21 = __ldg(ln2g + c0 + 1);
    float b20 = __ldg(ln2b + c0), b21 = __ldg(ln2b + c0 + 1);
    #pragma unroll
    for (int i = 0; i < 4; ++i) {
        float y0 = fa[i][0] + es[(rg * 4 + i) * 68 + c0];
        float y1 = fa[i][1] + es[(rg * 4 + i) * 68 + c0 + 1];
        float s = y0 + y1;
        float q = y0 * y0 + y1 * y1;
        #pragma unroll
        for (int o = 16; o; o >>= 1) {
            s += __shfl_xor_sync(0xffffffffu, s, o);
            q += __shfl_xor_sync(0xffffffffu, q, o);
        }
        float mu = s * (1.f / 64.f);
        float var = q * (1.f / 64.f) - mu * mu;
        float rs = rsqrtf(var + 1e-5f);
        *(float2*)(res + (size_t)(row0 + rg * 4 + i) * 64 + c0) =
            make_float2((y0 - mu) * rs * g20 + b20, (y1 - mu) * rs * g21 + b21);
    }
}

// ---------------------------------------------------------------------------
// Launch
// ---------------------------------------------------------------------------
extern "C" void kernel_launch(void* const* d_in, const int* in_sizes, int n_in,
                              void* d_out, int out_size) {
    const float* x    = (const float*)d_in[0];
    const void*  mask = d_in[1];
    const float* u    = (const float*)d_in[2];
    const float* wq   = (const float*)d_in[3];
    const float* wk   = (const float*)d_in[4];
    const float* wv   = (const float*)d_in[5];
    const float* uqw  = (const float*)d_in[6];
    const float* ukw  = (const float*)d_in[7];
    const float* uvw  = (const float*)d_in[8];
    const float* sq1  = (const float*)d_in[9];
    const float* sq2  = (const float*)d_in[10];
    const float* sk1  = (const float*)d_in[11];
    const float* sk2  = (const float*)d_in[12];
    const float* sv1  = (const float*)d_in[13];
    const float* sv2  = (const float*)d_in[14];
    const float* fcw  = (const float*)d_in[15];
    const float* ln1g = (const float*)d_in[16];
    const float* ln1b = (const float*)d_in[17];
    const float* ffn1 = (const float*)d_in[18];
    const float* ffn2 = (const float*)d_in[19];
    const float* ln2g = (const float*)d_in[20];
    const float* ln2b = (const float*)d_in[21];

    float* res  = (float*)d_out;
    float* attn = res + (size_t)NB * SEQ * DM;

    cudaFuncSetAttribute(proj_kernel,  cudaFuncAttributeMaxDynamicSharedMemorySize, PROJ_SMEM_BYTES);
    cudaFuncSetAttribute(attn2_kernel, cudaFuncAttributeMaxDynamicSharedMemorySize, ATT_SMEM_BYTES);
    cudaFuncSetAttribute(post_kernel,  cudaFuncAttributeMaxDynamicSharedMemorySize, POST_SMEM_BYTES);

    detect_mask_kernel<<<1, 32>>>((const unsigned char*)mask);
    convert_mask_kernel<<<(NB * SEQ * SEQ) / 256, 256>>>(mask);
    gates_kernel<<<NB, 32>>>(u, sq1, sq2, sk1, sk2, sv1, sv2);
    proj_kernel<<<(NB * SEQ) / 64, 256, PROJ_SMEM_BYTES>>>(x, wq, wk, wv, uqw, ukw, uvw);
    attn2_kernel<<<NB * NH * (SEQ / TQ), 256, ATT_SMEM_BYTES>>>(attn);
    post_kernel<<<(NB * SEQ) / 32, 256, POST_SMEM_BYTES>>>(x, fcw, ln1g, ln1b, ffn1, ffn2,
                                                           ln2g, ln2b, res);
}

// round 17
// speedup vs baseline: 1.2925x; 1.0075x over previous
#include <cuda_runtime.h>
#include <cuda_fp16.h>
#include <cstdint>
#include <cstddef>

// ---------------------------------------------------------------------------
// Problem constants
// ---------------------------------------------------------------------------
#define NB   8
#define NH   4
#define SEQ  2048
#define DM   64

#define TQA  64          // q rows per attention CTA
#define KH   136
#define VH   72
#define NT   (SEQ / 64)

#define LOG2E 1.4426950408889634f

// ---------------------------------------------------------------------------
// Static device scratch
// ---------------------------------------------------------------------------
__device__ float    g_gates[3 * NB];
__device__ int      g_mask_mode;
__device__ __half   g_Qeh[(size_t)NB * NH * SEQ * 128];    // fp16, scaled 0.125*log2e
__device__ __half   g_Keh[(size_t)NB * NH * SEQ * 128];
__device__ __half   g_Veh[(size_t)NB * NH * 64 * SEQ];     // transposed [v][k] fp16
__device__ float    g_ctx[(size_t)NB * SEQ * 256];
__device__ unsigned g_maskb[(size_t)NB * SEQ * 64];
__device__ __half   g_ph[(size_t)NB * NH * SEQ * SEQ];     // fp16 p scratch

// ---------------------------------------------------------------------------
// Helpers
// ---------------------------------------------------------------------------
__device__ __forceinline__ void mma_f16_k16(float& c0, float& c1, float& c2, float& c3,
                                            unsigned a0, unsigned a1, unsigned a2, unsigned a3,
                                            unsigned b0, unsigned b1) {
    asm volatile(
        "mma.sync.aligned.m16n8k16.row.col.f32.f16.f16.f32 "
        "{%0,%1,%2,%3},{%4,%5,%6,%7},{%8,%9},{%0,%1,%2,%3};"
        : "+f"(c0), "+f"(c1), "+f"(c2), "+f"(c3)
        : "r"(a0), "r"(a1), "r"(a2), "r"(a3), "r"(b0), "r"(b1));
}

__device__ __forceinline__ void ldsm_x4(unsigned& r0, unsigned& r1, unsigned& r2, unsigned& r3,
                                        unsigned addr) {
    asm volatile("ldmatrix.sync.aligned.m8n8.x4.shared.b16 {%0,%1,%2,%3}, [%4];"
                 : "=r"(r0), "=r"(r1), "=r"(r2), "=r"(r3) : "r"(addr));
}

__device__ __forceinline__ __half2 h2exp2_approx(__half2 x) {
    __half2 r;
    asm("ex2.approx.f16x2 %0, %1;" : "=r"(*(unsigned*)&r) : "r"(*(unsigned*)&x));
    return r;
}

__device__ __forceinline__ unsigned h2_as_u(__half2 v) {
    return *(unsigned*)&v;
}

__device__ __forceinline__ void cp_async16(void* smem, const void* gmem) {
    unsigned sa = (unsigned)__cvta_generic_to_shared(smem);
    asm volatile("cp.async.cg.shared.global [%0], [%1], 16;\n" :: "r"(sa), "l"(gmem));
}
__device__ __forceinline__ void cp_async4(void* smem, const void* gmem) {
    unsigned sa = (unsigned)__cvta_generic_to_shared(smem);
    asm volatile("cp.async.ca.shared.global [%0], [%1], 4;\n" :: "r"(sa), "l"(gmem));
}
#define CP_COMMIT() asm volatile("cp.async.commit_group;\n")
#define CP_WAIT(n)  asm volatile("cp.async.wait_group %0;\n" :: "n"(n))

// ---------------------------------------------------------------------------
// Kernel D: detect mask encoding
// ---------------------------------------------------------------------------
__global__ void detect_mask_kernel(const unsigned char* __restrict__ m) {
    int found = 0;
    for (int i = threadIdx.x; i < 1024; i += 32)
        if (m[i * 4 + 1] | m[i * 4 + 2] | m[i * 4 + 3]) found = 1;
    for (int o = 16; o; o >>= 1)
        found |= __shfl_xor_sync(0xffffffffu, found, o);
    if (threadIdx.x == 0) g_mask_mode = found ? 0 : 1;
}

// ---------------------------------------------------------------------------
// Kernel M: bit-pack the mask
// ---------------------------------------------------------------------------
__global__ void __launch_bounds__(256) convert_mask_kernel(const void* __restrict__ mask) {
    unsigned gid = blockIdx.x * 256 + threadIdx.x;
    unsigned nz;
    if (g_mask_mode) nz = (((const int*)mask)[gid] != 0) ? 1u : 0u;
    else             nz = (((const unsigned char*)mask)[gid] != 0) ? 1u : 0u;
    unsigned bits = __ballot_sync(0xffffffffu, nz);
    if ((threadIdx.x & 31) == 0) g_maskb[gid >> 5] = bits;
}

// ---------------------------------------------------------------------------
// Kernel 0: scalar gates
// ---------------------------------------------------------------------------
__global__ void gates_kernel(const float* __restrict__ u,
                             const float* __restrict__ sq1, const float* __restrict__ sq2,
                             const float* __restrict__ sk1, const float* __restrict__ sk2,
                             const float* __restrict__ sv1, const float* __restrict__ sv2) {
    const int b = blockIdx.x;
    const int lane = threadIdx.x;
    float hq = 0.f, hk = 0.f, hv = 0.f;
    for (int d = 0; d < DM; ++d) {
        float uv = u[b * DM + d];
        hq += uv * sq1[d * 32 + lane];
        hk += uv * sk1[d * 32 + lane];
        hv += uv * sv1[d * 32 + lane];
    }
    hq = fmaxf(hq, 0.f) * sq2[lane];
    hk = fmaxf(hk, 0.f) * sk2[lane];
    hv = fmaxf(hv, 0.f) * sv2[lane];
    for (int off = 16; off; off >>= 1) {
        hq += __shfl_xor_sync(0xffffffffu, hq, off);
        hk += __shfl_xor_sync(0xffffffffu, hk, off);
        hv += __shfl_xor_sync(0xffffffffu, hv, off);
    }
    if (lane == 0) {
        g_gates[b]      = hq;
        g_gates[8 + b]  = hk;
        g_gates[16 + b] = hv;
    }
}

// ---------------------------------------------------------------------------
// Kernel 1 (v4): tensor-core projections (identical to passing R16)
// ---------------------------------------------------------------------------
#define PROJ_SMEM_BYTES ((64*72 + 256*72 + 256*72) * 2 + (64*68) * 4)

__global__ void __launch_bounds__(256, 2) proj_kernel(
    const float* __restrict__ x,
    const float* __restrict__ wq, const float* __restrict__ wk, const float* __restrict__ wv,
    const float* __restrict__ uqw, const float* __restrict__ ukw, const float* __restrict__ uvw) {
    extern __shared__ __half smh[];
    __half* xh  = smh;                 // 64 x 72
    __half* wt  = xh + 64 * 72;        // 256 x 72
    __half* vt  = wt + 256 * 72;       // 256 x 72
    float*  uvs = (float*)(vt + 256 * 72);  // 64 x 68

    const unsigned smbase = (unsigned)__cvta_generic_to_shared(smh);
    const unsigned xh_a = smbase;
    const unsigned wt_a = smbase + (unsigned)(64 * 72) * 2;

    const int t    = threadIdx.x;
    const int w    = t >> 5;
    const int lane = t & 31;
    const int g    = lane >> 2;
    const int tig  = lane & 3;
    const int wr   = w >> 1;
    const int wc   = w & 1;
    const int ra   = wr * 16 + g;
    const int rb   = ra + 8;

    const int lb = lane & 7;
    const int r8 = ((lane >> 4) & 1) * 8;
    const int c8 = ((lane >> 3) & 1) * 8;

    const int row0 = blockIdx.x * 64;
    const int b    = row0 >> 11;
    const int lr0  = row0 & (SEQ - 1);

    for (int i = t; i < 64 * 16; i += 256) {
        int r = i >> 4, c4 = (i & 15) * 4;
        float4 v = *(const float4*)(x + (size_t)(row0 + r) * DM + c4);
        __half2 h0 = __floats2half2_rn(v.x, v.y);
        __half2 h1 = __floats2half2_rn(v.z, v.w);
        *(__half2*)(xh + r * 72 + c4)     = h0;
        *(__half2*)(xh + r * 72 + c4 + 2) = h1;
    }
    for (int i = t; i < 3 * 64 * 64; i += 256) {
        int mat = i >> 12;
        int j   = i & 4095;
        int k   = j >> 6;
        int n   = j & 63;
        const float* wsrc = (mat == 0) ? uqw : (mat == 1) ? ukw : uvw;
        wt[(mat * 64 + n) * 72 + k] = __float2half(wsrc[k * 64 + n]);
    }
    __syncthreads();

    unsigned a[4][4];
    {
        unsigned aoff = xh_a + (unsigned)((wr * 16 + (lane & 15)) * 72) * 2
                             + (unsigned)(((lane >> 4) & 1) * 16);
        #pragma unroll
        for (int kk = 0; kk < 4; ++kk)
            ldsm_x4(a[kk][0], a[kk][1], a[kk][2], a[kk][3], aoff + kk * 32);
    }

    const float gq = g_gates[b] * 0.125f * LOG2E;
    const float gk = g_gates[8 + b];
    const float gv = g_gates[16 + b];

    for (int grp = 0; grp < 6; ++grp) {
        const int gn0 = wc * 96 + grp * 16;
        float cA0 = 0.f, cA1 = 0.f, cA2 = 0.f, cA3 = 0.f;
        float cB0 = 0.f, cB1 = 0.f, cB2 = 0.f, cB3 = 0.f;
        unsigned boff = wt_a + (unsigned)(((gn0 + r8 + lb) * 72 + c8) * 2);
        #pragma unroll
        for (int kk = 0; kk < 4; ++kk) {
            unsigned b0, b1, b2, b3;
            ldsm_x4(b0, b1, b2, b3, boff + kk * 32);
            mma_f16_k16(cA0, cA1, cA2, cA3, a[kk][0], a[kk][1], a[kk][2], a[kk][3], b0, b1);
            mma_f16_k16(cB0, cB1, cB2, cB3, a[kk][0], a[kk][1], a[kk][2], a[kk][3], b2, b3);
        }
        const int mat = gn0 >> 6;
        const int jc  = gn0 & 63;
        if (mat < 2) {
            float s = (mat == 0) ? gq : gk;
            __half* tgt = (mat == 0) ? g_Qeh : g_Keh;
            __half2 hA0 = __floats2half2_rn(cA0 * s, cA1 * s);
            __half2 hA1 = __floats2half2_rn(cA2 * s, cA3 * s);
            __half2 hB0 = __floats2half2_rn(cB0 * s, cB1 * s);
            __half2 hB1 = __floats2half2_rn(cB2 * s, cB3 * s);
            #pragma unroll
            for (int h = 0; h < 4; ++h) {
                size_t rowA = ((size_t)(b * 4 + h) * SEQ + lr0 + ra) * 128 + 64 + jc + 2 * tig;
                size_t rowB = ((size_t)(b * 4 + h) * SEQ + lr0 + rb) * 128 + 64 + jc + 2 * tig;
                *(__half2*)(tgt + rowA)     = hA0;
                *(__half2*)(tgt + rowB)     = hA1;
                *(__half2*)(tgt + rowA + 8) = hB0;
                *(__half2*)(tgt + rowB + 8) = hB1;
            }
        } else {
            int cc = jc + 2 * tig;
            *(float2*)(uvs + ra * 68 + cc)     = make_float2(cA0 * gv, cA1 * gv);
            *(float2*)(uvs + rb * 68 + cc)     = make_float2(cA2 * gv, cA3 * gv);
            *(float2*)(uvs + ra * 68 + cc + 8) = make_float2(cB0 * gv, cB1 * gv);
            *(float2*)(uvs + rb * 68 + cc + 8) = make_float2(cB2 * gv, cB3 * gv);
        }
    }
    __syncthreads();

    for (int m = 0; m < 3; ++m) {
        const float* wsrc = (m == 0) ? wq : (m == 1) ? wk : wv;
        for (int i = t; i < 64 * 256; i += 256) {
            int k = i >> 8;
            int n = i & 255;
            wt[n * 72 + k] = __float2half(wsrc[k * 256 + n]);
        }
        __syncthreads();

        for (int grp = 0; grp < 8; ++grp) {
            const int gn0 = wc * 128 + grp * 16;
            float cA0 = 0.f, cA1 = 0.f, cA2 = 0.f, cA3 = 0.f;
            float cB0 = 0.f, cB1 = 0.f, cB2 = 0.f, cB3 = 0.f;
            unsigned boff = wt_a + (unsigned)(((gn0 + r8 + lb) * 72 + c8) * 2);
            #pragma unroll
            for (int kk = 0; kk < 4; ++kk) {
                unsigned b0, b1, b2, b3;
                ldsm_x4(b0, b1, b2, b3, boff + kk * 32);
                mma_f16_k16(cA0, cA1, cA2, cA3, a[kk][0], a[kk][1], a[kk][2], a[kk][3], b0, b1);
                mma_f16_k16(cB0, cB1, cB2, cB3, a[kk][0], a[kk][1], a[kk][2], a[kk][3], b2, b3);
            }
            const int h  = gn0 >> 6;
            const int jc = gn0 & 63;
            if (m < 2) {
                float s = (m == 0) ? (0.125f * LOG2E) : 1.0f;
                __half* tgt = (m == 0) ? g_Qeh : g_Keh;
                size_t rowA = ((size_t)(b * 4 + h) * SEQ + lr0 + ra) * 128 + jc + 2 * tig;
                size_t rowB = ((size_t)(b * 4 + h) * SEQ + lr0 + rb) * 128 + jc + 2 * tig;
                *(__half2*)(tgt + rowA)     = __floats2half2_rn(cA0 * s, cA1 * s);
                *(__half2*)(tgt + rowB)     = __floats2half2_rn(cA2 * s, cA3 * s);
                *(__half2*)(tgt + rowA + 8) = __floats2half2_rn(cB0 * s, cB1 * s);
                *(__half2*)(tgt + rowB + 8) = __floats2half2_rn(cB2 * s, cB3 * s);
            } else {
                const int cc = jc + 2 * tig;
                const int v0 = gn0 + 2 * tig;
                vt[(v0    ) * 72 + ra] = __float2half(cA0 + uvs[ra * 68 + cc]);
                vt[(v0 + 1) * 72 + ra] = __float2half(cA1 + uvs[ra * 68 + cc + 1]);
                vt[(v0    ) * 72 + rb] = __float2half(cA2 + uvs[rb * 68 + cc]);
                vt[(v0 + 1) * 72 + rb] = __float2half(cA3 + uvs[rb * 68 + cc + 1]);
                vt[(v0 + 8) * 72 + ra] = __float2half(cB0 + uvs[ra * 68 + cc + 8]);
                vt[(v0 + 9) * 72 + ra] = __float2half(cB1 + uvs[ra * 68 + cc + 9]);
                vt[(v0 + 8) * 72 + rb] = __float2half(cB2 + uvs[rb * 68 + cc + 8]);
                vt[(v0 + 9) * 72 + rb] = __float2half(cB3 + uvs[rb * 68 + cc + 9]);
            }
        }
        __syncthreads();
    }

    {
        const int v  = t;
        const int h  = v >> 6;
        const int vr = v & 63;
        __half* dst = g_Veh + ((size_t)(b * 4 + h) * 64 + vr) * SEQ + lr0;
        #pragma unroll
        for (int c = 0; c < 8; ++c) {
            uint4 pk = *(const uint4*)(vt + v * 72 + c * 8);
            *(uint4*)(dst + c * 8) = pk;
        }
    }
}

// ---------------------------------------------------------------------------
// Kernel 2 (v11): attention, TQ=64 / 512 threads / 16 warps, 2 CTAs/SM.
// Warp = (qq = w>>2: 16-row quarter, np = w&3: 16-col group). Same per-warp
// shape as v10 (low regs); CTA count halves => K/V L2 traffic halves.
// smem(halves): qs 64x136 | ks 2x64x136 | vsh 2x64x72 | psh 2x64x72
//   + red 256f | inv 64f | msb 2x128 u32  = ~91.4 KB
// ---------------------------------------------------------------------------
#define ATT_SMEM_BYTES ((TQA*KH + 2*64*KH + 2*64*VH + 2*TQA*VH) * 2 + 256*4 + 64*4 + 256*4)

__global__ void __launch_bounds__(512, 2) attn2_kernel(float* __restrict__ attn_out) {
    extern __shared__ __half smh[];
    __half* qs  = smh;                       // 64 x 136
    __half* ks  = qs + TQA * KH;             // 2 x 64 x 136
    __half* vsh = ks + 2 * 64 * KH;          // 2 x 64 x 72
    __half* psh = vsh + 2 * 64 * VH;         // 2 x 64 x 72
    float*  red = (float*)(psh + 2 * TQA * VH);  // 16 x 16
    float*  inv = red + 256;                     // 64
    unsigned* msb = (unsigned*)(inv + 64);       // 2 x 128

    const unsigned smbase = (unsigned)__cvta_generic_to_shared(smh);
    const unsigned ks_a = smbase + (unsigned)(TQA * KH) * 2;
    const unsigned vs_a = ks_a + (unsigned)(2 * 64 * KH) * 2;
    const unsigned ps_a = vs_a + (unsigned)(2 * 64 * VH) * 2;

    const int t    = threadIdx.x;
    const int w    = t >> 5;
    const int lane = t & 31;
    const int g    = lane >> 2;
    const int tig  = lane & 3;
    const int qq   = w >> 2;               // 0..3: 16-row quarter
    const int np   = w & 3;                // 16-col group
    const int n0   = np * 16;
    const int ra   = qq * 16 + g;
    const int rb   = ra + 8;

    const int lb  = lane & 7;
    const int r8  = ((lane >> 4) & 1) * 8;
    const int c8  = ((lane >> 3) & 1) * 8;
    const unsigned koff = (unsigned)(((n0 + r8 + lb) * KH + c8) * 2);
    const unsigned voff = (unsigned)(((n0 + r8 + lb) * VH + c8) * 2);
    const unsigned poff = (unsigned)((qq * 16 + (lane & 15)) * VH * 2 + ((lane >> 4) & 1) * 16);

    const int bh = blockIdx.x >> 5;        // 32 q-tiles per (b,h)
    const int qt = blockIdx.x & 31;
    const int b  = bh >> 2;
    const int h  = bh & 3;
    const int q0 = qt * TQA;

    const __half* Qg = g_Qeh + ((size_t)bh * SEQ + q0) * 128;
    const __half* Kg = g_Keh + (size_t)bh * SEQ * 128;
    const __half* Vg = g_Veh + (size_t)bh * 64 * SEQ;
    const unsigned* Mb = g_maskb + ((size_t)b * SEQ + q0) * 64;
    __half* php = g_ph + ((size_t)bh * SEQ + q0) * SEQ;
    float* ao = attn_out + ((size_t)bh * SEQ + q0) * SEQ;

    // ---- stage Q + tile 0 ----
    for (int i = t; i < TQA * 16; i += 512) {
        int r = i >> 4, cc = (i & 15) * 8;
        cp_async16(qs + r * KH + cc, Qg + (size_t)r * 128 + cc);
    }
    for (int i = t; i < 64 * 16; i += 512) {
        int r = i >> 4, cc = (i & 15) * 8;
        cp_async16(ks + r * KH + cc, Kg + (size_t)r * 128 + cc);
    }
    for (int i = t; i < 64 * 8; i += 512) {
        int r = i >> 3, cc = (i & 7) * 8;
        cp_async16(vsh + r * VH + cc, Vg + (size_t)r * SEQ + cc);
    }
    if (t < 2 * TQA)
        cp_async4(msb + t, Mb + (size_t)(t >> 1) * 64 + (t & 1));
    CP_COMMIT();
    CP_WAIT(0);
    __syncthreads();

    // ---- hoist A (Q) fragments ----
    unsigned a[8][4];
    #pragma unroll
    for (int kk = 0; kk < 8; ++kk) {
        a[kk][0] = *(const unsigned*)(qs + ra * KH + kk * 16 + 2 * tig);
        a[kk][1] = *(const unsigned*)(qs + rb * KH + kk * 16 + 2 * tig);
        a[kk][2] = *(const unsigned*)(qs + ra * KH + kk * 16 + 2 * tig + 8);
        a[kk][3] = *(const unsigned*)(qs + rb * KH + kk * 16 + 2 * tig + 8);
    }

    float cxA0 = 0.f, cxA1 = 0.f, cxA2 = 0.f, cxA3 = 0.f;
    float cxB0 = 0.f, cxB1 = 0.f, cxB2 = 0.f, cxB3 = 0.f;
    float sl0 = 0.f, sl1 = 0.f;
    const int colA = n0 + 2 * tig;
    const int colB = colA + 8;
    const int mw   = n0 >> 5;

    for (int tile = 0; tile < NT; ++tile) {
        const int buf = tile & 1;
        const unsigned kbuf_a = ks_a + (unsigned)(buf * 64 * KH) * 2;
        const unsigned vbuf_a = vs_a + (unsigned)(buf * 64 * VH) * 2;
        const unsigned pbuf_a = ps_a + (unsigned)(buf * TQA * VH) * 2;
        const unsigned* mb = msb + buf * 2 * TQA;
        const int k0 = tile * 64;

        // ---- QK: 8 chunks x (LDSM.x4 + 2 mmas reusing A) ----
        float cA0 = 0.f, cA1 = 0.f, cA2 = 0.f, cA3 = 0.f;
        float cB0 = 0.f, cB1 = 0.f, cB2 = 0.f, cB3 = 0.f;
        #pragma unroll
        for (int kk = 0; kk < 8; ++kk) {
            unsigned b0, b1, b2, b3;
            ldsm_x4(b0, b1, b2, b3, kbuf_a + koff + kk * 32);
            mma_f16_k16(cA0, cA1, cA2, cA3, a[kk][0], a[kk][1], a[kk][2], a[kk][3], b0, b1);
            mma_f16_k16(cB0, cB1, cB2, cB3, a[kk][0], a[kk][1], a[kk][2], a[kk][3], b2, b3);
        }

        // ---- mask + fp16x2 exp2 ----
        unsigned w0 = mb[ra * 2 + mw];
        unsigned w1 = mb[rb * 2 + mw];
        float mA00 = ((w0 >> (colA & 31)) & 1u)       ? -100.f : cA0;
        float mA01 = ((w0 >> ((colA + 1) & 31)) & 1u) ? -100.f : cA1;
        float mA10 = ((w1 >> (colA & 31)) & 1u)       ? -100.f : cA2;
        float mA11 = ((w1 >> ((colA + 1) & 31)) & 1u) ? -100.f : cA3;
        float mB00 = ((w0 >> (colB & 31)) & 1u)       ? -100.f : cB0;
        float mB01 = ((w0 >> ((colB + 1) & 31)) & 1u) ? -100.f : cB1;
        float mB10 = ((w1 >> (colB & 31)) & 1u)       ? -100.f : cB2;
        float mB11 = ((w1 >> ((colB + 1) & 31)) & 1u) ? -100.f : cB3;
        __half2 hA0 = h2exp2_approx(__floats2half2_rn(mA00, mA01));
        __half2 hA1 = h2exp2_approx(__floats2half2_rn(mA10, mA11));
        __half2 hB0 = h2exp2_approx(__floats2half2_rn(mB00, mB01));
        __half2 hB1 = h2exp2_approx(__floats2half2_rn(mB10, mB11));
        float2 fA0 = __half22float2(hA0);
        float2 fA1 = __half22float2(hA1);
        float2 fB0 = __half22float2(hB0);
        float2 fB1 = __half22float2(hB1);
        sl0 += fA0.x + fA0.y + fB0.x + fB0.y;
        sl1 += fA1.x + fA1.y + fB1.x + fB1.y;

        // ---- p fp16 -> scratch global + psh ----
        *(__half2*)(php + (size_t)ra * SEQ + k0 + colA) = hA0;
        *(__half2*)(php + (size_t)rb * SEQ + k0 + colA) = hA1;
        *(__half2*)(php + (size_t)ra * SEQ + k0 + colB) = hB0;
        *(__half2*)(php + (size_t)rb * SEQ + k0 + colB) = hB1;
        __half* pw = psh + buf * TQA * VH;
        *(__half2*)(pw + ra * VH + colA) = hA0;
        *(__half2*)(pw + rb * VH + colA) = hA1;
        *(__half2*)(pw + ra * VH + colB) = hB0;
        *(__half2*)(pw + rb * VH + colB) = hB1;
        __syncthreads();    // S1: psh ready; prior tile's buffers fully consumed

        // ---- prefetch tile+1 ----
        if (tile + 1 < NT) {
            const int nb = buf ^ 1;
            const int nk0 = k0 + 64;
            for (int i = t; i < 64 * 16; i += 512) {
                int r = i >> 4, cc = (i & 15) * 8;
                cp_async16(ks + nb * 64 * KH + r * KH + cc,
                           Kg + (size_t)(nk0 + r) * 128 + cc);
            }
            for (int i = t; i < 64 * 8; i += 512) {
                int r = i >> 3, cc = (i & 7) * 8;
                cp_async16(vsh + nb * 64 * VH + r * VH + cc,
                           Vg + (size_t)r * SEQ + nk0 + cc);
            }
            if (t < 2 * TQA)
                cp_async4(msb + nb * 2 * TQA + t,
                          Mb + (size_t)(t >> 1) * 64 + (nk0 >> 5) + (t & 1));
            CP_COMMIT();
        }

        // ---- PV: 4 chunks x (p LDSM.x4 + V LDSM.x4 + 2 mmas) ----
        #pragma unroll
        for (int kk = 0; kk < 4; ++kk) {
            unsigned p0, p1, p2, p3, v0, v1, v2, v3;
            ldsm_x4(p0, p1, p2, p3, pbuf_a + poff + kk * 32);
            ldsm_x4(v0, v1, v2, v3, vbuf_a + voff + kk * 32);
            mma_f16_k16(cxA0, cxA1, cxA2, cxA3, p0, p1, p2, p3, v0, v1);
            mma_f16_k16(cxB0, cxB1, cxB2, cxB3, p0, p1, p2, p3, v2, v3);
        }

        CP_WAIT(0);
        __syncthreads();    // end: next tile visible; buffers free
    }

    // ---- row-sum reduction (4 col-warps per quarter) ----
    sl0 += __shfl_xor_sync(0xffffffffu, sl0, 1);
    sl0 += __shfl_xor_sync(0xffffffffu, sl0, 2);
    sl1 += __shfl_xor_sync(0xffffffffu, sl1, 1);
    sl1 += __shfl_xor_sync(0xffffffffu, sl1, 2);
    if (tig == 0) {
        red[w * 16 + g]     = sl0;
        red[w * 16 + 8 + g] = sl1;
    }
    __syncthreads();
    if (t < TQA) {
        int qr = t >> 4;
        int rr = t & 15;
        float s = 0.f;
        #pragma unroll
        for (int ww = 0; ww < 4; ++ww) s += red[(qr * 4 + ww) * 16 + rr];
        inv[t] = 1.f / s;
    }
    __syncthreads();

    // ---- normalized ctx write ----
    {
        float iv0 = inv[ra];
        float iv1 = inv[rb];
        size_t r0g = (size_t)b * SEQ + q0;
        *(float2*)(g_ctx + (r0g + ra) * 256 + h * 64 + colA) = make_float2(cxA0 * iv0, cxA1 * iv0);
        *(float2*)(g_ctx + (r0g + rb) * 256 + h * 64 + colA) = make_float2(cxA2 * iv1, cxA3 * iv1);
        *(float2*)(g_ctx + (r0g + ra) * 256 + h * 64 + colB) = make_float2(cxB0 * iv0, cxB1 * iv0);
        *(float2*)(g_ctx + (r0g + rb) * 256 + h * 64 + colB) = make_float2(cxB2 * iv1, cxB3 * iv1);
    }

    // ---- normalize: read fp16 scratch (L2-warm), write fp32 attn once ----
    for (int i = t; i < TQA * 256; i += 512) {
        int r = i >> 8;
        int c = i & 255;
        float iv = inv[r];
        uint4 pk = *((const uint4*)(php + (size_t)r * SEQ) + c);
        float2 q0f = __half22float2(*(__half2*)&pk.x);
        float2 q1f = __half22float2(*(__half2*)&pk.y);
        float2 q2f = __half22float2(*(__half2*)&pk.z);
        float2 q3f = __half22float2(*(__half2*)&pk.w);
        float4 o0 = make_float4(q0f.x * iv, q0f.y * iv, q1f.x * iv, q1f.y * iv);
        float4 o1 = make_float4(q2f.x * iv, q2f.y * iv, q3f.x * iv, q3f.y * iv);
        float4* dst = (float4*)(ao + (size_t)r * SEQ) + c * 2;
        dst[0] = o0;
        dst[1] = o1;
    }
}

// ---------------------------------------------------------------------------
// Kernel 3 (v2): fc + LN1 + FFN + LN2 (identical to passing R16)
// ---------------------------------------------------------------------------
#define POST_SMEM_BYTES ((32*260 + 2*32*68) * 4)

__global__ void __launch_bounds__(256, 4) post_kernel(
    const float* __restrict__ x, const float* __restrict__ fcw,
    const float* __restrict__ ln1g, const float* __restrict__ ln1b,
    const float* __restrict__ f1, const float* __restrict__ f2,
    const float* __restrict__ ln2g, const float* __restrict__ ln2b,
    float* __restrict__ res) {
    extern __shared__ float sm[];
    float* cs = sm;               // 32 x 260
    float* hs = cs + 32 * 260;    // 32 x 68
    float* es = hs + 32 * 68;     // 32 x 68

    const int t = threadIdx.x;
    const int row0 = blockIdx.x * 32;

    for (int i = t; i < 32 * 64; i += 256) {
        int r = i >> 6, c = (i & 63) * 4;
        *(float4*)(cs + r * 260 + c) = *(const float4*)(g_ctx + (size_t)(row0 + r) * 256 + c);
    }
    for (int i = t; i < 32 * 16; i += 256) {
        int r = i >> 4, c = (i & 15) * 4;
        *(float4*)(hs + r * 68 + c) = *(const float4*)(x + (size_t)(row0 + r) * DM + c);
    }
    __syncthreads();

    const int rg = t >> 5;
    const int cg = t & 31;
    const int c0 = cg * 2;

    float acc[4][2];
    #pragma unroll
    for (int i = 0; i < 4; ++i) { acc[i][0] = 0.f; acc[i][1] = 0.f; }
    for (int k = 0; k < 256; ++k) {
        float2 bb = __ldg((const float2*)(fcw + k * 64 + c0));
        #pragma unroll
        for (int i = 0; i < 4; ++i) {
            float av = cs[(rg * 4 + i) * 260 + k];
            acc[i][0] += av * bb.x;
            acc[i][1] += av * bb.y;
        }
    }

    float g0 = __ldg(ln1g + c0), g1 = __ldg(ln1g + c0 + 1);
    float b0 = __ldg(ln1b + c0), b1 = __ldg(ln1b + c0 + 1);
    #pragma unroll
    for (int i = 0; i < 4; ++i) {
        float y0 = acc[i][0] + hs[(rg * 4 + i) * 68 + c0];
        float y1 = acc[i][1] + hs[(rg * 4 + i) * 68 + c0 + 1];
        float s = y0 + y1;
        float q = y0 * y0 + y1 * y1;
        #pragma unroll
        for (int o = 16; o; o >>= 1) {
            s += __shfl_xor_sync(0xffffffffu, s, o);
            q += __shfl_xor_sync(0xffffffffu, q, o);
        }
        float mu = s * (1.f / 64.f);
        float var = q * (1.f / 64.f) - mu * mu;
        float rs = rsqrtf(var + 1e-5f);
        *(float2*)(es + (rg * 4 + i) * 68 + c0) =
            make_float2((y0 - mu) * rs * g0 + b0, (y1 - mu) * rs * g1 + b1);
    }
    __syncthreads();

    float h4[4][2];
    #pragma unroll
    for (int i = 0; i < 4; ++i) { h4[i][0] = 0.f; h4[i][1] = 0.f; }
    for (int k = 0; k < 64; ++k) {
        float2 bb = __ldg((const float2*)(f1 + k * 64 + c0));
        #pragma unroll
        for (int i = 0; i < 4; ++i) {
            float av = es[(rg * 4 + i) * 68 + k];
            h4[i][0] += av * bb.x;
            h4[i][1] += av * bb.y;
        }
    }
    __syncthreads();
    #pragma unroll
    for (int i = 0; i < 4; ++i)
        *(float2*)(hs + (rg * 4 + i) * 68 + c0) =
            make_float2(fmaxf(h4[i][0], 0.f), fmaxf(h4[i][1], 0.f));
    __syncthreads();

    float fa[4][2];
    #pragma unroll
    for (int i = 0; i < 4; ++i) { fa[i][0] = 0.f; fa[i][1] = 0.f; }
    for (int k = 0; k < 64; ++k) {
        float2 bb = __ldg((const float2*)(f2 + k * 64 + c0));
        #pragma unroll
        for (int i = 0; i < 4; ++i) {
            float av = hs[(rg * 4 + i) * 68 + k];
            fa[i][0] += av * bb.x;
            fa[i][1] += av * bb.y;
        }
    }
    float g20 = __ldg(ln2g + c0), g21 = __ldg(ln2g + c0 + 1);
    float b20 = __ldg(ln2b + c0), b21 = __ldg(ln2b + c0 + 1);
    #pragma unroll
    for (int i = 0; i < 4; ++i) {
        float y0 = fa[i][0] + es[(rg * 4 + i) * 68 + c0];
        float y1 = fa[i][1] + es[(rg * 4 + i) * 68 + c0 + 1];
        float s = y0 + y1;
        float q = y0 * y0 + y1 * y1;
        #pragma unroll
        for (int o = 16; o; o >>= 1) {
            s += __shfl_xor_sync(0xffffffffu, s, o);
            q += __shfl_xor_sync(0xffffffffu, q, o);
        }
        float mu = s * (1.f / 64.f);
        float var = q * (1.f / 64.f) - mu * mu;
        float rs = rsqrtf(var + 1e-5f);
        *(float2*)(res + (size_t)(row0 + rg * 4 + i) * 64 + c0) =
            make_float2((y0 - mu) * rs * g20 + b20, (y1 - mu) * rs * g21 + b21);
    }
}

// ---------------------------------------------------------------------------
// Launch
// ---------------------------------------------------------------------------
extern "C" void kernel_launch(void* const* d_in, const int* in_sizes, int n_in,
                              void* d_out, int out_size) {
    const float* x    = (const float*)d_in[0];
    const void*  mask = d_in[1];
    const float* u    = (const float*)d_in[2];
    const float* wq   = (const float*)d_in[3];
    const float* wk   = (const float*)d_in[4];
    const float* wv   = (const float*)d_in[5];
    const float* uqw  = (const float*)d_in[6];
    const float* ukw  = (const float*)d_in[7];
    const float* uvw  = (const float*)d_in[8];
    const float* sq1  = (const float*)d_in[9];
    const float* sq2  = (const float*)d_in[10];
    const float* sk1  = (const float*)d_in[11];
    const float* sk2  = (const float*)d_in[12];
    const float* sv1  = (const float*)d_in[13];
    const float* sv2  = (const float*)d_in[14];
    const float* fcw  = (const float*)d_in[15];
    const float* ln1g = (const float*)d_in[16];
    const float* ln1b = (const float*)d_in[17];
    const float* ffn1 = (const float*)d_in[18];
    const float* ffn2 = (const float*)d_in[19];
    const float* ln2g = (const float*)d_in[20];
    const float* ln2b = (const float*)d_in[21];

    float* res  = (float*)d_out;
    float* attn = res + (size_t)NB * SEQ * DM;

    cudaFuncSetAttribute(proj_kernel,  cudaFuncAttributeMaxDynamicSharedMemorySize, PROJ_SMEM_BYTES);
    cudaFuncSetAttribute(attn2_kernel, cudaFuncAttributeMaxDynamicSharedMemorySize, ATT_SMEM_BYTES);
    cudaFuncSetAttribute(post_kernel,  cudaFuncAttributeMaxDynamicSharedMemorySize, POST_SMEM_BYTES);

    detect_mask_kernel<<<1, 32>>>((const unsigned char*)mask);
    convert_mask_kernel<<<(NB * SEQ * SEQ) / 256, 256>>>(mask);
    gates_kernel<<<NB, 32>>>(u, sq1, sq2, sk1, sk2, sv1, sv2);
    proj_kernel<<<(NB * SEQ) / 64, 256, PROJ_SMEM_BYTES>>>(x, wq, wk, wv, uqw, ukw, uvw);
    attn2_kernel<<<NB * NH * (SEQ / TQA), 512, ATT_SMEM_BYTES>>>(attn);
    post_kernel<<<(NB * SEQ) / 32, 256, POST_SMEM_BYTES>>>(x, fcw, ln1g, ln1b, ffn1, ffn2,
                                                           ln2g, ln2b, res);
}